// round 1
// baseline (speedup 1.0000x reference)
#include <cuda_runtime.h>
#include <math.h>

#define D      512
#define NC     64
#define NBANK  200000
#define BSZ    2048
#define NCLS   100
#define KSEL   64

#define O_ORIG   0
#define O_Y      (BSZ*NCLS)
#define O_L1     (2*BSZ*NCLS)
#define O_L2     (O_L1+1)
#define O_NORM   (O_L1+2)
#define O_CPRED  (O_L1+3)

// scratch (device globals: no allocation allowed)
__device__ float g_S[(size_t)NC*NBANK];   // dot(c_n, bank_j), row per concept
__device__ float g_bank_sq[NBANK];
__device__ float g_gram[NC*NC];
__device__ float g_inv[NC*NC];
__device__ float g_Wc[NC*NCLS];
__device__ float g_Q[BSZ*NC];
__device__ float g_csum[NC];

// ---------------------------------------------------------------------------
// Generic small SGEMM: Co[m,n] = sum_k A[m*ars + k*acs] * B[k*brs + n*bcs]
// block = 256 threads, 64x64 tile, 4x4 microtile. M%64==0, K%32==0 assumed.
// ---------------------------------------------------------------------------
__global__ void __launch_bounds__(256) gemm_generic(
    const float* __restrict__ A, const float* __restrict__ B,
    float* __restrict__ Co,
    int M, int N, int Kd,
    int ars, int acs, int brs, int bcs, int ldc)
{
    __shared__ float As[32][64];
    __shared__ float Bs[32][64];
    int tid = threadIdx.x;
    int m0 = blockIdx.x * 64, n0 = blockIdx.y * 64;
    int tx = tid & 15, ty = tid >> 4;
    float acc[4][4] = {};

    for (int k0 = 0; k0 < Kd; k0 += 32) {
        #pragma unroll
        for (int e = 0; e < 8; e++) {
            int idx = tid + e * 256;
            int k = idx >> 6, q = idx & 63;
            As[k][q] = A[(size_t)(m0 + q) * ars + (size_t)(k0 + k) * acs];
            int nn = n0 + q;
            Bs[k][q] = (nn < N) ? B[(size_t)(k0 + k) * brs + (size_t)nn * bcs] : 0.f;
        }
        __syncthreads();
        #pragma unroll
        for (int k = 0; k < 32; k++) {
            float4 av = *(const float4*)&As[k][tx * 4];
            float4 bv = *(const float4*)&Bs[k][ty * 4];
            float ax[4] = {av.x, av.y, av.z, av.w};
            float bx[4] = {bv.x, bv.y, bv.z, bv.w};
            #pragma unroll
            for (int i = 0; i < 4; i++)
                #pragma unroll
                for (int e = 0; e < 4; e++)
                    acc[i][e] += ax[i] * bx[e];
        }
        __syncthreads();
    }
    #pragma unroll
    for (int i = 0; i < 4; i++) {
        int m = m0 + tx * 4 + i;
        #pragma unroll
        for (int e = 0; e < 4; e++) {
            int nn = n0 + ty * 4 + e;
            if (nn < N) Co[(size_t)m * ldc + nn] = acc[i][e];
        }
    }
}

// ---------------------------------------------------------------------------
// 64x64 Gauss-Jordan inverse of g_gram -> g_inv (gram is strongly diag-dominant)
// 1024 threads: thread = (row r, col-group cg of 4 cols)
// ---------------------------------------------------------------------------
__global__ void __launch_bounds__(1024) invert64()
{
    __shared__ float a[64][64];
    __shared__ float mi[64][64];
    __shared__ float fcol[64];
    int tid = threadIdx.x;
    int r = tid >> 4, cg = (tid & 15) * 4;

    for (int i = tid; i < 4096; i += 1024) {
        a[i >> 6][i & 63] = g_gram[i];
        mi[i >> 6][i & 63] = ((i >> 6) == (i & 63)) ? 1.f : 0.f;
    }
    __syncthreads();

    for (int p = 0; p < 64; p++) {
        if (tid < 64) fcol[tid] = a[tid][p];
        __syncthreads();
        float pinv = 1.f / fcol[p];
        if (r == p) {
            #pragma unroll
            for (int c = 0; c < 4; c++) { a[p][cg + c] *= pinv; mi[p][cg + c] *= pinv; }
        }
        __syncthreads();
        if (r != p) {
            float f = fcol[r];
            #pragma unroll
            for (int c = 0; c < 4; c++) {
                a[r][cg + c]  -= f * a[p][cg + c];
                mi[r][cg + c] -= f * mi[p][cg + c];
            }
        }
        __syncthreads();
    }
    for (int i = tid; i < 4096; i += 1024) g_inv[i] = mi[i >> 6][i & 63];
}

// ---------------------------------------------------------------------------
// Big GEMM: S[n][j] = sum_d C[d][n]*bank[j][d]  (64 x 200000, K=512)
// Also computes g_bank_sq. Block: 64 bank rows, all 64 concepts, 256 threads.
// ---------------------------------------------------------------------------
__global__ void __launch_bounds__(256) big_gemm(
    const float* __restrict__ C, const float* __restrict__ bank)
{
    __shared__ float As[32][64];   // C chunk: [k][n]
    __shared__ float Bs[32][68];   // bank chunk transposed: [k][j]
    int tid = threadIdx.x;
    int jbase = blockIdx.x * 64;
    int tx = tid & 15, ty = tid >> 4;     // tx -> concepts, ty -> bank rows
    int jl0 = tid >> 3;                   // 0..31: this thread's staging row
    int k4  = tid & 7;                    // 0..7 : k-quad within 32-chunk

    float acc[4][4] = {};
    float sq0 = 0.f, sq1 = 0.f;
    const float* b0p = bank + (size_t)(jbase + jl0) * D + k4 * 4;
    const float* b1p = bank + (size_t)(jbase + jl0 + 32) * D + k4 * 4;

    for (int k0 = 0; k0 < D; k0 += 32) {
        // stage C chunk (layout already [k][n])
        const float4* Cg = (const float4*)(C + (size_t)k0 * NC);
        ((float4*)As)[tid]       = Cg[tid];
        ((float4*)As)[tid + 256] = Cg[tid + 256];
        // stage bank chunk with transpose + accumulate row sumsq
        float4 b0 = *(const float4*)(b0p + k0);
        float4 b1 = *(const float4*)(b1p + k0);
        sq0 += b0.x*b0.x + b0.y*b0.y + b0.z*b0.z + b0.w*b0.w;
        sq1 += b1.x*b1.x + b1.y*b1.y + b1.z*b1.z + b1.w*b1.w;
        int kk = k4 * 4;
        Bs[kk+0][jl0] = b0.x; Bs[kk+1][jl0] = b0.y; Bs[kk+2][jl0] = b0.z; Bs[kk+3][jl0] = b0.w;
        Bs[kk+0][jl0+32] = b1.x; Bs[kk+1][jl0+32] = b1.y; Bs[kk+2][jl0+32] = b1.z; Bs[kk+3][jl0+32] = b1.w;
        __syncthreads();
        #pragma unroll
        for (int k = 0; k < 32; k++) {
            float4 av = *(const float4*)&As[k][tx * 4];
            float4 bv = *(const float4*)&Bs[k][ty * 4];
            float ax[4] = {av.x, av.y, av.z, av.w};
            float bx[4] = {bv.x, bv.y, bv.z, bv.w};
            #pragma unroll
            for (int i = 0; i < 4; i++)
                #pragma unroll
                for (int e = 0; e < 4; e++)
                    acc[i][e] += ax[i] * bx[e];
        }
        __syncthreads();
    }

    // reduce sumsq over the 8 lanes that share a staging row
    #pragma unroll
    for (int o = 4; o; o >>= 1) {
        sq0 += __shfl_xor_sync(0xffffffffu, sq0, o, 8);
        sq1 += __shfl_xor_sync(0xffffffffu, sq1, o, 8);
    }
    if (k4 == 0) {
        g_bank_sq[jbase + jl0]      = sq0;
        g_bank_sq[jbase + jl0 + 32] = sq1;
    }

    #pragma unroll
    for (int i = 0; i < 4; i++) {
        int n = tx * 4 + i;
        float4 v = make_float4(acc[i][0], acc[i][1], acc[i][2], acc[i][3]);
        *(float4*)(g_S + (size_t)n * NBANK + jbase + ty * 4) = v;
    }
}

// ---------------------------------------------------------------------------
// Per-concept exact top-64 smallest d2; accumulates sum of the corresponding
// dots into g_csum[n]. 64 blocks x 1024 threads.
// d2 = c_sq[n] + bank_sq[j] - 2*S[n][j]  (clamped at 0; positive-float bits
// are order-isomorphic to uint)
// ---------------------------------------------------------------------------
#define SELCAP 3072
__global__ void __launch_bounds__(1024) select_topk()
{
    int n = blockIdx.x;
    int tid = threadIdx.x;
    int lane = tid & 31, w = tid >> 5;
    const float* Srow = g_S + (size_t)n * NBANK;
    float csq = g_gram[n * NC + n];

    __shared__ unsigned hist[4096];
    __shared__ unsigned wbufa[32];
    __shared__ unsigned wbufb[32];
    __shared__ float    fred[32];
    __shared__ unsigned cand_key[SELCAP];
    __shared__ float    cand_S[SELCAP];
    __shared__ unsigned s_cnt, s_kmin, s_shift, s_cb1;
    __shared__ int      s_b1;
    __shared__ float    s_below;

    // ---- pass 0: key min/max ----
    unsigned kmin = 0xffffffffu, kmax = 0u;
    for (int j = tid; j < NBANK; j += 1024) {
        float d2 = fmaxf(csq + g_bank_sq[j] - 2.f * Srow[j], 0.f);
        unsigned key = __float_as_uint(d2);
        kmin = min(kmin, key); kmax = max(kmax, key);
    }
    #pragma unroll
    for (int o = 16; o; o >>= 1) {
        kmin = min(kmin, __shfl_xor_sync(0xffffffffu, kmin, o));
        kmax = max(kmax, __shfl_xor_sync(0xffffffffu, kmax, o));
    }
    if (lane == 0) { wbufa[w] = kmin; wbufb[w] = kmax; }
    __syncthreads();
    if (tid < 32) {
        kmin = wbufa[tid]; kmax = wbufb[tid];
        #pragma unroll
        for (int o = 16; o; o >>= 1) {
            kmin = min(kmin, __shfl_xor_sync(0xffffffffu, kmin, o));
            kmax = max(kmax, __shfl_xor_sync(0xffffffffu, kmax, o));
        }
        if (tid == 0) {
            s_kmin = kmin;
            unsigned range = kmax - kmin;
            unsigned sh = 0;
            if (range >= 4096u) sh = (unsigned)(32 - __clz(range) - 12);
            s_shift = sh;
            s_cnt = 0;
        }
    }
    for (int i = tid; i < 4096; i += 1024) hist[i] = 0;
    __syncthreads();
    unsigned kmin0 = s_kmin, sh = s_shift;

    // ---- pass 1: histogram ----
    for (int j = tid; j < NBANK; j += 1024) {
        float d2 = fmaxf(csq + g_bank_sq[j] - 2.f * Srow[j], 0.f);
        unsigned b = (__float_as_uint(d2) - kmin0) >> sh;
        atomicAdd(&hist[b], 1u);
    }
    __syncthreads();

    // ---- block scan: find bin b1 where cumulative count crosses KSEL ----
    {
        unsigned h0 = hist[tid*4], h1 = hist[tid*4+1], h2 = hist[tid*4+2], h3 = hist[tid*4+3];
        unsigned tsum = h0 + h1 + h2 + h3;
        unsigned v = tsum;
        #pragma unroll
        for (int o = 1; o < 32; o <<= 1) {
            unsigned u = __shfl_up_sync(0xffffffffu, v, o);
            if (lane >= o) v += u;
        }
        if (lane == 31) wbufa[w] = v;
        __syncthreads();
        if (tid < 32) {
            unsigned x = wbufa[tid];
            #pragma unroll
            for (int o = 1; o < 32; o <<= 1) {
                unsigned u = __shfl_up_sync(0xffffffffu, x, o);
                if (tid >= o) x += u;
            }
            wbufa[tid] = x;
        }
        __syncthreads();
        unsigned excl = v - tsum + (w ? wbufa[w - 1] : 0u);
        if (excl < KSEL && excl + tsum >= KSEL) {
            unsigned c = excl;
            int b = tid * 4;
            unsigned hh[4] = {h0, h1, h2, h3};
            int i = 0;
            while (i < 3 && c + hh[i] < KSEL) { c += hh[i]; i++; }
            s_b1 = b + i; s_cb1 = c;
        }
    }
    __syncthreads();
    int b1 = s_b1;

    // ---- pass 2: sum below-bin dots; collect boundary-bin candidates ----
    float sum = 0.f;
    for (int j = tid; j < NBANK; j += 1024) {
        float s = Srow[j];
        float d2 = fmaxf(csq + g_bank_sq[j] - 2.f * s, 0.f);
        unsigned key = __float_as_uint(d2);
        int b = (int)((key - kmin0) >> sh);
        if (b < b1) sum += s;
        else if (b == b1) {
            unsigned p = atomicAdd(&s_cnt, 1u);
            if (p < SELCAP) { cand_key[p] = key; cand_S[p] = s; }
        }
    }
    #pragma unroll
    for (int o = 16; o; o >>= 1) sum += __shfl_xor_sync(0xffffffffu, sum, o);
    if (lane == 0) fred[w] = sum;
    __syncthreads();
    if (tid < 32) {
        float x = fred[tid];
        #pragma unroll
        for (int o = 16; o; o >>= 1) x += __shfl_xor_sync(0xffffffffu, x, o);
        if (tid == 0) s_below = x;
    }
    __syncthreads();

    // ---- final: pick the remaining r smallest among candidates (warp 0) ----
    int r = KSEL - (int)s_cb1;
    int m = (int)min(s_cnt, (unsigned)SELCAP);
    if (tid < 32) {
        float extra = 0.f;
        for (int it = 0; it < r; it++) {
            unsigned best = 0xffffffffu;
            unsigned bsec = 0xffffffffu;   // S bits for deterministic tie-break
            int bi = -1;
            for (int i = tid; i < m; i += 32) {
                unsigned k = cand_key[i];
                unsigned sb = __float_as_uint(cand_S[i]);
                if (k < best || (k == best && sb < bsec)) { best = k; bsec = sb; bi = i; }
            }
            #pragma unroll
            for (int o = 16; o; o >>= 1) {
                unsigned ok  = __shfl_xor_sync(0xffffffffu, best, o);
                unsigned osb = __shfl_xor_sync(0xffffffffu, bsec, o);
                int      obi = __shfl_xor_sync(0xffffffffu, bi, o);
                if (ok < best || (ok == best && osb < bsec)) { best = ok; bsec = osb; bi = obi; }
            }
            if (tid == 0 && bi >= 0) { extra += cand_S[bi]; cand_key[bi] = 0xffffffffu; }
            __syncwarp();
        }
        if (tid == 0) g_csum[n] = s_below + extra;
    }
}

// ---------------------------------------------------------------------------
// Scalars
// ---------------------------------------------------------------------------
__global__ void __launch_bounds__(256) finalize(float* __restrict__ out)
{
    __shared__ float r1[8], r2[8], r3[8];
    int tid = threadIdx.x, lane = tid & 31, w = tid >> 5;
    float gs = 0.f, tr = 0.f;
    for (int i = tid; i < NC * NC; i += 256) {
        float v = g_gram[i];
        gs += v;
        if ((i >> 6) == (i & 63)) tr += v;
    }
    float cs = (tid < NC) ? g_csum[tid] : 0.f;
    #pragma unroll
    for (int o = 16; o; o >>= 1) {
        gs += __shfl_xor_sync(0xffffffffu, gs, o);
        tr += __shfl_xor_sync(0xffffffffu, tr, o);
        cs += __shfl_xor_sync(0xffffffffu, cs, o);
    }
    if (lane == 0) { r1[w] = gs; r2[w] = tr; r3[w] = cs; }
    __syncthreads();
    if (tid == 0) {
        float GS = 0, TR = 0, CS = 0;
        for (int i = 0; i < 8; i++) { GS += r1[i]; TR += r2[i]; CS += r3[i]; }
        out[O_L1]   = CS / (float)(NC * KSEL);
        out[O_L2]   = (GS - TR) / (float)(NC * NC);
        out[O_NORM] = TR / (float)(NC * NC);
    }
}

// ---------------------------------------------------------------------------
extern "C" void kernel_launch(void* const* d_in, const int* in_sizes, int n_in,
                              void* d_out, int out_size)
{
    (void)in_sizes; (void)n_in; (void)out_size;
    const float* C    = (const float*)d_in[0];  // (512, 64)
    const float* E    = (const float*)d_in[1];  // (2048, 512)
    const float* bank = (const float*)d_in[2];  // (200000, 512)
    const float* W    = (const float*)d_in[3];  // (512, 100)
    float* out = (float*)d_out;

    float *pgram, *pinv, *pWc, *pQ;
    cudaGetSymbolAddress((void**)&pgram, g_gram);
    cudaGetSymbolAddress((void**)&pinv,  g_inv);
    cudaGetSymbolAddress((void**)&pWc,   g_Wc);
    cudaGetSymbolAddress((void**)&pQ,    g_Q);

    // gram = C^T C   (A: a(m,k)=C[k*64+m];  B: b(k,n)=C[k*64+n])
    gemm_generic<<<dim3(1, 1), 256>>>(C, C, pgram, NC, NC, D, 1, NC, NC, 1, NC);
    // Wc = C^T @ w_head
    gemm_generic<<<dim3(1, 2), 256>>>(C, W, pWc, NC, NCLS, D, 1, NC, NCLS, 1, NCLS);
    // inv(gram)
    invert64<<<1, 1024>>>();
    // orig_pred = E @ w_head
    gemm_generic<<<dim3(32, 2), 256>>>(E, W, out + O_ORIG, BSZ, NCLS, D, D, 1, NCLS, 1, NCLS);
    // concept_pred = E @ C
    gemm_generic<<<dim3(32, 1), 256>>>(E, C, out + O_CPRED, BSZ, NC, D, D, 1, NC, 1, NC);
    // Q = concept_pred @ inv^T   (b(k,n) = inv[n*64+k])
    gemm_generic<<<dim3(32, 1), 256>>>(out + O_CPRED, pinv, pQ, BSZ, NC, NC, NC, 1, 1, NC, NC);
    // y_pred = Q @ Wc
    gemm_generic<<<dim3(32, 2), 256>>>(pQ, pWc, out + O_Y, BSZ, NCLS, NC, NC, 1, NCLS, 1, NCLS);
    // S = C^T @ bank^T  (+ bank_sq)
    big_gemm<<<NBANK / 64, 256>>>(C, bank);
    // per-concept exact top-64 sum of dots
    select_topk<<<NC, 1024>>>();
    // scalars
    finalize<<<1, 256>>>(out);
}

// round 3
// speedup vs baseline: 1.3703x; 1.3703x over previous
#include <cuda_runtime.h>
#include <cuda_bf16.h>
#include <math.h>
#include <stdint.h>

#define D      512
#define NC     64
#define NBANK  200000
#define BSZ    2048
#define NCLS   100
#define KSEL   64
#define NCHUNK 8
#define MTILE  128
#define SJ_LD  132   // padded j-stride for epilogue transpose tile

#define O_ORIG   0
#define O_Y      (BSZ*NCLS)
#define O_L1     (2*BSZ*NCLS)
#define O_L2     (O_L1+1)
#define O_NORM   (O_L1+2)
#define O_CPRED  (O_L1+3)

// ------------------------- device scratch ----------------------------------
__device__ float    g_S[(size_t)NC*NBANK];
__device__ float    g_bank_sq[NBANK];
__device__ float    g_gram[NC*NC];
__device__ float    g_inv[NC*NC];
__device__ float    g_Wc[NC*NCLS];
__device__ float    g_Q[BSZ*NC];
__device__ float    g_csum[NC];
__device__ unsigned g_kmin[NC];
__device__ unsigned g_kmax[NC];
// pre-swizzled bf16 C tiles: per chunk c, tile [64 n][64 k], 8KB each
__device__ uint4    g_Bh4[NCHUNK*512];
__device__ uint4    g_Bl4[NCHUNK*512];

// ------------------------- helpers -----------------------------------------
__device__ __forceinline__ uint32_t smem_u32(const void* p) {
    uint32_t a;
    asm("{ .reg .u64 t; cvta.to.shared.u64 t, %1; cvt.u32.u64 %0, t; }"
        : "=r"(a) : "l"(p));
    return a;
}
__device__ __forceinline__ unsigned swz128(unsigned o) { return o ^ ((o >> 3) & 0x70u); }

#define LDMX4(r, a) \
    asm volatile("ldmatrix.sync.aligned.m8n8.x4.shared.b16 {%0,%1,%2,%3}, [%4];" \
        : "=r"((r)[0]), "=r"((r)[1]), "=r"((r)[2]), "=r"((r)[3]) : "r"(a))

#define MMA16816(d, a, b0, b1) \
    asm volatile("mma.sync.aligned.m16n8k16.row.col.f32.bf16.bf16.f32 " \
        "{%0,%1,%2,%3}, {%4,%5,%6,%7}, {%8,%9}, {%0,%1,%2,%3};" \
        : "+f"((d)[0]), "+f"((d)[1]), "+f"((d)[2]), "+f"((d)[3]) \
        : "r"((a)[0]), "r"((a)[1]), "r"((a)[2]), "r"((a)[3]), "r"(b0), "r"(b1))

// ------------------- prep: split+swizzle C, reset min/max ------------------
__global__ void __launch_bounds__(256) prep_convertC(const float* __restrict__ C)
{
    int tid = threadIdx.x;
    char* bh = (char*)g_Bh4;
    char* bl = (char*)g_Bl4;
    for (int idx = tid; idx < D * NC; idx += 256) {
        int n = idx & 63, k = idx >> 6;          // C[k*64+n] == C[idx], coalesced
        float x = C[idx];
        __nv_bfloat16 h = __float2bfloat16_rn(x);
        float hf = __bfloat162float(h);
        __nv_bfloat16 l = __float2bfloat16_rn(x - hf);
        int c = k >> 6, kk = k & 63;
        unsigned off = swz128((unsigned)(n * 128 + kk * 2));
        *(__nv_bfloat16*)(bh + c * 8192 + off) = h;
        *(__nv_bfloat16*)(bl + c * 8192 + off) = l;
    }
    if (tid < NC) { g_kmin[tid] = 0xffffffffu; g_kmax[tid] = 0u; }
}

// ------------------- small SGEMM (coalesced staging) ------------------------
template <bool ATRANS>
__global__ void __launch_bounds__(256) sgemm64(
    const float* __restrict__ A, const float* __restrict__ B, float* __restrict__ Co,
    int M, int N, int K, int lda, int ldb, int ldc)
{
    __shared__ float As[64][33];
    __shared__ __align__(16) float Bs[32][64];
    int tid = threadIdx.x;
    int m0 = blockIdx.x * 64, n0 = blockIdx.y * 64;
    int tx = tid & 15, ty = tid >> 4;
    float acc[4][4] = {};

    for (int k0 = 0; k0 < K; k0 += 32) {
        #pragma unroll
        for (int e = 0; e < 8; e++) {
            int idx = e * 256 + tid;
            if (ATRANS) {
                int m = idx & 63, k = idx >> 6;
                As[m][k] = A[(size_t)(k0 + k) * lda + (m0 + m)];
            } else {
                int k = idx & 31, m = idx >> 5;
                As[m][k] = A[(size_t)(m0 + m) * lda + (k0 + k)];
            }
            int n = idx & 63, k2 = idx >> 6;
            int nn = n0 + n;
            Bs[k2][n] = (nn < N) ? B[(size_t)(k0 + k2) * ldb + nn] : 0.f;
        }
        __syncthreads();
        #pragma unroll
        for (int k = 0; k < 32; k++) {
            float a0 = As[tx * 4 + 0][k];
            float a1 = As[tx * 4 + 1][k];
            float a2 = As[tx * 4 + 2][k];
            float a3 = As[tx * 4 + 3][k];
            float4 bv = *(const float4*)&Bs[k][ty * 4];
            acc[0][0] += a0 * bv.x; acc[0][1] += a0 * bv.y; acc[0][2] += a0 * bv.z; acc[0][3] += a0 * bv.w;
            acc[1][0] += a1 * bv.x; acc[1][1] += a1 * bv.y; acc[1][2] += a1 * bv.z; acc[1][3] += a1 * bv.w;
            acc[2][0] += a2 * bv.x; acc[2][1] += a2 * bv.y; acc[2][2] += a2 * bv.z; acc[2][3] += a2 * bv.w;
            acc[3][0] += a3 * bv.x; acc[3][1] += a3 * bv.y; acc[3][2] += a3 * bv.z; acc[3][3] += a3 * bv.w;
        }
        __syncthreads();
    }
    #pragma unroll
    for (int i = 0; i < 4; i++) {
        int m = m0 + tx * 4 + i;
        #pragma unroll
        for (int e = 0; e < 4; e++) {
            int nn = n0 + ty * 4 + e;
            if (nn < N) Co[(size_t)m * ldc + nn] = acc[i][e];
        }
    }
}

// ------------------- 64x64 Gauss-Jordan inverse -----------------------------
__global__ void __launch_bounds__(1024) invert64()
{
    __shared__ float a[64][64];
    __shared__ float mi[64][64];
    __shared__ float fcol[64];
    int tid = threadIdx.x;
    int r = tid >> 4, cg = (tid & 15) * 4;

    for (int i = tid; i < 4096; i += 1024) {
        a[i >> 6][i & 63]  = g_gram[i];
        mi[i >> 6][i & 63] = ((i >> 6) == (i & 63)) ? 1.f : 0.f;
    }
    __syncthreads();
    for (int p = 0; p < 64; p++) {
        if (tid < 64) fcol[tid] = a[tid][p];
        __syncthreads();
        float pinv = 1.f / fcol[p];
        if (r == p) {
            #pragma unroll
            for (int c = 0; c < 4; c++) { a[p][cg + c] *= pinv; mi[p][cg + c] *= pinv; }
        }
        __syncthreads();
        if (r != p) {
            float f = fcol[r];
            #pragma unroll
            for (int c = 0; c < 4; c++) {
                a[r][cg + c]  -= f * a[p][cg + c];
                mi[r][cg + c] -= f * mi[p][cg + c];
            }
        }
        __syncthreads();
    }
    for (int i = tid; i < 4096; i += 1024) g_inv[i] = mi[i >> 6][i & 63];
}

// ------------------- big GEMM via mma.sync (bf16 3-term split) ---------------
// S[j][n] = sum_d bank[j][d] * C[d][n] for a 128-row tile of j.
// Also: bank_sq, and per-concept d2 min/max (atomics into g_kmin/g_kmax).
// SMEM: [0..512) row_sq, [512..768) csq, T(1024-aligned): Ah(16K)|Al(16K)|Bh(8K)|Bl(8K)
#define BG_SMEM 51200
__global__ void __launch_bounds__(256) big_gemm(const float* __restrict__ bank)
{
    extern __shared__ char sm[];
    uint32_t base = smem_u32(sm);
    const int tid = threadIdx.x;
    const int lane = tid & 31, w = tid >> 5;
    const int wm = w & 3, wn = w >> 2;       // 4 m-quarters x 2 n-halves

    uint32_t T = (base + 768 + 1023) & ~1023u;
    uint32_t off_T = T - base;
    float* row_sq = (float*)(sm);            // 128 floats
    float* s_csq  = (float*)(sm + 512);      // 64 floats
    char*  smT    = sm + off_T;

    if (tid < NC) s_csq[tid] = g_gram[tid * NC + tid];

    const int jbase = blockIdx.x * MTILE;
    const int r0 = tid >> 4, qa = tid & 15;
    float sq[8] = {};

    float acc[2][4][4] = {};
    const int arow = wm * 32 + (lane & 15);
    const int brow = wn * 32 + (lane & 15);
    const unsigned khb = (unsigned)(lane >> 4) * 16;

    for (int c = 0; c < NCHUNK; c++) {
        if (c) __syncthreads();
        // stage A: 128 rows x 64 k fp32 -> hi/lo bf16, swizzled
        #pragma unroll
        for (int p = 0; p < 8; p++) {
            int r = p * 16 + r0;
            int j = jbase + r; if (j >= NBANK) j = NBANK - 1;
            float4 v = *(const float4*)(bank + (size_t)j * D + c * 64 + qa * 4);
            sq[p] += v.x * v.x + v.y * v.y + v.z * v.z + v.w * v.w;
            __nv_bfloat162 h0 = __floats2bfloat162_rn(v.x, v.y);
            __nv_bfloat162 h1 = __floats2bfloat162_rn(v.z, v.w);
            float lx = v.x - __low2float(h0),  ly = v.y - __high2float(h0);
            float lz = v.z - __low2float(h1),  lw = v.w - __high2float(h1);
            __nv_bfloat162 l0 = __floats2bfloat162_rn(lx, ly);
            __nv_bfloat162 l1 = __floats2bfloat162_rn(lz, lw);
            unsigned off = swz128((unsigned)(r * 128 + qa * 8));
            uint2 hv, lv;
            hv.x = *(unsigned*)&h0; hv.y = *(unsigned*)&h1;
            lv.x = *(unsigned*)&l0; lv.y = *(unsigned*)&l1;
            *(uint2*)(smT + off)          = hv;
            *(uint2*)(smT + 16384 + off)  = lv;
        }
        // stage B: copy pre-swizzled chunk (8KB hi + 8KB lo)
        {
            const uint4* gbh = g_Bh4 + c * 512;
            const uint4* gbl = g_Bl4 + c * 512;
            uint4* pbh = (uint4*)(smT + 32768);
            uint4* pbl = (uint4*)(smT + 40960);
            #pragma unroll
            for (int e = 0; e < 2; e++) {
                pbh[e * 256 + tid] = gbh[e * 256 + tid];
                pbl[e * 256 + tid] = gbl[e * 256 + tid];
            }
        }
        __syncthreads();
        // compute: 4 k-slabs of 16
        #pragma unroll
        for (int kc = 0; kc < 4; kc++) {
            uint32_t ah[2][4], al[2][4], bh4[2][4], bl4[2][4];
            #pragma unroll
            for (int mt = 0; mt < 2; mt++) {
                unsigned o = swz128((unsigned)((arow + mt * 16) * 128 + kc * 32 + khb));
                LDMX4(ah[mt], T + o);
                LDMX4(al[mt], T + 16384 + o);
            }
            #pragma unroll
            for (int np = 0; np < 2; np++) {
                unsigned o = swz128((unsigned)((brow + np * 16) * 128 + kc * 32 + khb));
                LDMX4(bh4[np], T + 32768 + o);
                LDMX4(bl4[np], T + 40960 + o);
            }
            #pragma unroll
            for (int mt = 0; mt < 2; mt++) {
                #pragma unroll
                for (int nt = 0; nt < 4; nt++) {
                    int np = nt >> 1, hf = nt & 1;
                    MMA16816(acc[mt][nt], ah[mt], bh4[np][hf], bh4[np][hf + 2]);
                    MMA16816(acc[mt][nt], ah[mt], bl4[np][hf], bl4[np][hf + 2]);
                    MMA16816(acc[mt][nt], al[mt], bh4[np][hf], bh4[np][hf + 2]);
                }
            }
        }
    }

    // row sumsq: reduce over the 16 lanes sharing a row
    #pragma unroll
    for (int p = 0; p < 8; p++) {
        #pragma unroll
        for (int o = 8; o; o >>= 1)
            sq[p] += __shfl_xor_sync(0xffffffffu, sq[p], o, 16);
    }
    if (qa == 0) {
        #pragma unroll
        for (int p = 0; p < 8; p++) {
            int r = p * 16 + r0, j = jbase + r;
            row_sq[r] = sq[p];
            if (j < NBANK) g_bank_sq[j] = sq[p];
        }
    }
    __syncthreads();   // compute done; reuse smT as fp32 [n][SJ_LD j] tile

    float* sT = (float*)smT;
    #pragma unroll
    for (int mt = 0; mt < 2; mt++) {
        #pragma unroll
        for (int nt = 0; nt < 4; nt++) {
            #pragma unroll
            for (int r = 0; r < 4; r++) {
                int m = wm * 32 + mt * 16 + (lane >> 2) + ((r >> 1) * 8);
                int n = wn * 32 + nt * 8 + (lane & 3) * 2 + (r & 1);
                sT[n * SJ_LD + m] = acc[mt][nt][r];
            }
        }
    }
    __syncthreads();

    // write S (coalesced) + d2 keys (in-place), then per-concept min/max
    {
        int j = tid & 127, nh = tid >> 7;
        float myb = row_sq[j];
        int jg = jbase + j;
        bool ok = (jg < NBANK);
        #pragma unroll 8
        for (int n = nh * 32; n < nh * 32 + 32; n++) {
            float s = sT[n * SJ_LD + j];
            if (ok) g_S[(size_t)n * NBANK + jg] = s;
            float d2 = fmaxf(__fmaf_rn(-2.f, s, s_csq[n] + myb), 0.f);
            ((unsigned*)sT)[n * SJ_LD + j] = __float_as_uint(d2);
        }
    }
    __syncthreads();
    {
        int n = tid >> 2, seg = tid & 3;
        unsigned mn = 0xffffffffu, mx = 0u;
        const unsigned* u = (const unsigned*)sT + n * SJ_LD + seg * 32;
        #pragma unroll 8
        for (int i = 0; i < 32; i++) {
            unsigned k = u[i];
            mn = min(mn, k); mx = max(mx, k);
        }
        mn = min(mn, __shfl_xor_sync(0xffffffffu, mn, 1, 4));
        mn = min(mn, __shfl_xor_sync(0xffffffffu, mn, 2, 4));
        mx = max(mx, __shfl_xor_sync(0xffffffffu, mx, 1, 4));
        mx = max(mx, __shfl_xor_sync(0xffffffffu, mx, 2, 4));
        if (seg == 0) { atomicMin(&g_kmin[n], mn); atomicMax(&g_kmax[n], mx); }
    }
}

// ------------------- per-concept exact top-64 (2 passes) -------------------
#define SELCAP 3072
__global__ void __launch_bounds__(1024) select_topk()
{
    int n = blockIdx.x;
    int tid = threadIdx.x;
    int lane = tid & 31, w = tid >> 5;
    const float4* Srow = (const float4*)(g_S + (size_t)n * NBANK);
    const float4* Bsq  = (const float4*)g_bank_sq;
    float csq = g_gram[n * NC + n];

    __shared__ unsigned hist[4096];
    __shared__ unsigned wbufa[32];
    __shared__ float    fred[32];
    __shared__ unsigned cand_key[SELCAP];
    __shared__ float    cand_S[SELCAP];
    __shared__ unsigned s_cnt, s_cb1;
    __shared__ int      s_b1;
    __shared__ float    s_below;

    unsigned kmin0 = g_kmin[n];
    unsigned range = g_kmax[n] - kmin0;
    unsigned sh = (range >= 4096u) ? (unsigned)(32 - __clz(range) - 12) : 0u;

    for (int i = tid; i < 4096; i += 1024) hist[i] = 0;
    if (tid == 0) s_cnt = 0;
    __syncthreads();

    // ---- pass 1: histogram ----
    for (int j4 = tid; j4 < NBANK / 4; j4 += 1024) {
        float4 sv = Srow[j4];
        float4 bv = Bsq[j4];
        float ss[4] = {sv.x, sv.y, sv.z, sv.w};
        float bb[4] = {bv.x, bv.y, bv.z, bv.w};
        #pragma unroll
        for (int t = 0; t < 4; t++) {
            float d2 = fmaxf(__fmaf_rn(-2.f, ss[t], csq + bb[t]), 0.f);
            unsigned key = __float_as_uint(d2);
            unsigned b = (key < kmin0) ? 0u : min((key - kmin0) >> sh, 4095u);
            atomicAdd(&hist[b], 1u);
        }
    }
    __syncthreads();

    // ---- scan: find boundary bin ----
    {
        unsigned h0 = hist[tid*4], h1 = hist[tid*4+1], h2 = hist[tid*4+2], h3 = hist[tid*4+3];
        unsigned tsum = h0 + h1 + h2 + h3;
        unsigned v = tsum;
        #pragma unroll
        for (int o = 1; o < 32; o <<= 1) {
            unsigned u = __shfl_up_sync(0xffffffffu, v, o);
            if (lane >= o) v += u;
        }
        if (lane == 31) wbufa[w] = v;
        __syncthreads();
        if (tid < 32) {
            unsigned x = wbufa[tid];
            #pragma unroll
            for (int o = 1; o < 32; o <<= 1) {
                unsigned u = __shfl_up_sync(0xffffffffu, x, o);
                if (tid >= o) x += u;
            }
            wbufa[tid] = x;
        }
        __syncthreads();
        unsigned excl = v - tsum + (w ? wbufa[w - 1] : 0u);
        if (excl < KSEL && excl + tsum >= KSEL) {
            unsigned c = excl;
            unsigned hh[4] = {h0, h1, h2, h3};
            int i = 0;
            while (i < 3 && c + hh[i] < KSEL) { c += hh[i]; i++; }
            s_b1 = tid * 4 + i; s_cb1 = c;
        }
    }
    __syncthreads();
    int b1 = s_b1;

    // ---- pass 2: sum dots strictly below; collect boundary candidates ----
    float sum = 0.f;
    for (int j4 = tid; j4 < NBANK / 4; j4 += 1024) {
        float4 sv = Srow[j4];
        float4 bv = Bsq[j4];
        float ss[4] = {sv.x, sv.y, sv.z, sv.w};
        float bb[4] = {bv.x, bv.y, bv.z, bv.w};
        #pragma unroll
        for (int t = 0; t < 4; t++) {
            float d2 = fmaxf(__fmaf_rn(-2.f, ss[t], csq + bb[t]), 0.f);
            unsigned key = __float_as_uint(d2);
            int b = (key < kmin0) ? 0 : (int)min((key - kmin0) >> sh, 4095u);
            if (b < b1) sum += ss[t];
            else if (b == b1) {
                unsigned p = atomicAdd(&s_cnt, 1u);
                if (p < SELCAP) { cand_key[p] = key; cand_S[p] = ss[t]; }
            }
        }
    }
    #pragma unroll
    for (int o = 16; o; o >>= 1) sum += __shfl_xor_sync(0xffffffffu, sum, o);
    if (lane == 0) fred[w] = sum;
    __syncthreads();
    if (tid < 32) {
        float x = fred[tid];
        #pragma unroll
        for (int o = 16; o; o >>= 1) x += __shfl_xor_sync(0xffffffffu, x, o);
        if (tid == 0) s_below = x;
    }
    __syncthreads();

    // ---- warp 0 picks remaining r smallest among candidates ----
    int r = KSEL - (int)s_cb1;
    int m = (int)min(s_cnt, (unsigned)SELCAP);
    if (tid < 32) {
        float extra = 0.f;
        for (int it = 0; it < r; it++) {
            unsigned best = 0xffffffffu, bsec = 0xffffffffu;
            int bi = -1;
            for (int i = tid; i < m; i += 32) {
                unsigned k = cand_key[i];
                unsigned sb = __float_as_uint(cand_S[i]);
                if (k < best || (k == best && sb < bsec)) { best = k; bsec = sb; bi = i; }
            }
            #pragma unroll
            for (int o = 16; o; o >>= 1) {
                unsigned ok  = __shfl_xor_sync(0xffffffffu, best, o);
                unsigned osb = __shfl_xor_sync(0xffffffffu, bsec, o);
                int      obi = __shfl_xor_sync(0xffffffffu, bi, o);
                if (ok < best || (ok == best && osb < bsec)) { best = ok; bsec = osb; bi = obi; }
            }
            if (tid == 0 && bi >= 0) { extra += cand_S[bi]; cand_key[bi] = 0xffffffffu; }
            __syncwarp();
        }
        if (tid == 0) g_csum[n] = s_below + extra;
    }
}

// ------------------- scalars ------------------------------------------------
__global__ void __launch_bounds__(256) finalize(float* __restrict__ out)
{
    __shared__ float r1[8], r2[8], r3[8];
    int tid = threadIdx.x, lane = tid & 31, w = tid >> 5;
    float gs = 0.f, tr = 0.f;
    for (int i = tid; i < NC * NC; i += 256) {
        float v = g_gram[i];
        gs += v;
        if ((i >> 6) == (i & 63)) tr += v;
    }
    float cs = (tid < NC) ? g_csum[tid] : 0.f;
    #pragma unroll
    for (int o = 16; o; o >>= 1) {
        gs += __shfl_xor_sync(0xffffffffu, gs, o);
        tr += __shfl_xor_sync(0xffffffffu, tr, o);
        cs += __shfl_xor_sync(0xffffffffu, cs, o);
    }
    if (lane == 0) { r1[w] = gs; r2[w] = tr; r3[w] = cs; }
    __syncthreads();
    if (tid == 0) {
        float GS = 0, TR = 0, CS = 0;
        for (int i = 0; i < 8; i++) { GS += r1[i]; TR += r2[i]; CS += r3[i]; }
        out[O_L1]   = CS / (float)(NC * KSEL);
        out[O_L2]   = (GS - TR) / (float)(NC * NC);
        out[O_NORM] = TR / (float)(NC * NC);
    }
}

// ----------------------------------------------------------------------------
extern "C" void kernel_launch(void* const* d_in, const int* in_sizes, int n_in,
                              void* d_out, int out_size)
{
    (void)in_sizes; (void)n_in; (void)out_size;
    const float* C    = (const float*)d_in[0];  // (512, 64)
    const float* E    = (const float*)d_in[1];  // (2048, 512)
    const float* bank = (const float*)d_in[2];  // (200000, 512)
    const float* W    = (const float*)d_in[3];  // (512, 100)
    float* out = (float*)d_out;

    float *pgram, *pinv, *pWc, *pQ;
    cudaGetSymbolAddress((void**)&pgram, g_gram);
    cudaGetSymbolAddress((void**)&pinv,  g_inv);
    cudaGetSymbolAddress((void**)&pWc,   g_Wc);
    cudaGetSymbolAddress((void**)&pQ,    g_Q);

    cudaFuncSetAttribute(big_gemm, cudaFuncAttributeMaxDynamicSharedMemorySize, BG_SMEM);

    // prep: C split/swizzle + reset min/max keys
    prep_convertC<<<1, 256>>>(C);
    // gram = C^T C ; Wc = C^T W
    sgemm64<true><<<dim3(1, 1), 256>>>(C, C, pgram, NC, NC, D, NC, NC, NC);
    sgemm64<true><<<dim3(1, 2), 256>>>(C, W, pWc, NC, NCLS, D, NC, NCLS, NCLS);
    invert64<<<1, 1024>>>();
    // orig_pred = E W ; concept_pred = E C
    sgemm64<false><<<dim3(32, 2), 256>>>(E, W, out + O_ORIG, BSZ, NCLS, D, D, NCLS, NCLS);
    sgemm64<false><<<dim3(32, 1), 256>>>(E, C, out + O_CPRED, BSZ, NC, D, D, NC, NC);
    // Q = cpred inv ; y = Q Wc
    sgemm64<false><<<dim3(32, 1), 256>>>(out + O_CPRED, pinv, pQ, BSZ, NC, NC, NC, NC, NC);
    sgemm64<false><<<dim3(32, 2), 256>>>(pQ, pWc, out + O_Y, BSZ, NCLS, NC, NC, NCLS, NCLS);
    // S = bank @ C (mma.sync bf16 3-term split) + bank_sq + d2 min/max
    big_gemm<<<(NBANK + MTILE - 1) / MTILE, 256, BG_SMEM>>>(bank);
    // exact per-concept top-64 sum of dots
    select_topk<<<NC, 1024>>>();
    finalize<<<1, 256>>>(out);
}

// round 4
// speedup vs baseline: 1.3844x; 1.0103x over previous
#include <cuda_runtime.h>
#include <cuda_bf16.h>
#include <math.h>
#include <stdint.h>

#define D      512
#define NC     64
#define NBANK  200000
#define BSZ    2048
#define NCLS   100
#define KSEL   64
#define NCHUNK 8
#define MTILE  128
#define SJ_LD  132

#define O_ORIG   0
#define O_Y      (BSZ*NCLS)
#define O_L1     (2*BSZ*NCLS)
#define O_L2     (O_L1+1)
#define O_NORM   (O_L1+2)
#define O_CPRED  (O_L1+3)

// ------------------------- device scratch ----------------------------------
__device__ unsigned g_D2[(size_t)NC*NBANK];   // d2 keys (float bits), row/concept
__device__ float    g_bank_sq[NBANK];
__device__ float    g_gram[NC*NC];
__device__ float    g_Wc[NC*NCLS];
__device__ float    g_Z[NC*NCLS];
__device__ float    g_csum[NC];
__device__ unsigned g_kmin[NC];
__device__ unsigned g_kmax[NC];
// pre-swizzled bf16 C tiles: per chunk c, tile [64 n][64 k], 8KB each
__device__ uint4    g_Bh4[NCHUNK*512];
__device__ uint4    g_Bl4[NCHUNK*512];

// ------------------------- helpers -----------------------------------------
__device__ __forceinline__ uint32_t smem_u32(const void* p) {
    uint32_t a;
    asm("{ .reg .u64 t; cvta.to.shared.u64 t, %1; cvt.u32.u64 %0, t; }"
        : "=r"(a) : "l"(p));
    return a;
}
__device__ __forceinline__ unsigned swz128(unsigned o) { return o ^ ((o >> 3) & 0x70u); }

__device__ __forceinline__ void cp16(uint32_t dst, const void* src) {
    asm volatile("cp.async.cg.shared.global [%0], [%1], 16;" :: "r"(dst), "l"(src));
}
#define CP_COMMIT() asm volatile("cp.async.commit_group;" ::: "memory")
#define CP_WAIT0()  asm volatile("cp.async.wait_group 0;" ::: "memory")
#define CP_WAIT1()  asm volatile("cp.async.wait_group 1;" ::: "memory")

#define LDMX4(r, a) \
    asm volatile("ldmatrix.sync.aligned.m8n8.x4.shared.b16 {%0,%1,%2,%3}, [%4];" \
        : "=r"((r)[0]), "=r"((r)[1]), "=r"((r)[2]), "=r"((r)[3]) : "r"(a))

#define MMA16816(d, a, b0, b1) \
    asm volatile("mma.sync.aligned.m16n8k16.row.col.f32.bf16.bf16.f32 " \
        "{%0,%1,%2,%3}, {%4,%5,%6,%7}, {%8,%9}, {%0,%1,%2,%3};" \
        : "+f"((d)[0]), "+f"((d)[1]), "+f"((d)[2]), "+f"((d)[3]) \
        : "r"((a)[0]), "r"((a)[1]), "r"((a)[2]), "r"((a)[3]), "r"(b0), "r"(b1))

// ------------------- prep: split+swizzle C, reset min/max ------------------
__global__ void __launch_bounds__(256) prep_convertC(const float* __restrict__ C)
{
    int tid = threadIdx.x;
    char* bh = (char*)g_Bh4;
    char* bl = (char*)g_Bl4;
    for (int idx = tid; idx < D * NC; idx += 256) {
        int n = idx & 63, k = idx >> 6;
        float x = C[idx];
        __nv_bfloat16 h = __float2bfloat16_rn(x);
        float hf = __bfloat162float(h);
        __nv_bfloat16 l = __float2bfloat16_rn(x - hf);
        int c = k >> 6, kk = k & 63;
        unsigned off = swz128((unsigned)(n * 128 + kk * 2));
        *(__nv_bfloat16*)(bh + c * 8192 + off) = h;
        *(__nv_bfloat16*)(bl + c * 8192 + off) = l;
    }
    if (tid < NC) { g_kmin[tid] = 0xffffffffu; g_kmax[tid] = 0u; }
}

// ------------------- small SGEMM (coalesced staging) ------------------------
template <bool ATRANS>
__global__ void __launch_bounds__(256) sgemm64(
    const float* __restrict__ A, const float* __restrict__ B, float* __restrict__ Co,
    int M, int N, int K, int lda, int ldb, int ldc)
{
    __shared__ float As[64][33];
    __shared__ __align__(16) float Bs[32][64];
    int tid = threadIdx.x;
    int m0 = blockIdx.x * 64, n0 = blockIdx.y * 64;
    int tx = tid & 15, ty = tid >> 4;
    float acc[4][4] = {};

    for (int k0 = 0; k0 < K; k0 += 32) {
        #pragma unroll
        for (int e = 0; e < 8; e++) {
            int idx = e * 256 + tid;
            if (ATRANS) {
                int m = idx & 63, k = idx >> 6;
                As[m][k] = A[(size_t)(k0 + k) * lda + (m0 + m)];
            } else {
                int k = idx & 31, m = idx >> 5;
                As[m][k] = A[(size_t)(m0 + m) * lda + (k0 + k)];
            }
            int n = idx & 63, k2 = idx >> 6;
            int nn = n0 + n;
            Bs[k2][n] = (nn < N) ? B[(size_t)(k0 + k2) * ldb + nn] : 0.f;
        }
        __syncthreads();
        #pragma unroll
        for (int k = 0; k < 32; k++) {
            float a0 = As[tx * 4 + 0][k];
            float a1 = As[tx * 4 + 1][k];
            float a2 = As[tx * 4 + 2][k];
            float a3 = As[tx * 4 + 3][k];
            float4 bv = *(const float4*)&Bs[k][ty * 4];
            acc[0][0] += a0 * bv.x; acc[0][1] += a0 * bv.y; acc[0][2] += a0 * bv.z; acc[0][3] += a0 * bv.w;
            acc[1][0] += a1 * bv.x; acc[1][1] += a1 * bv.y; acc[1][2] += a1 * bv.z; acc[1][3] += a1 * bv.w;
            acc[2][0] += a2 * bv.x; acc[2][1] += a2 * bv.y; acc[2][2] += a2 * bv.z; acc[2][3] += a2 * bv.w;
            acc[3][0] += a3 * bv.x; acc[3][1] += a3 * bv.y; acc[3][2] += a3 * bv.z; acc[3][3] += a3 * bv.w;
        }
        __syncthreads();
    }
    #pragma unroll
    for (int i = 0; i < 4; i++) {
        int m = m0 + tx * 4 + i;
        #pragma unroll
        for (int e = 0; e < 4; e++) {
            int nn = n0 + ty * 4 + e;
            if (nn < N) Co[(size_t)m * ldc + nn] = acc[i][e];
        }
    }
}

// ------------------- solve: Z = G^{-1} Wc via GJ on [G|Wc] -------------------
__global__ void __launch_bounds__(256) solve64()
{
    __shared__ float a[64][168];
    __shared__ float fcol[64];
    int tid = threadIdx.x;
    int r = tid >> 2, cq = tid & 3;
    int c0 = cq * 41;

    for (int i = tid; i < 64 * 64; i += 256) a[i >> 6][i & 63] = g_gram[i];
    for (int i = tid; i < 64 * NCLS; i += 256) a[i / NCLS][64 + i % NCLS] = g_Wc[i];
    __syncthreads();
    if (cq == 0) fcol[r] = a[r][0];
    __syncthreads();

    for (int p = 0; p < 64; p++) {
        float pv = 1.f / fcol[p];
        float f = fcol[r];
        float ap[41];
        #pragma unroll
        for (int i = 0; i < 41; i++) ap[i] = a[p][c0 + i] * pv;
        __syncthreads();
        if (r == p) {
            #pragma unroll
            for (int i = 0; i < 41; i++) {
                a[p][c0 + i] = ap[i];
                if (c0 + i == p + 1) fcol[p] = ap[i];
            }
        } else {
            #pragma unroll
            for (int i = 0; i < 41; i++) {
                float v = __fmaf_rn(-f, ap[i], a[r][c0 + i]);
                a[r][c0 + i] = v;
                if (c0 + i == p + 1) fcol[r] = v;
            }
        }
        __syncthreads();
    }
    for (int i = tid; i < 64 * NCLS; i += 256) g_Z[i] = a[i / NCLS][64 + i % NCLS];
}

// ------------------- big GEMM: cp.async pipelined mma.sync -------------------
// d2 keys written to g_D2; bank_sq + per-concept key min/max fused.
// SMEM layout (base0, 1024-aligned):
//  [0,65536)        raw fp32 bank chunk, double buffer (2 x 32KB)  (epilogue: sT)
//  [65536,98304)    B tiles double buffer (2 x {Bh 8K, Bl 8K})
//  [98304,114688)   Ah   [114688,131072) Al
//  [131072,..)      row_sq(512B), csq(256B)
#define BG_SMEM (131840 + 1024)
__global__ void __launch_bounds__(256) big_gemm(const float* __restrict__ bank)
{
    extern __shared__ char sm[];
    uint32_t rawbase = smem_u32(sm);
    uint32_t base0 = (rawbase + 1023) & ~1023u;
    char* smp = sm + (base0 - rawbase);
    const int tid = threadIdx.x;
    const int lane = tid & 31, w = tid >> 5;
    const int wm = w & 3, wn = w >> 2;

    const uint32_t RAW = base0;
    const uint32_t BB  = base0 + 65536;
    const uint32_t AH  = base0 + 98304;
    const uint32_t AL  = base0 + 114688;
    float* row_sq = (float*)(smp + 131072);
    float* s_csq  = (float*)(smp + 131584);

    if (tid < NC) s_csq[tid] = g_gram[tid * NC + tid];

    const int jbase = blockIdx.x * MTILE;
    const int r0 = tid >> 4, qa = tid & 15;
    float sq[8] = {};
    float acc[2][4][4] = {};
    const int arow = wm * 32 + (lane & 15);
    const int brow = wn * 32 + (lane & 15);
    const unsigned khb = (unsigned)(lane >> 4) * 16;

    auto issue = [&](int c, int b) {
        #pragma unroll
        for (int e = 0; e < 8; e++) {
            int s = e * 256 + tid;
            int r = s >> 4, cs = s & 15;
            int j = jbase + r; if (j >= NBANK) j = NBANK - 1;
            cp16(RAW + b * 32768 + s * 16, bank + (size_t)j * D + c * 64 + cs * 4);
        }
        #pragma unroll
        for (int e = 0; e < 2; e++) {
            int s = e * 256 + tid;
            cp16(BB + b * 16384 + s * 16,        g_Bh4 + c * 512 + s);
            cp16(BB + b * 16384 + 8192 + s * 16, g_Bl4 + c * 512 + s);
        }
    };

    issue(0, 0); CP_COMMIT();

    for (int c = 0; c < NCHUNK; c++) {
        if (c) __syncthreads();                 // prev compute done; buffers reusable
        if (c + 1 < NCHUNK) { issue(c + 1, (c + 1) & 1); CP_COMMIT(); CP_WAIT1(); }
        else CP_WAIT0();
        __syncthreads();                        // chunk c data visible

        // convert raw -> Ah/Al (swizzled), accumulate sumsq
        const char* rb = smp + (c & 1) * 32768;
        #pragma unroll
        for (int p = 0; p < 8; p++) {
            int r = p * 16 + r0;
            float4 v = *(const float4*)(rb + r * 256 + qa * 16);
            sq[p] += v.x * v.x + v.y * v.y + v.z * v.z + v.w * v.w;
            __nv_bfloat162 h0 = __floats2bfloat162_rn(v.x, v.y);
            __nv_bfloat162 h1 = __floats2bfloat162_rn(v.z, v.w);
            float lx = v.x - __low2float(h0),  ly = v.y - __high2float(h0);
            float lz = v.z - __low2float(h1),  lw = v.w - __high2float(h1);
            __nv_bfloat162 l0 = __floats2bfloat162_rn(lx, ly);
            __nv_bfloat162 l1 = __floats2bfloat162_rn(lz, lw);
            unsigned off = swz128((unsigned)(r * 128 + qa * 8));
            uint2 hv, lv;
            hv.x = *(unsigned*)&h0; hv.y = *(unsigned*)&h1;
            lv.x = *(unsigned*)&l0; lv.y = *(unsigned*)&l1;
            *(uint2*)(smp + 98304  + off) = hv;
            *(uint2*)(smp + 114688 + off) = lv;
        }
        __syncthreads();                        // Ah/Al ready

        const uint32_t BH = BB + (c & 1) * 16384;
        const uint32_t BL = BH + 8192;
        #pragma unroll
        for (int kc = 0; kc < 4; kc++) {
            uint32_t ah[2][4], al[2][4], bh4[2][4], bl4[2][4];
            #pragma unroll
            for (int mt = 0; mt < 2; mt++) {
                unsigned o = swz128((unsigned)((arow + mt * 16) * 128 + kc * 32 + khb));
                LDMX4(ah[mt], AH + o);
                LDMX4(al[mt], AL + o);
            }
            #pragma unroll
            for (int np = 0; np < 2; np++) {
                unsigned o = swz128((unsigned)((brow + np * 16) * 128 + kc * 32 + khb));
                LDMX4(bh4[np], BH + o);
                LDMX4(bl4[np], BL + o);
            }
            #pragma unroll
            for (int mt = 0; mt < 2; mt++) {
                #pragma unroll
                for (int nt = 0; nt < 4; nt++) {
                    int np = nt >> 1, hf = nt & 1;
                    MMA16816(acc[mt][nt], ah[mt], bh4[np][hf], bh4[np][hf + 2]);
                    MMA16816(acc[mt][nt], ah[mt], bl4[np][hf], bl4[np][hf + 2]);
                    MMA16816(acc[mt][nt], al[mt], bh4[np][hf], bh4[np][hf + 2]);
                }
            }
        }
    }

    // row sumsq
    #pragma unroll
    for (int p = 0; p < 8; p++) {
        #pragma unroll
        for (int o = 8; o; o >>= 1)
            sq[p] += __shfl_xor_sync(0xffffffffu, sq[p], o, 16);
    }
    if (qa == 0) {
        #pragma unroll
        for (int p = 0; p < 8; p++) {
            int r = p * 16 + r0, j = jbase + r;
            row_sq[r] = sq[p];
            if (j < NBANK) g_bank_sq[j] = sq[p];
        }
    }
    __syncthreads();     // compute done; reuse RAW region as fp32 [n][SJ_LD] tile

    float* sT = (float*)smp;
    #pragma unroll
    for (int mt = 0; mt < 2; mt++) {
        #pragma unroll
        for (int nt = 0; nt < 4; nt++) {
            #pragma unroll
            for (int r = 0; r < 4; r++) {
                int m = wm * 32 + mt * 16 + (lane >> 2) + ((r >> 1) * 8);
                int n = wn * 32 + nt * 8 + (lane & 3) * 2 + (r & 1);
                sT[n * SJ_LD + m] = acc[mt][nt][r];
            }
        }
    }
    __syncthreads();

    // write d2 keys (coalesced), stash keys in-place for min/max
    {
        int j = tid & 127, nh = tid >> 7;
        float myb = row_sq[j];
        int jg = jbase + j;
        bool ok = (jg < NBANK);
        #pragma unroll 8
        for (int n = nh * 32; n < nh * 32 + 32; n++) {
            float s = sT[n * SJ_LD + j];
            float d2 = fmaxf(__fmaf_rn(-2.f, s, s_csq[n] + myb), 0.f);
            unsigned key = __float_as_uint(d2);
            if (ok) g_D2[(size_t)n * NBANK + jg] = key;
            ((unsigned*)sT)[n * SJ_LD + j] = key;
        }
    }
    __syncthreads();
    {
        int n = tid >> 2, seg = tid & 3;
        unsigned mn = 0xffffffffu, mx = 0u;
        const unsigned* u = (const unsigned*)sT + n * SJ_LD + seg * 32;
        #pragma unroll 8
        for (int i = 0; i < 32; i++) {
            unsigned k = u[i];
            mn = min(mn, k); mx = max(mx, k);
        }
        mn = min(mn, __shfl_xor_sync(0xffffffffu, mn, 1, 4));
        mn = min(mn, __shfl_xor_sync(0xffffffffu, mn, 2, 4));
        mx = max(mx, __shfl_xor_sync(0xffffffffu, mx, 1, 4));
        mx = max(mx, __shfl_xor_sync(0xffffffffu, mx, 2, 4));
        if (seg == 0) { atomicMin(&g_kmin[n], mn); atomicMax(&g_kmax[n], mx); }
    }
}

// ------------------- per-concept exact top-64 over d2 keys ------------------
#define SELCAP 2048
__global__ void __launch_bounds__(1024) select_topk()
{
    int n = blockIdx.x;
    int tid = threadIdx.x;
    int lane = tid & 31, w = tid >> 5;
    const uint4* keys = (const uint4*)(g_D2 + (size_t)n * NBANK);
    float csq = g_gram[n * NC + n];

    __shared__ unsigned hist[4096];
    __shared__ unsigned wbufa[32];
    __shared__ float    fred[32], fred2[32];
    __shared__ unsigned cand_key[SELCAP];
    __shared__ int      cand_j[SELCAP];
    __shared__ unsigned s_cnt, s_cb1;
    __shared__ int      s_b1;
    __shared__ float    s_d2b, s_bqb;

    unsigned kmin0 = g_kmin[n];
    unsigned range = g_kmax[n] - kmin0;
    unsigned sh = (range >= 4096u) ? (unsigned)(32 - __clz(range) - 12) : 0u;

    for (int i = tid; i < 4096; i += 1024) hist[i] = 0;
    if (tid == 0) s_cnt = 0;
    __syncthreads();

    // pass 1: histogram
    for (int j4 = tid; j4 < NBANK / 4; j4 += 1024) {
        uint4 kv = keys[j4];
        unsigned ka[4] = {kv.x, kv.y, kv.z, kv.w};
        #pragma unroll
        for (int t = 0; t < 4; t++) {
            unsigned key = ka[t];
            unsigned b = (key < kmin0) ? 0u : min((key - kmin0) >> sh, 4095u);
            atomicAdd(&hist[b], 1u);
        }
    }
    __syncthreads();

    // scan: boundary bin
    {
        unsigned h0 = hist[tid*4], h1 = hist[tid*4+1], h2 = hist[tid*4+2], h3 = hist[tid*4+3];
        unsigned tsum = h0 + h1 + h2 + h3;
        unsigned v = tsum;
        #pragma unroll
        for (int o = 1; o < 32; o <<= 1) {
            unsigned u = __shfl_up_sync(0xffffffffu, v, o);
            if (lane >= o) v += u;
        }
        if (lane == 31) wbufa[w] = v;
        __syncthreads();
        if (tid < 32) {
            unsigned x = wbufa[tid];
            #pragma unroll
            for (int o = 1; o < 32; o <<= 1) {
                unsigned u = __shfl_up_sync(0xffffffffu, x, o);
                if (tid >= o) x += u;
            }
            wbufa[tid] = x;
        }
        __syncthreads();
        unsigned excl = v - tsum + (w ? wbufa[w - 1] : 0u);
        if (excl < KSEL && excl + tsum >= KSEL) {
            unsigned c = excl;
            unsigned hh[4] = {h0, h1, h2, h3};
            int i = 0;
            while (i < 3 && c + hh[i] < KSEL) { c += hh[i]; i++; }
            s_b1 = tid * 4 + i; s_cb1 = c;
        }
    }
    __syncthreads();
    int b1 = s_b1;

    // pass 2: definite winners (b<b1) summed directly; boundary bin collected
    float d2s = 0.f, bqs = 0.f;
    for (int j4 = tid; j4 < NBANK / 4; j4 += 1024) {
        uint4 kv = keys[j4];
        unsigned ka[4] = {kv.x, kv.y, kv.z, kv.w};
        #pragma unroll
        for (int t = 0; t < 4; t++) {
            unsigned key = ka[t];
            int b = (key < kmin0) ? 0 : (int)min((key - kmin0) >> sh, 4095u);
            if (b < b1) {
                d2s += __uint_as_float(key);
                bqs += g_bank_sq[j4 * 4 + t];
            } else if (b == b1) {
                unsigned p = atomicAdd(&s_cnt, 1u);
                if (p < SELCAP) { cand_key[p] = key; cand_j[p] = j4 * 4 + t; }
            }
        }
    }
    #pragma unroll
    for (int o = 16; o; o >>= 1) {
        d2s += __shfl_xor_sync(0xffffffffu, d2s, o);
        bqs += __shfl_xor_sync(0xffffffffu, bqs, o);
    }
    if (lane == 0) { fred[w] = d2s; fred2[w] = bqs; }
    __syncthreads();
    if (tid < 32) {
        float x = fred[tid], y = fred2[tid];
        #pragma unroll
        for (int o = 16; o; o >>= 1) {
            x += __shfl_xor_sync(0xffffffffu, x, o);
            y += __shfl_xor_sync(0xffffffffu, y, o);
        }
        if (tid == 0) { s_d2b = x; s_bqb = y; }
    }
    __syncthreads();

    // warp 0: pick remaining r smallest (key, j) among boundary candidates
    int r = KSEL - (int)s_cb1;
    int m = (int)min(s_cnt, (unsigned)SELCAP);
    if (tid < 32) {
        float d2x = 0.f, bqx = 0.f;
        for (int it = 0; it < r; it++) {
            unsigned best = 0xffffffffu;
            int bestj = 0x7fffffff, bi = -1;
            for (int i = tid; i < m; i += 32) {
                unsigned k = cand_key[i];
                int jj = cand_j[i];
                if (k < best || (k == best && jj < bestj)) { best = k; bestj = jj; bi = i; }
            }
            #pragma unroll
            for (int o = 16; o; o >>= 1) {
                unsigned ok = __shfl_xor_sync(0xffffffffu, best, o);
                int      oj = __shfl_xor_sync(0xffffffffu, bestj, o);
                int      ob = __shfl_xor_sync(0xffffffffu, bi, o);
                if (ok < best || (ok == best && oj < bestj)) { best = ok; bestj = oj; bi = ob; }
            }
            if (tid == 0 && bi >= 0) {
                d2x += __uint_as_float(best);
                bqx += g_bank_sq[bestj];
                cand_key[bi] = 0xffffffffu;
                cand_j[bi] = 0x7fffffff;
            }
            __syncwarp();
        }
        if (tid == 0)
            g_csum[n] = 0.5f * ((float)KSEL * csq + (s_bqb + bqx) - (s_d2b + d2x));
    }
}

// ------------------- scalars ------------------------------------------------
__global__ void __launch_bounds__(256) finalize(float* __restrict__ out)
{
    __shared__ float r1[8], r2[8], r3[8];
    int tid = threadIdx.x, lane = tid & 31, w = tid >> 5;
    float gs = 0.f, tr = 0.f;
    for (int i = tid; i < NC * NC; i += 256) {
        float v = g_gram[i];
        gs += v;
        if ((i >> 6) == (i & 63)) tr += v;
    }
    float cs = (tid < NC) ? g_csum[tid] : 0.f;
    #pragma unroll
    for (int o = 16; o; o >>= 1) {
        gs += __shfl_xor_sync(0xffffffffu, gs, o);
        tr += __shfl_xor_sync(0xffffffffu, tr, o);
        cs += __shfl_xor_sync(0xffffffffu, cs, o);
    }
    if (lane == 0) { r1[w] = gs; r2[w] = tr; r3[w] = cs; }
    __syncthreads();
    if (tid == 0) {
        float GS = 0, TR = 0, CS = 0;
        for (int i = 0; i < 8; i++) { GS += r1[i]; TR += r2[i]; CS += r3[i]; }
        out[O_L1]   = CS / (float)(NC * KSEL);
        out[O_L2]   = (GS - TR) / (float)(NC * NC);
        out[O_NORM] = TR / (float)(NC * NC);
    }
}

// ----------------------------------------------------------------------------
extern "C" void kernel_launch(void* const* d_in, const int* in_sizes, int n_in,
                              void* d_out, int out_size)
{
    (void)in_sizes; (void)n_in; (void)out_size;
    const float* C    = (const float*)d_in[0];  // (512, 64)
    const float* E    = (const float*)d_in[1];  // (2048, 512)
    const float* bank = (const float*)d_in[2];  // (200000, 512)
    const float* W    = (const float*)d_in[3];  // (512, 100)
    float* out = (float*)d_out;

    float *pgram, *pWc, *pZ;
    cudaGetSymbolAddress((void**)&pgram, g_gram);
    cudaGetSymbolAddress((void**)&pWc,   g_Wc);
    cudaGetSymbolAddress((void**)&pZ,    g_Z);

    cudaFuncSetAttribute(big_gemm, cudaFuncAttributeMaxDynamicSharedMemorySize, BG_SMEM);

    prep_convertC<<<1, 256>>>(C);
    // gram = C^T C ; Wc = C^T W
    sgemm64<true><<<dim3(1, 1), 256>>>(C, C, pgram, NC, NC, D, NC, NC, NC);
    sgemm64<true><<<dim3(1, 2), 256>>>(C, W, pWc, NC, NCLS, D, NC, NCLS, NCLS);
    // Z = inv(gram) @ Wc
    solve64<<<1, 256>>>();
    // orig_pred = E W ; concept_pred = E C ; y = cpred Z
    sgemm64<false><<<dim3(32, 2), 256>>>(E, W, out + O_ORIG, BSZ, NCLS, D, D, NCLS, NCLS);
    sgemm64<false><<<dim3(32, 1), 256>>>(E, C, out + O_CPRED, BSZ, NC, D, D, NC, NC);
    sgemm64<false><<<dim3(32, 2), 256>>>(out + O_CPRED, pZ, out + O_Y, BSZ, NCLS, NC, NC, NCLS, NCLS);
    // d2 keys = f(bank @ C) via pipelined mma.sync + bank_sq + key min/max
    big_gemm<<<(NBANK + MTILE - 1) / MTILE, 256, BG_SMEM>>>(bank);
    // exact per-concept top-64 (sum of dots reconstructed from d2)
    select_topk<<<NC, 1024>>>();
    finalize<<<1, 256>>>(out);
}

// round 5
// speedup vs baseline: 1.5946x; 1.1519x over previous
#include <cuda_runtime.h>
#include <cuda_bf16.h>
#include <math.h>
#include <stdint.h>

#define D      512
#define NC     64
#define NBANK  200000
#define BSZ    2048
#define NCLS   100
#define KSEL   64
#define NCHUNK 8
#define MTILE  128
#define SJ_LD  132
#define NWC    164   // concat [W | C] columns

#define O_ORIG   0
#define O_Y      (BSZ*NCLS)
#define O_L1     (2*BSZ*NCLS)
#define O_L2     (O_L1+1)
#define O_NORM   (O_L1+2)
#define O_CPRED  (O_L1+3)

// ------------------------- device scratch ----------------------------------
__device__ unsigned g_D2[(size_t)NC*NBANK];   // d2 keys (float bits), row/concept
__device__ float    g_bank_sq[NBANK];
__device__ float    g_gram[NC*NC];
__device__ float    g_Wc[NC*NCLS];
__device__ float    g_Z[NC*NCLS];
__device__ float    g_WC[D*NWC];
__device__ float    g_csum[NC];
__device__ unsigned g_kmin[NC];
__device__ unsigned g_kmax[NC];
// pre-swizzled bf16 C tiles: per chunk c, tile [64 n][64 k], 8KB each
__device__ uint4    g_Bh4[NCHUNK*512];
__device__ uint4    g_Bl4[NCHUNK*512];

// ------------------------- helpers -----------------------------------------
__device__ __forceinline__ uint32_t smem_u32(const void* p) {
    uint32_t a;
    asm("{ .reg .u64 t; cvta.to.shared.u64 t, %1; cvt.u32.u64 %0, t; }"
        : "=r"(a) : "l"(p));
    return a;
}
__device__ __forceinline__ unsigned swz128(unsigned o) { return o ^ ((o >> 3) & 0x70u); }

__device__ __forceinline__ void cp16(uint32_t dst, const void* src) {
    asm volatile("cp.async.cg.shared.global [%0], [%1], 16;" :: "r"(dst), "l"(src));
}
#define CP_COMMIT() asm volatile("cp.async.commit_group;" ::: "memory")
#define CP_WAIT0()  asm volatile("cp.async.wait_group 0;" ::: "memory")
#define CP_WAIT1()  asm volatile("cp.async.wait_group 1;" ::: "memory")

#define LDMX4(r, a) \
    asm volatile("ldmatrix.sync.aligned.m8n8.x4.shared.b16 {%0,%1,%2,%3}, [%4];" \
        : "=r"((r)[0]), "=r"((r)[1]), "=r"((r)[2]), "=r"((r)[3]) : "r"(a))

#define MMA16816(d, a, b0, b1) \
    asm volatile("mma.sync.aligned.m16n8k16.row.col.f32.bf16.bf16.f32 " \
        "{%0,%1,%2,%3}, {%4,%5,%6,%7}, {%8,%9}, {%0,%1,%2,%3};" \
        : "+f"((d)[0]), "+f"((d)[1]), "+f"((d)[2]), "+f"((d)[3]) \
        : "r"((a)[0]), "r"((a)[1]), "r"((a)[2]), "r"((a)[3]), "r"(b0), "r"(b1))

// ------------- prep: split+swizzle C, build [W|C], reset min/max ------------
__global__ void __launch_bounds__(256) prep(const float* __restrict__ C,
                                            const float* __restrict__ W)
{
    int tid = threadIdx.x;
    int gtid = blockIdx.x * 256 + tid;
    int gstride = gridDim.x * 256;
    // concat [W | C] row-major [k][164]
    for (int idx = gtid; idx < D * NWC; idx += gstride) {
        int k = idx / NWC, n = idx % NWC;
        g_WC[idx] = (n < NCLS) ? W[k * NCLS + n] : C[k * NC + (n - NCLS)];
    }
    if (blockIdx.x == 0) {
        char* bh = (char*)g_Bh4;
        char* bl = (char*)g_Bl4;
        for (int idx = tid; idx < D * NC; idx += 256) {
            int n = idx & 63, k = idx >> 6;
            float x = C[idx];
            __nv_bfloat16 h = __float2bfloat16_rn(x);
            float hf = __bfloat162float(h);
            __nv_bfloat16 l = __float2bfloat16_rn(x - hf);
            int c = k >> 6, kk = k & 63;
            unsigned off = swz128((unsigned)(n * 128 + kk * 2));
            *(__nv_bfloat16*)(bh + c * 8192 + off) = h;
            *(__nv_bfloat16*)(bl + c * 8192 + off) = l;
        }
        if (tid < NC) { g_kmin[tid] = 0xffffffffu; g_kmax[tid] = 0u; }
    }
}

// ------------------- small SGEMM (coalesced staging) ------------------------
// SPLIT: n<NCLS -> Co (ld NCLS), n>=NCLS -> Co2 (ld NC)
template <bool ATRANS, bool SPLIT>
__global__ void __launch_bounds__(256) sgemm64(
    const float* __restrict__ A, const float* __restrict__ B,
    float* __restrict__ Co, float* __restrict__ Co2,
    int M, int N, int K, int lda, int ldb, int ldc)
{
    __shared__ float As[64][33];
    __shared__ __align__(16) float Bs[32][64];
    int tid = threadIdx.x;
    int m0 = blockIdx.x * 64, n0 = blockIdx.y * 64;
    int tx = tid & 15, ty = tid >> 4;
    float acc[4][4] = {};

    for (int k0 = 0; k0 < K; k0 += 32) {
        #pragma unroll
        for (int e = 0; e < 8; e++) {
            int idx = e * 256 + tid;
            if (ATRANS) {
                int m = idx & 63, k = idx >> 6;
                As[m][k] = A[(size_t)(k0 + k) * lda + (m0 + m)];
            } else {
                int k = idx & 31, m = idx >> 5;
                As[m][k] = A[(size_t)(m0 + m) * lda + (k0 + k)];
            }
            int n = idx & 63, k2 = idx >> 6;
            int nn = n0 + n;
            Bs[k2][n] = (nn < N) ? B[(size_t)(k0 + k2) * ldb + nn] : 0.f;
        }
        __syncthreads();
        #pragma unroll
        for (int k = 0; k < 32; k++) {
            float a0 = As[tx * 4 + 0][k];
            float a1 = As[tx * 4 + 1][k];
            float a2 = As[tx * 4 + 2][k];
            float a3 = As[tx * 4 + 3][k];
            float4 bv = *(const float4*)&Bs[k][ty * 4];
            acc[0][0] += a0 * bv.x; acc[0][1] += a0 * bv.y; acc[0][2] += a0 * bv.z; acc[0][3] += a0 * bv.w;
            acc[1][0] += a1 * bv.x; acc[1][1] += a1 * bv.y; acc[1][2] += a1 * bv.z; acc[1][3] += a1 * bv.w;
            acc[2][0] += a2 * bv.x; acc[2][1] += a2 * bv.y; acc[2][2] += a2 * bv.z; acc[2][3] += a2 * bv.w;
            acc[3][0] += a3 * bv.x; acc[3][1] += a3 * bv.y; acc[3][2] += a3 * bv.z; acc[3][3] += a3 * bv.w;
        }
        __syncthreads();
    }
    #pragma unroll
    for (int i = 0; i < 4; i++) {
        int m = m0 + tx * 4 + i;
        #pragma unroll
        for (int e = 0; e < 4; e++) {
            int nn = n0 + ty * 4 + e;
            if (nn < N) {
                if (SPLIT) {
                    if (nn < NCLS) Co[(size_t)m * NCLS + nn] = acc[i][e];
                    else           Co2[(size_t)m * NC + (nn - NCLS)] = acc[i][e];
                } else {
                    Co[(size_t)m * ldc + nn] = acc[i][e];
                }
            }
        }
    }
}

// ---------- solve Z = G^{-1} Wc : column-owned register Gauss-Jordan --------
__global__ void __launch_bounds__(192) solve64()
{
    __shared__ float fc[64];
    int c = threadIdx.x;          // column owner: 0..163
    bool active = (c < 64 + NCLS);
    float col[64];

    if (active) {
        if (c < 64) {
            #pragma unroll
            for (int r = 0; r < 64; r++) col[r] = g_gram[r * 64 + c];
        } else {
            #pragma unroll
            for (int r = 0; r < 64; r++) col[r] = g_Wc[r * NCLS + (c - 64)];
        }
    }
    #pragma unroll
    for (int p = 0; p < 64; p++) {
        if (c == p) {
            #pragma unroll
            for (int r = 0; r < 64; r++) fc[r] = col[r];
        }
        __syncthreads();
        if (active) {
            float pinv = 1.f / fc[p];
            float piv = col[p] * pinv;
            col[p] = piv;
            #pragma unroll
            for (int r = 0; r < 64; r++)
                if (r != p) col[r] = __fmaf_rn(-fc[r], piv, col[r]);
        }
        __syncthreads();
    }
    if (c >= 64 && active) {
        #pragma unroll
        for (int r = 0; r < 64; r++) g_Z[r * NCLS + (c - 64)] = col[r];
    }
}

// ------------------- big GEMM: cp.async pipelined mma.sync -------------------
#define BG_SMEM (131840 + 1024)
__global__ void __launch_bounds__(256) big_gemm(const float* __restrict__ bank)
{
    extern __shared__ char sm[];
    uint32_t rawbase = smem_u32(sm);
    uint32_t base0 = (rawbase + 1023) & ~1023u;
    char* smp = sm + (base0 - rawbase);
    const int tid = threadIdx.x;
    const int lane = tid & 31, w = tid >> 5;
    const int wm = w & 3, wn = w >> 2;

    const uint32_t RAW = base0;
    const uint32_t BB  = base0 + 65536;
    const uint32_t AH  = base0 + 98304;
    const uint32_t AL  = base0 + 114688;
    float* row_sq = (float*)(smp + 131072);
    float* s_csq  = (float*)(smp + 131584);

    if (tid < NC) s_csq[tid] = g_gram[tid * NC + tid];

    const int jbase = blockIdx.x * MTILE;
    const int r0 = tid >> 4, qa = tid & 15;
    float sq[8] = {};
    float acc[2][4][4] = {};
    const int arow = wm * 32 + (lane & 15);
    const int brow = wn * 32 + (lane & 15);
    const unsigned khb = (unsigned)(lane >> 4) * 16;

    auto issue = [&](int c, int b) {
        #pragma unroll
        for (int e = 0; e < 8; e++) {
            int s = e * 256 + tid;
            int r = s >> 4, cs = s & 15;
            int j = jbase + r; if (j >= NBANK) j = NBANK - 1;
            cp16(RAW + b * 32768 + s * 16, bank + (size_t)j * D + c * 64 + cs * 4);
        }
        #pragma unroll
        for (int e = 0; e < 2; e++) {
            int s = e * 256 + tid;
            cp16(BB + b * 16384 + s * 16,        g_Bh4 + c * 512 + s);
            cp16(BB + b * 16384 + 8192 + s * 16, g_Bl4 + c * 512 + s);
        }
    };

    issue(0, 0); CP_COMMIT();

    for (int c = 0; c < NCHUNK; c++) {
        if (c) __syncthreads();
        if (c + 1 < NCHUNK) { issue(c + 1, (c + 1) & 1); CP_COMMIT(); CP_WAIT1(); }
        else CP_WAIT0();
        __syncthreads();

        const char* rb = smp + (c & 1) * 32768;
        #pragma unroll
        for (int p = 0; p < 8; p++) {
            int r = p * 16 + r0;
            float4 v = *(const float4*)(rb + r * 256 + qa * 16);
            sq[p] += v.x * v.x + v.y * v.y + v.z * v.z + v.w * v.w;
            __nv_bfloat162 h0 = __floats2bfloat162_rn(v.x, v.y);
            __nv_bfloat162 h1 = __floats2bfloat162_rn(v.z, v.w);
            float lx = v.x - __low2float(h0),  ly = v.y - __high2float(h0);
            float lz = v.z - __low2float(h1),  lw = v.w - __high2float(h1);
            __nv_bfloat162 l0 = __floats2bfloat162_rn(lx, ly);
            __nv_bfloat162 l1 = __floats2bfloat162_rn(lz, lw);
            unsigned off = swz128((unsigned)(r * 128 + qa * 8));
            uint2 hv, lv;
            hv.x = *(unsigned*)&h0; hv.y = *(unsigned*)&h1;
            lv.x = *(unsigned*)&l0; lv.y = *(unsigned*)&l1;
            *(uint2*)(smp + 98304  + off) = hv;
            *(uint2*)(smp + 114688 + off) = lv;
        }
        __syncthreads();

        const uint32_t BH = BB + (c & 1) * 16384;
        const uint32_t BL = BH + 8192;
        #pragma unroll
        for (int kc = 0; kc < 4; kc++) {
            uint32_t ah[2][4], al[2][4], bh4[2][4], bl4[2][4];
            #pragma unroll
            for (int mt = 0; mt < 2; mt++) {
                unsigned o = swz128((unsigned)((arow + mt * 16) * 128 + kc * 32 + khb));
                LDMX4(ah[mt], AH + o);
                LDMX4(al[mt], AL + o);
            }
            #pragma unroll
            for (int np = 0; np < 2; np++) {
                unsigned o = swz128((unsigned)((brow + np * 16) * 128 + kc * 32 + khb));
                LDMX4(bh4[np], BH + o);
                LDMX4(bl4[np], BL + o);
            }
            #pragma unroll
            for (int mt = 0; mt < 2; mt++) {
                #pragma unroll
                for (int nt = 0; nt < 4; nt++) {
                    int np = nt >> 1, hf = nt & 1;
                    MMA16816(acc[mt][nt], ah[mt], bh4[np][hf], bh4[np][hf + 2]);
                    MMA16816(acc[mt][nt], ah[mt], bl4[np][hf], bl4[np][hf + 2]);
                    MMA16816(acc[mt][nt], al[mt], bh4[np][hf], bh4[np][hf + 2]);
                }
            }
        }
    }

    // row sumsq
    #pragma unroll
    for (int p = 0; p < 8; p++) {
        #pragma unroll
        for (int o = 8; o; o >>= 1)
            sq[p] += __shfl_xor_sync(0xffffffffu, sq[p], o, 16);
    }
    if (qa == 0) {
        #pragma unroll
        for (int p = 0; p < 8; p++) {
            int r = p * 16 + r0, j = jbase + r;
            row_sq[r] = sq[p];
            if (j < NBANK) g_bank_sq[j] = sq[p];
        }
    }
    __syncthreads();

    float* sT = (float*)smp;
    #pragma unroll
    for (int mt = 0; mt < 2; mt++) {
        #pragma unroll
        for (int nt = 0; nt < 4; nt++) {
            #pragma unroll
            for (int r = 0; r < 4; r++) {
                int m = wm * 32 + mt * 16 + (lane >> 2) + ((r >> 1) * 8);
                int n = wn * 32 + nt * 8 + (lane & 3) * 2 + (r & 1);
                sT[n * SJ_LD + m] = acc[mt][nt][r];
            }
        }
    }
    __syncthreads();

    {
        int j = tid & 127, nh = tid >> 7;
        float myb = row_sq[j];
        int jg = jbase + j;
        bool ok = (jg < NBANK);
        #pragma unroll 8
        for (int n = nh * 32; n < nh * 32 + 32; n++) {
            float s = sT[n * SJ_LD + j];
            float d2 = fmaxf(__fmaf_rn(-2.f, s, s_csq[n] + myb), 0.f);
            unsigned key = __float_as_uint(d2);
            if (ok) g_D2[(size_t)n * NBANK + jg] = key;
            ((unsigned*)sT)[n * SJ_LD + j] = key;
        }
    }
    __syncthreads();
    {
        int n = tid >> 2, seg = tid & 3;
        unsigned mn = 0xffffffffu, mx = 0u;
        const unsigned* u = (const unsigned*)sT + n * SJ_LD + seg * 32;
        #pragma unroll 8
        for (int i = 0; i < 32; i++) {
            unsigned k = u[i];
            mn = min(mn, k); mx = max(mx, k);
        }
        mn = min(mn, __shfl_xor_sync(0xffffffffu, mn, 1, 4));
        mn = min(mn, __shfl_xor_sync(0xffffffffu, mn, 2, 4));
        mx = max(mx, __shfl_xor_sync(0xffffffffu, mx, 1, 4));
        mx = max(mx, __shfl_xor_sync(0xffffffffu, mx, 2, 4));
        if (seg == 0) { atomicMin(&g_kmin[n], mn); atomicMax(&g_kmax[n], mx); }
    }
}

// ------------------- per-concept exact top-64 over d2 keys ------------------
#define SELCAP 2048
__global__ void __launch_bounds__(1024) select_topk()
{
    int n = blockIdx.x;
    int tid = threadIdx.x;
    int lane = tid & 31, w = tid >> 5;
    const uint4* keys = (const uint4*)(g_D2 + (size_t)n * NBANK);
    float csq = g_gram[n * NC + n];

    __shared__ unsigned hist[4096];
    __shared__ unsigned wbufa[32];
    __shared__ float    fred[32], fred2[32];
    __shared__ unsigned cand_key[SELCAP];
    __shared__ int      cand_j[SELCAP];
    __shared__ unsigned s_cnt, s_cb1;
    __shared__ int      s_b1;
    __shared__ float    s_d2b, s_bqb;

    unsigned kmin0 = g_kmin[n];
    unsigned range = g_kmax[n] - kmin0;
    unsigned sh = (range >= 4096u) ? (unsigned)(32 - __clz(range) - 12) : 0u;

    for (int i = tid; i < 4096; i += 1024) hist[i] = 0;
    if (tid == 0) s_cnt = 0;
    __syncthreads();

    for (int j4 = tid; j4 < NBANK / 4; j4 += 1024) {
        uint4 kv = keys[j4];
        unsigned ka[4] = {kv.x, kv.y, kv.z, kv.w};
        #pragma unroll
        for (int t = 0; t < 4; t++) {
            unsigned key = ka[t];
            unsigned b = (key < kmin0) ? 0u : min((key - kmin0) >> sh, 4095u);
            atomicAdd(&hist[b], 1u);
        }
    }
    __syncthreads();

    {
        unsigned h0 = hist[tid*4], h1 = hist[tid*4+1], h2 = hist[tid*4+2], h3 = hist[tid*4+3];
        unsigned tsum = h0 + h1 + h2 + h3;
        unsigned v = tsum;
        #pragma unroll
        for (int o = 1; o < 32; o <<= 1) {
            unsigned u = __shfl_up_sync(0xffffffffu, v, o);
            if (lane >= o) v += u;
        }
        if (lane == 31) wbufa[w] = v;
        __syncthreads();
        if (tid < 32) {
            unsigned x = wbufa[tid];
            #pragma unroll
            for (int o = 1; o < 32; o <<= 1) {
                unsigned u = __shfl_up_sync(0xffffffffu, x, o);
                if (tid >= o) x += u;
            }
            wbufa[tid] = x;
        }
        __syncthreads();
        unsigned excl = v - tsum + (w ? wbufa[w - 1] : 0u);
        if (excl < KSEL && excl + tsum >= KSEL) {
            unsigned c = excl;
            unsigned hh[4] = {h0, h1, h2, h3};
            int i = 0;
            while (i < 3 && c + hh[i] < KSEL) { c += hh[i]; i++; }
            s_b1 = tid * 4 + i; s_cb1 = c;
        }
    }
    __syncthreads();
    int b1 = s_b1;

    float d2s = 0.f, bqs = 0.f;
    for (int j4 = tid; j4 < NBANK / 4; j4 += 1024) {
        uint4 kv = keys[j4];
        unsigned ka[4] = {kv.x, kv.y, kv.z, kv.w};
        #pragma unroll
        for (int t = 0; t < 4; t++) {
            unsigned key = ka[t];
            int b = (key < kmin0) ? 0 : (int)min((key - kmin0) >> sh, 4095u);
            if (b < b1) {
                d2s += __uint_as_float(key);
                bqs += g_bank_sq[j4 * 4 + t];
            } else if (b == b1) {
                unsigned p = atomicAdd(&s_cnt, 1u);
                if (p < SELCAP) { cand_key[p] = key; cand_j[p] = j4 * 4 + t; }
            }
        }
    }
    #pragma unroll
    for (int o = 16; o; o >>= 1) {
        d2s += __shfl_xor_sync(0xffffffffu, d2s, o);
        bqs += __shfl_xor_sync(0xffffffffu, bqs, o);
    }
    if (lane == 0) { fred[w] = d2s; fred2[w] = bqs; }
    __syncthreads();
    if (tid < 32) {
        float x = fred[tid], y = fred2[tid];
        #pragma unroll
        for (int o = 16; o; o >>= 1) {
            x += __shfl_xor_sync(0xffffffffu, x, o);
            y += __shfl_xor_sync(0xffffffffu, y, o);
        }
        if (tid == 0) { s_d2b = x; s_bqb = y; }
    }
    __syncthreads();

    int r = KSEL - (int)s_cb1;
    int m = (int)min(s_cnt, (unsigned)SELCAP);
    if (tid < 32) {
        float d2x = 0.f, bqx = 0.f;
        for (int it = 0; it < r; it++) {
            unsigned best = 0xffffffffu;
            int bestj = 0x7fffffff, bi = -1;
            for (int i = tid; i < m; i += 32) {
                unsigned k = cand_key[i];
                int jj = cand_j[i];
                if (k < best || (k == best && jj < bestj)) { best = k; bestj = jj; bi = i; }
            }
            #pragma unroll
            for (int o = 16; o; o >>= 1) {
                unsigned ok = __shfl_xor_sync(0xffffffffu, best, o);
                int      oj = __shfl_xor_sync(0xffffffffu, bestj, o);
                int      ob = __shfl_xor_sync(0xffffffffu, bi, o);
                if (ok < best || (ok == best && oj < bestj)) { best = ok; bestj = oj; bi = ob; }
            }
            if (tid == 0 && bi >= 0) {
                d2x += __uint_as_float(best);
                bqx += g_bank_sq[bestj];
                cand_key[bi] = 0xffffffffu;
                cand_j[bi] = 0x7fffffff;
            }
            __syncwarp();
        }
        if (tid == 0)
            g_csum[n] = 0.5f * ((float)KSEL * csq + (s_bqb + bqx) - (s_d2b + d2x));
    }
}

// ------------------- scalars ------------------------------------------------
__global__ void __launch_bounds__(256) finalize(float* __restrict__ out)
{
    __shared__ float r1[8], r2[8], r3[8];
    int tid = threadIdx.x, lane = tid & 31, w = tid >> 5;
    float gs = 0.f, tr = 0.f;
    for (int i = tid; i < NC * NC; i += 256) {
        float v = g_gram[i];
        gs += v;
        if ((i >> 6) == (i & 63)) tr += v;
    }
    float cs = (tid < NC) ? g_csum[tid] : 0.f;
    #pragma unroll
    for (int o = 16; o; o >>= 1) {
        gs += __shfl_xor_sync(0xffffffffu, gs, o);
        tr += __shfl_xor_sync(0xffffffffu, tr, o);
        cs += __shfl_xor_sync(0xffffffffu, cs, o);
    }
    if (lane == 0) { r1[w] = gs; r2[w] = tr; r3[w] = cs; }
    __syncthreads();
    if (tid == 0) {
        float GS = 0, TR = 0, CS = 0;
        for (int i = 0; i < 8; i++) { GS += r1[i]; TR += r2[i]; CS += r3[i]; }
        out[O_L1]   = CS / (float)(NC * KSEL);
        out[O_L2]   = (GS - TR) / (float)(NC * NC);
        out[O_NORM] = TR / (float)(NC * NC);
    }
}

// ----------------------------------------------------------------------------
extern "C" void kernel_launch(void* const* d_in, const int* in_sizes, int n_in,
                              void* d_out, int out_size)
{
    (void)in_sizes; (void)n_in; (void)out_size;
    const float* C    = (const float*)d_in[0];  // (512, 64)
    const float* E    = (const float*)d_in[1];  // (2048, 512)
    const float* bank = (const float*)d_in[2];  // (200000, 512)
    const float* W    = (const float*)d_in[3];  // (512, 100)
    float* out = (float*)d_out;

    float *pgram, *pWc, *pZ, *pWC;
    cudaGetSymbolAddress((void**)&pgram, g_gram);
    cudaGetSymbolAddress((void**)&pWc,   g_Wc);
    cudaGetSymbolAddress((void**)&pZ,    g_Z);
    cudaGetSymbolAddress((void**)&pWC,   g_WC);

    cudaFuncSetAttribute(big_gemm, cudaFuncAttributeMaxDynamicSharedMemorySize, BG_SMEM);

    // prep: C tiles + [W|C] concat + minmax reset
    prep<<<32, 256>>>(C, W);
    // gram = C^T C ; Wc = C^T W
    sgemm64<true, false><<<dim3(1, 1), 256>>>(C, C, pgram, nullptr, NC, NC, D, NC, NC, NC);
    sgemm64<true, false><<<dim3(1, 2), 256>>>(C, W, pWc, nullptr, NC, NCLS, D, NC, NCLS, NCLS);
    // Z = inv(gram) @ Wc  (register-column Gauss-Jordan)
    solve64<<<1, 192>>>();
    // [orig_pred | concept_pred] = E @ [W | C]  (split epilogue)
    sgemm64<false, true><<<dim3(32, 3), 256>>>(E, pWC, out + O_ORIG, out + O_CPRED,
                                               BSZ, NWC, D, D, NWC, 0);
    // y = cpred @ Z
    sgemm64<false, false><<<dim3(32, 2), 256>>>(out + O_CPRED, pZ, out + O_Y, nullptr,
                                                BSZ, NCLS, NC, NC, NCLS, NCLS);
    // d2 keys via pipelined mma.sync + bank_sq + key min/max
    big_gemm<<<(NBANK + MTILE - 1) / MTILE, 256, BG_SMEM>>>(bank);
    // exact per-concept top-64
    select_topk<<<NC, 1024>>>();
    finalize<<<1, 256>>>(out);
}

// round 6
// speedup vs baseline: 1.8045x; 1.1317x over previous
#include <cuda_runtime.h>
#include <cuda_bf16.h>
#include <math.h>
#include <stdint.h>

#define D      512
#define NC     64
#define NBANK  200000
#define BSZ    2048
#define NCLS   100
#define KSEL   64
#define NCHUNK 8
#define MTILE  128
#define SJ_LD  132
#define NWC    164   // concat [W | C] columns

#define O_ORIG   0
#define O_Y      (BSZ*NCLS)
#define O_L1     (2*BSZ*NCLS)
#define O_L2     (O_L1+1)
#define O_NORM   (O_L1+2)
#define O_CPRED  (O_L1+3)

// ------------------------- device scratch ----------------------------------
__device__ unsigned g_D2[(size_t)NC*NBANK];   // d2 keys (float bits), row/concept
__device__ float    g_bank_sq[NBANK];
__device__ float    g_gram[NC*NC];
__device__ float    g_Wc[NC*NCLS];
__device__ float    g_Z[NC*NCLS];
__device__ float    g_WC[D*NWC];
__device__ float    g_csum[NC];
__device__ float    g_csqv[NC];
__device__ unsigned g_kmin[NC];
__device__ unsigned g_kmax[NC];
// pre-swizzled bf16 C tiles: per chunk c, tile [64 n][64 k], 8KB each
__device__ uint4    g_Bh4[NCHUNK*512];
__device__ uint4    g_Bl4[NCHUNK*512];

// ------------------------- helpers -----------------------------------------
__device__ __forceinline__ uint32_t smem_u32(const void* p) {
    uint32_t a;
    asm("{ .reg .u64 t; cvta.to.shared.u64 t, %1; cvt.u32.u64 %0, t; }"
        : "=r"(a) : "l"(p));
    return a;
}
__device__ __forceinline__ unsigned swz128(unsigned o) { return o ^ ((o >> 3) & 0x70u); }

__device__ __forceinline__ void cp16(uint32_t dst, const void* src) {
    asm volatile("cp.async.cg.shared.global [%0], [%1], 16;" :: "r"(dst), "l"(src));
}
#define CP_COMMIT() asm volatile("cp.async.commit_group;" ::: "memory")
#define CP_WAIT0()  asm volatile("cp.async.wait_group 0;" ::: "memory")
#define CP_WAIT1()  asm volatile("cp.async.wait_group 1;" ::: "memory")

#define LDMX4(r, a) \
    asm volatile("ldmatrix.sync.aligned.m8n8.x4.shared.b16 {%0,%1,%2,%3}, [%4];" \
        : "=r"((r)[0]), "=r"((r)[1]), "=r"((r)[2]), "=r"((r)[3]) : "r"(a))

#define MMA16816(d, a, b0, b1) \
    asm volatile("mma.sync.aligned.m16n8k16.row.col.f32.bf16.bf16.f32 " \
        "{%0,%1,%2,%3}, {%4,%5,%6,%7}, {%8,%9}, {%0,%1,%2,%3};" \
        : "+f"((d)[0]), "+f"((d)[1]), "+f"((d)[2]), "+f"((d)[3]) \
        : "r"((a)[0]), "r"((a)[1]), "r"((a)[2]), "r"((a)[3]), "r"(b0), "r"(b1))

// -------- prep: split+swizzle C, build [W|C], c_sq, reset min/max -----------
__global__ void __launch_bounds__(256) prep(const float* __restrict__ C,
                                            const float* __restrict__ W)
{
    int tid = threadIdx.x;
    int gtid = blockIdx.x * 256 + tid;
    int gstride = gridDim.x * 256;
    for (int idx = gtid; idx < D * NWC; idx += gstride) {
        int k = idx / NWC, n = idx % NWC;
        g_WC[idx] = (n < NCLS) ? W[k * NCLS + n] : C[k * NC + (n - NCLS)];
    }
    if (blockIdx.x == 0) {
        char* bh = (char*)g_Bh4;
        char* bl = (char*)g_Bl4;
        for (int idx = tid; idx < D * NC; idx += 256) {
            int n = idx & 63, k = idx >> 6;
            float x = C[idx];
            __nv_bfloat16 h = __float2bfloat16_rn(x);
            float hf = __bfloat162float(h);
            __nv_bfloat16 l = __float2bfloat16_rn(x - hf);
            int c = k >> 6, kk = k & 63;
            unsigned off = swz128((unsigned)(n * 128 + kk * 2));
            *(__nv_bfloat16*)(bh + c * 8192 + off) = h;
            *(__nv_bfloat16*)(bl + c * 8192 + off) = l;
        }
        // deterministic per-concept sumsq (c_sq)
        if (tid < NC) {
            float s = 0.f;
            #pragma unroll 8
            for (int k = 0; k < D; k++) {
                float x = C[k * NC + tid];
                s = __fmaf_rn(x, x, s);
            }
            g_csqv[tid] = s;
            g_kmin[tid] = 0xffffffffu;
            g_kmax[tid] = 0u;
        }
    }
}

// ------------------- small SGEMM (coalesced staging) ------------------------
template <bool ATRANS, bool SPLIT>
__global__ void __launch_bounds__(256) sgemm64(
    const float* __restrict__ A, const float* __restrict__ B,
    float* __restrict__ Co, float* __restrict__ Co2,
    int M, int N, int K, int lda, int ldb, int ldc)
{
    __shared__ float As[64][33];
    __shared__ __align__(16) float Bs[32][64];
    int tid = threadIdx.x;
    int m0 = blockIdx.x * 64, n0 = blockIdx.y * 64;
    int tx = tid & 15, ty = tid >> 4;
    float acc[4][4] = {};

    for (int k0 = 0; k0 < K; k0 += 32) {
        #pragma unroll
        for (int e = 0; e < 8; e++) {
            int idx = e * 256 + tid;
            if (ATRANS) {
                int m = idx & 63, k = idx >> 6;
                As[m][k] = A[(size_t)(k0 + k) * lda + (m0 + m)];
            } else {
                int k = idx & 31, m = idx >> 5;
                As[m][k] = A[(size_t)(m0 + m) * lda + (k0 + k)];
            }
            int n = idx & 63, k2 = idx >> 6;
            int nn = n0 + n;
            Bs[k2][n] = (nn < N) ? B[(size_t)(k0 + k2) * ldb + nn] : 0.f;
        }
        __syncthreads();
        #pragma unroll
        for (int k = 0; k < 32; k++) {
            float a0 = As[tx * 4 + 0][k];
            float a1 = As[tx * 4 + 1][k];
            float a2 = As[tx * 4 + 2][k];
            float a3 = As[tx * 4 + 3][k];
            float4 bv = *(const float4*)&Bs[k][ty * 4];
            acc[0][0] += a0 * bv.x; acc[0][1] += a0 * bv.y; acc[0][2] += a0 * bv.z; acc[0][3] += a0 * bv.w;
            acc[1][0] += a1 * bv.x; acc[1][1] += a1 * bv.y; acc[1][2] += a1 * bv.z; acc[1][3] += a1 * bv.w;
            acc[2][0] += a2 * bv.x; acc[2][1] += a2 * bv.y; acc[2][2] += a2 * bv.z; acc[2][3] += a2 * bv.w;
            acc[3][0] += a3 * bv.x; acc[3][1] += a3 * bv.y; acc[3][2] += a3 * bv.z; acc[3][3] += a3 * bv.w;
        }
        __syncthreads();
    }
    #pragma unroll
    for (int i = 0; i < 4; i++) {
        int m = m0 + tx * 4 + i;
        #pragma unroll
        for (int e = 0; e < 4; e++) {
            int nn = n0 + ty * 4 + e;
            if (nn < N) {
                if (SPLIT) {
                    if (nn < NCLS) Co[(size_t)m * NCLS + nn] = acc[i][e];
                    else           Co2[(size_t)m * NC + (nn - NCLS)] = acc[i][e];
                } else {
                    Co[(size_t)m * ldc + nn] = acc[i][e];
                }
            }
        }
    }
}

// ---- solve Z = G^{-1} Wc : column-owned GJ, 1 barrier/pivot, no I$ blowup --
__global__ void __launch_bounds__(192) solve64()
{
    __shared__ float fc[2][64];
    int c = threadIdx.x;              // column owner: 0..163
    bool active = (c < 64 + NCLS);
    float col[64];

    if (active) {
        if (c < 64) {
            #pragma unroll
            for (int r = 0; r < 64; r++) col[r] = g_gram[r * 64 + c];
        } else {
            #pragma unroll
            for (int r = 0; r < 64; r++) col[r] = g_Wc[r * NCLS + (c - 64)];
        }
    }
    if (c == 0) {
        #pragma unroll
        for (int r = 0; r < 64; r++) fc[0][r] = col[r];
    }
    __syncthreads();

    #pragma unroll 1
    for (int p = 0; p < 64; p++) {
        const float* fcur = fc[p & 1];
        float pinv = 1.f / fcur[p];
        if (active) {
            float piv = col[p] * pinv;
            #pragma unroll
            for (int r = 0; r < 64; r++)
                col[r] = __fmaf_rn(-fcur[r], piv, col[r]);
            col[p] = piv;
            if (c == p + 1) {
                float* fnx = fc[(p + 1) & 1];
                #pragma unroll
                for (int r = 0; r < 64; r++) fnx[r] = col[r];
            }
        }
        __syncthreads();
    }
    if (c >= 64 && active) {
        #pragma unroll
        for (int r = 0; r < 64; r++) g_Z[r * NCLS + (c - 64)] = col[r];
    }
}

// ------------------- big GEMM: cp.async pipelined mma.sync -------------------
#define BG_SMEM (131840 + 1024)
__global__ void __launch_bounds__(256) big_gemm(const float* __restrict__ bank)
{
    extern __shared__ char sm[];
    uint32_t rawbase = smem_u32(sm);
    uint32_t base0 = (rawbase + 1023) & ~1023u;
    char* smp = sm + (base0 - rawbase);
    const int tid = threadIdx.x;
    const int lane = tid & 31, w = tid >> 5;
    const int wm = w & 3, wn = w >> 2;

    const uint32_t RAW = base0;
    const uint32_t BB  = base0 + 65536;
    const uint32_t AH  = base0 + 98304;
    const uint32_t AL  = base0 + 114688;
    float* row_sq = (float*)(smp + 131072);
    float* s_csq  = (float*)(smp + 131584);

    if (tid < NC) s_csq[tid] = g_csqv[tid];

    const int jbase = blockIdx.x * MTILE;
    const int r0 = tid >> 4, qa = tid & 15;
    float sq[8] = {};
    float acc[2][4][4] = {};
    const int arow = wm * 32 + (lane & 15);
    const int brow = wn * 32 + (lane & 15);
    const unsigned khb = (unsigned)(lane >> 4) * 16;

    auto issue = [&](int c, int b) {
        #pragma unroll
        for (int e = 0; e < 8; e++) {
            int s = e * 256 + tid;
            int r = s >> 4, cs = s & 15;
            int j = jbase + r; if (j >= NBANK) j = NBANK - 1;
            cp16(RAW + b * 32768 + s * 16, bank + (size_t)j * D + c * 64 + cs * 4);
        }
        #pragma unroll
        for (int e = 0; e < 2; e++) {
            int s = e * 256 + tid;
            cp16(BB + b * 16384 + s * 16,        g_Bh4 + c * 512 + s);
            cp16(BB + b * 16384 + 8192 + s * 16, g_Bl4 + c * 512 + s);
        }
    };

    issue(0, 0); CP_COMMIT();

    for (int c = 0; c < NCHUNK; c++) {
        if (c) __syncthreads();
        if (c + 1 < NCHUNK) { issue(c + 1, (c + 1) & 1); CP_COMMIT(); CP_WAIT1(); }
        else CP_WAIT0();
        __syncthreads();

        const char* rb = smp + (c & 1) * 32768;
        #pragma unroll
        for (int p = 0; p < 8; p++) {
            int r = p * 16 + r0;
            float4 v = *(const float4*)(rb + r * 256 + qa * 16);
            sq[p] += v.x * v.x + v.y * v.y + v.z * v.z + v.w * v.w;
            __nv_bfloat162 h0 = __floats2bfloat162_rn(v.x, v.y);
            __nv_bfloat162 h1 = __floats2bfloat162_rn(v.z, v.w);
            float lx = v.x - __low2float(h0),  ly = v.y - __high2float(h0);
            float lz = v.z - __low2float(h1),  lw = v.w - __high2float(h1);
            __nv_bfloat162 l0 = __floats2bfloat162_rn(lx, ly);
            __nv_bfloat162 l1 = __floats2bfloat162_rn(lz, lw);
            unsigned off = swz128((unsigned)(r * 128 + qa * 8));
            uint2 hv, lv;
            hv.x = *(unsigned*)&h0; hv.y = *(unsigned*)&h1;
            lv.x = *(unsigned*)&l0; lv.y = *(unsigned*)&l1;
            *(uint2*)(smp + 98304  + off) = hv;
            *(uint2*)(smp + 114688 + off) = lv;
        }
        __syncthreads();

        const uint32_t BH = BB + (c & 1) * 16384;
        const uint32_t BL = BH + 8192;
        #pragma unroll
        for (int kc = 0; kc < 4; kc++) {
            uint32_t ah[2][4], al[2][4], bh4[2][4], bl4[2][4];
            #pragma unroll
            for (int mt = 0; mt < 2; mt++) {
                unsigned o = swz128((unsigned)((arow + mt * 16) * 128 + kc * 32 + khb));
                LDMX4(ah[mt], AH + o);
                LDMX4(al[mt], AL + o);
            }
            #pragma unroll
            for (int np = 0; np < 2; np++) {
                unsigned o = swz128((unsigned)((brow + np * 16) * 128 + kc * 32 + khb));
                LDMX4(bh4[np], BH + o);
                LDMX4(bl4[np], BL + o);
            }
            #pragma unroll
            for (int mt = 0; mt < 2; mt++) {
                #pragma unroll
                for (int nt = 0; nt < 4; nt++) {
                    int np = nt >> 1, hf = nt & 1;
                    MMA16816(acc[mt][nt], ah[mt], bh4[np][hf], bh4[np][hf + 2]);
                    MMA16816(acc[mt][nt], ah[mt], bl4[np][hf], bl4[np][hf + 2]);
                    MMA16816(acc[mt][nt], al[mt], bh4[np][hf], bh4[np][hf + 2]);
                }
            }
        }
    }

    #pragma unroll
    for (int p = 0; p < 8; p++) {
        #pragma unroll
        for (int o = 8; o; o >>= 1)
            sq[p] += __shfl_xor_sync(0xffffffffu, sq[p], o, 16);
    }
    if (qa == 0) {
        #pragma unroll
        for (int p = 0; p < 8; p++) {
            int r = p * 16 + r0, j = jbase + r;
            row_sq[r] = sq[p];
            if (j < NBANK) g_bank_sq[j] = sq[p];
        }
    }
    __syncthreads();

    float* sT = (float*)smp;
    #pragma unroll
    for (int mt = 0; mt < 2; mt++) {
        #pragma unroll
        for (int nt = 0; nt < 4; nt++) {
            #pragma unroll
            for (int r = 0; r < 4; r++) {
                int m = wm * 32 + mt * 16 + (lane >> 2) + ((r >> 1) * 8);
                int n = wn * 32 + nt * 8 + (lane & 3) * 2 + (r & 1);
                sT[n * SJ_LD + m] = acc[mt][nt][r];
            }
        }
    }
    __syncthreads();

    {
        int j = tid & 127, nh = tid >> 7;
        float myb = row_sq[j];
        int jg = jbase + j;
        bool ok = (jg < NBANK);
        #pragma unroll 8
        for (int n = nh * 32; n < nh * 32 + 32; n++) {
            float s = sT[n * SJ_LD + j];
            float d2 = fmaxf(__fmaf_rn(-2.f, s, s_csq[n] + myb), 0.f);
            unsigned key = __float_as_uint(d2);
            if (ok) g_D2[(size_t)n * NBANK + jg] = key;
            ((unsigned*)sT)[n * SJ_LD + j] = key;
        }
    }
    __syncthreads();
    {
        int n = tid >> 2, seg = tid & 3;
        unsigned mn = 0xffffffffu, mx = 0u;
        const unsigned* u = (const unsigned*)sT + n * SJ_LD + seg * 32;
        #pragma unroll 8
        for (int i = 0; i < 32; i++) {
            unsigned k = u[i];
            mn = min(mn, k); mx = max(mx, k);
        }
        mn = min(mn, __shfl_xor_sync(0xffffffffu, mn, 1, 4));
        mn = min(mn, __shfl_xor_sync(0xffffffffu, mn, 2, 4));
        mx = max(mx, __shfl_xor_sync(0xffffffffu, mx, 1, 4));
        mx = max(mx, __shfl_xor_sync(0xffffffffu, mx, 2, 4));
        if (seg == 0) { atomicMin(&g_kmin[n], mn); atomicMax(&g_kmax[n], mx); }
    }
}

// ------------------- per-concept exact top-64 over d2 keys ------------------
#define SELCAP 2048
__global__ void __launch_bounds__(1024) select_topk()
{
    int n = blockIdx.x;
    int tid = threadIdx.x;
    int lane = tid & 31, w = tid >> 5;
    const uint4* keys = (const uint4*)(g_D2 + (size_t)n * NBANK);
    float csq = g_csqv[n];

    __shared__ unsigned hist[4096];
    __shared__ unsigned wbufa[32];
    __shared__ float    fred[32], fred2[32];
    __shared__ unsigned cand_key[SELCAP];
    __shared__ int      cand_j[SELCAP];
    __shared__ unsigned s_cnt, s_cb1;
    __shared__ int      s_b1;
    __shared__ float    s_d2b, s_bqb;

    unsigned kmin0 = g_kmin[n];
    unsigned range = g_kmax[n] - kmin0;
    unsigned sh = (range >= 4096u) ? (unsigned)(32 - __clz(range) - 12) : 0u;

    for (int i = tid; i < 4096; i += 1024) hist[i] = 0;
    if (tid == 0) s_cnt = 0;
    __syncthreads();

    for (int j4 = tid; j4 < NBANK / 4; j4 += 1024) {
        uint4 kv = keys[j4];
        unsigned ka[4] = {kv.x, kv.y, kv.z, kv.w};
        #pragma unroll
        for (int t = 0; t < 4; t++) {
            unsigned key = ka[t];
            unsigned b = (key < kmin0) ? 0u : min((key - kmin0) >> sh, 4095u);
            atomicAdd(&hist[b], 1u);
        }
    }
    __syncthreads();

    {
        unsigned h0 = hist[tid*4], h1 = hist[tid*4+1], h2 = hist[tid*4+2], h3 = hist[tid*4+3];
        unsigned tsum = h0 + h1 + h2 + h3;
        unsigned v = tsum;
        #pragma unroll
        for (int o = 1; o < 32; o <<= 1) {
            unsigned u = __shfl_up_sync(0xffffffffu, v, o);
            if (lane >= o) v += u;
        }
        if (lane == 31) wbufa[w] = v;
        __syncthreads();
        if (tid < 32) {
            unsigned x = wbufa[tid];
            #pragma unroll
            for (int o = 1; o < 32; o <<= 1) {
                unsigned u = __shfl_up_sync(0xffffffffu, x, o);
                if (tid >= o) x += u;
            }
            wbufa[tid] = x;
        }
        __syncthreads();
        unsigned excl = v - tsum + (w ? wbufa[w - 1] : 0u);
        if (excl < KSEL && excl + tsum >= KSEL) {
            unsigned c = excl;
            unsigned hh[4] = {h0, h1, h2, h3};
            int i = 0;
            while (i < 3 && c + hh[i] < KSEL) { c += hh[i]; i++; }
            s_b1 = tid * 4 + i; s_cb1 = c;
        }
    }
    __syncthreads();
    int b1 = s_b1;

    float d2s = 0.f, bqs = 0.f;
    for (int j4 = tid; j4 < NBANK / 4; j4 += 1024) {
        uint4 kv = keys[j4];
        unsigned ka[4] = {kv.x, kv.y, kv.z, kv.w};
        #pragma unroll
        for (int t = 0; t < 4; t++) {
            unsigned key = ka[t];
            int b = (key < kmin0) ? 0 : (int)min((key - kmin0) >> sh, 4095u);
            if (b < b1) {
                d2s += __uint_as_float(key);
                bqs += g_bank_sq[j4 * 4 + t];
            } else if (b == b1) {
                unsigned p = atomicAdd(&s_cnt, 1u);
                if (p < SELCAP) { cand_key[p] = key; cand_j[p] = j4 * 4 + t; }
            }
        }
    }
    #pragma unroll
    for (int o = 16; o; o >>= 1) {
        d2s += __shfl_xor_sync(0xffffffffu, d2s, o);
        bqs += __shfl_xor_sync(0xffffffffu, bqs, o);
    }
    if (lane == 0) { fred[w] = d2s; fred2[w] = bqs; }
    __syncthreads();
    if (tid < 32) {
        float x = fred[tid], y = fred2[tid];
        #pragma unroll
        for (int o = 16; o; o >>= 1) {
            x += __shfl_xor_sync(0xffffffffu, x, o);
            y += __shfl_xor_sync(0xffffffffu, y, o);
        }
        if (tid == 0) { s_d2b = x; s_bqb = y; }
    }
    __syncthreads();

    int r = KSEL - (int)s_cb1;
    int m = (int)min(s_cnt, (unsigned)SELCAP);
    if (tid < 32) {
        float d2x = 0.f, bqx = 0.f;
        for (int it = 0; it < r; it++) {
            unsigned best = 0xffffffffu;
            int bestj = 0x7fffffff, bi = -1;
            for (int i = tid; i < m; i += 32) {
                unsigned k = cand_key[i];
                int jj = cand_j[i];
                if (k < best || (k == best && jj < bestj)) { best = k; bestj = jj; bi = i; }
            }
            #pragma unroll
            for (int o = 16; o; o >>= 1) {
                unsigned ok = __shfl_xor_sync(0xffffffffu, best, o);
                int      oj = __shfl_xor_sync(0xffffffffu, bestj, o);
                int      ob = __shfl_xor_sync(0xffffffffu, bi, o);
                if (ok < best || (ok == best && oj < bestj)) { best = ok; bestj = oj; bi = ob; }
            }
            if (tid == 0 && bi >= 0) {
                d2x += __uint_as_float(best);
                bqx += g_bank_sq[bestj];
                cand_key[bi] = 0xffffffffu;
                cand_j[bi] = 0x7fffffff;
            }
            __syncwarp();
        }
        if (tid == 0)
            g_csum[n] = 0.5f * ((float)KSEL * csq + (s_bqb + bqx) - (s_d2b + d2x));
    }
}

// ------------------- scalars ------------------------------------------------
__global__ void __launch_bounds__(256) finalize(float* __restrict__ out)
{
    __shared__ float r1[8], r2[8], r3[8];
    int tid = threadIdx.x, lane = tid & 31, w = tid >> 5;
    float gs = 0.f, tr = 0.f;
    for (int i = tid; i < NC * NC; i += 256) {
        float v = g_gram[i];
        gs += v;
        if ((i >> 6) == (i & 63)) tr += v;
    }
    float cs = (tid < NC) ? g_csum[tid] : 0.f;
    #pragma unroll
    for (int o = 16; o; o >>= 1) {
        gs += __shfl_xor_sync(0xffffffffu, gs, o);
        tr += __shfl_xor_sync(0xffffffffu, tr, o);
        cs += __shfl_xor_sync(0xffffffffu, cs, o);
    }
    if (lane == 0) { r1[w] = gs; r2[w] = tr; r3[w] = cs; }
    __syncthreads();
    if (tid == 0) {
        float GS = 0, TR = 0, CS = 0;
        for (int i = 0; i < 8; i++) { GS += r1[i]; TR += r2[i]; CS += r3[i]; }
        out[O_L1]   = CS / (float)(NC * KSEL);
        out[O_L2]   = (GS - TR) / (float)(NC * NC);
        out[O_NORM] = TR / (float)(NC * NC);
    }
}

// ----------------------------------------------------------------------------
extern "C" void kernel_launch(void* const* d_in, const int* in_sizes, int n_in,
                              void* d_out, int out_size)
{
    (void)in_sizes; (void)n_in; (void)out_size;
    const float* C    = (const float*)d_in[0];  // (512, 64)
    const float* E    = (const float*)d_in[1];  // (2048, 512)
    const float* bank = (const float*)d_in[2];  // (200000, 512)
    const float* W    = (const float*)d_in[3];  // (512, 100)
    float* out = (float*)d_out;

    float *pgram, *pWc, *pZ, *pWC;
    cudaGetSymbolAddress((void**)&pgram, g_gram);
    cudaGetSymbolAddress((void**)&pWc,   g_Wc);
    cudaGetSymbolAddress((void**)&pZ,    g_Z);
    cudaGetSymbolAddress((void**)&pWC,   g_WC);

    cudaFuncSetAttribute(big_gemm, cudaFuncAttributeMaxDynamicSharedMemorySize, BG_SMEM);

    // fork-join: side stream for the small dependent chain
    cudaStream_t s2;
    cudaStreamCreateWithFlags(&s2, cudaStreamNonBlocking);
    cudaEvent_t eF, eJ;
    cudaEventCreateWithFlags(&eF, cudaEventDisableTiming);
    cudaEventCreateWithFlags(&eJ, cudaEventDisableTiming);

    // main: prep (B tiles, [W|C], c_sq, minmax reset)
    prep<<<32, 256>>>(C, W);
    cudaEventRecord(eF, 0);
    cudaStreamWaitEvent(s2, eF, 0);

    // branch A (side stream): gram -> Wc -> solve -> E@[W|C] -> y
    sgemm64<true, false><<<dim3(1, 1), 256, 0, s2>>>(C, C, pgram, nullptr, NC, NC, D, NC, NC, NC);
    sgemm64<true, false><<<dim3(1, 2), 256, 0, s2>>>(C, W, pWc, nullptr, NC, NCLS, D, NC, NCLS, NCLS);
    solve64<<<1, 192, 0, s2>>>();
    sgemm64<false, true><<<dim3(32, 3), 256, 0, s2>>>(E, pWC, out + O_ORIG, out + O_CPRED,
                                                      BSZ, NWC, D, D, NWC, 0);
    sgemm64<false, false><<<dim3(32, 2), 256, 0, s2>>>(out + O_CPRED, pZ, out + O_Y, nullptr,
                                                       BSZ, NCLS, NC, NC, NCLS, NCLS);
    cudaEventRecord(eJ, s2);

    // main: big_gemm -> select
    big_gemm<<<(NBANK + MTILE - 1) / MTILE, 256, BG_SMEM>>>(bank);
    select_topk<<<NC, 1024>>>();

    // join, then scalars
    cudaStreamWaitEvent(0, eJ, 0);
    finalize<<<1, 256>>>(out);
}

// round 7
// speedup vs baseline: 2.8048x; 1.5543x over previous
#include <cuda_runtime.h>
#include <cuda_bf16.h>
#include <math.h>
#include <stdint.h>

#define D      512
#define NC     64
#define NBANK  200000
#define BSZ    2048
#define NCLS   100
#define KSEL   64
#define NCHUNK 8
#define MTILE  128
#define SJ_LD  132
#define NWC    164   // concat [W | C] columns

#define O_ORIG   0
#define O_Y      (BSZ*NCLS)
#define O_L1     (2*BSZ*NCLS)
#define O_L2     (O_L1+1)
#define O_NORM   (O_L1+2)
#define O_CPRED  (O_L1+3)

// ------------------------- device scratch ----------------------------------
__device__ unsigned g_D2[(size_t)NC*NBANK];   // d2 keys (float bits), row/concept
__device__ float    g_bank_sq[NBANK];
__device__ float    g_gram[NC*NC];
__device__ float    g_Wc[NC*NCLS];
__device__ float    g_Z[NC*NCLS];
__device__ float    g_WC[D*NWC];
__device__ float    g_csum[NC];
__device__ float    g_csqv[NC];
__device__ unsigned g_kmin[NC];
__device__ unsigned g_kmax[NC];
// pre-swizzled bf16 C tiles: per chunk c, tile [64 n][64 k], 8KB each
__device__ uint4    g_Bh4[NCHUNK*512];

// ------------------------- helpers -----------------------------------------
__device__ __forceinline__ uint32_t smem_u32(const void* p) {
    uint32_t a;
    asm("{ .reg .u64 t; cvta.to.shared.u64 t, %1; cvt.u32.u64 %0, t; }"
        : "=r"(a) : "l"(p));
    return a;
}
__device__ __forceinline__ unsigned swz128(unsigned o) { return o ^ ((o >> 3) & 0x70u); }

__device__ __forceinline__ void cp16(uint32_t dst, const void* src) {
    asm volatile("cp.async.cg.shared.global [%0], [%1], 16;" :: "r"(dst), "l"(src));
}
#define CP_COMMIT() asm volatile("cp.async.commit_group;" ::: "memory")
#define CP_WAIT0()  asm volatile("cp.async.wait_group 0;" ::: "memory")
#define CP_WAIT1()  asm volatile("cp.async.wait_group 1;" ::: "memory")

#define LDMX4(r, a) \
    asm volatile("ldmatrix.sync.aligned.m8n8.x4.shared.b16 {%0,%1,%2,%3}, [%4];" \
        : "=r"((r)[0]), "=r"((r)[1]), "=r"((r)[2]), "=r"((r)[3]) : "r"(a))

#define MMA16816(d, a, b0, b1) \
    asm volatile("mma.sync.aligned.m16n8k16.row.col.f32.bf16.bf16.f32 " \
        "{%0,%1,%2,%3}, {%4,%5,%6,%7}, {%8,%9}, {%0,%1,%2,%3};" \
        : "+f"((d)[0]), "+f"((d)[1]), "+f"((d)[2]), "+f"((d)[3]) \
        : "r"((a)[0]), "r"((a)[1]), "r"((a)[2]), "r"((a)[3]), "r"(b0), "r"(b1))

// -------- prep: swizzle C(bf16), build [W|C], c_sq, reset min/max -----------
__global__ void __launch_bounds__(256) prep(const float* __restrict__ C,
                                            const float* __restrict__ W)
{
    int tid = threadIdx.x;
    int gtid = blockIdx.x * 256 + tid;
    int gstride = gridDim.x * 256;
    for (int idx = gtid; idx < D * NWC; idx += gstride) {
        int k = idx / NWC, n = idx % NWC;
        g_WC[idx] = (n < NCLS) ? W[k * NCLS + n] : C[k * NC + (n - NCLS)];
    }
    if (blockIdx.x == 0) {
        char* bh = (char*)g_Bh4;
        for (int idx = tid; idx < D * NC; idx += 256) {
            int n = idx & 63, k = idx >> 6;
            float x = C[idx];
            __nv_bfloat16 h = __float2bfloat16_rn(x);
            int c = k >> 6, kk = k & 63;
            unsigned off = swz128((unsigned)(n * 128 + kk * 2));
            *(__nv_bfloat16*)(bh + c * 8192 + off) = h;
        }
        // deterministic per-concept sumsq (c_sq)
        if (tid < NC) {
            float s = 0.f;
            #pragma unroll 8
            for (int k = 0; k < D; k++) {
                float x = C[k * NC + tid];
                s = __fmaf_rn(x, x, s);
            }
            g_csqv[tid] = s;
            g_kmin[tid] = 0xffffffffu;
            g_kmax[tid] = 0u;
        }
    }
}

// ------------------- small SGEMM (coalesced staging) ------------------------
// SPLIT: n<NCLS -> Co (ld NCLS), n>=NCLS -> Co2 (ld NC)
template <bool ATRANS, bool SPLIT>
__global__ void __launch_bounds__(256) sgemm64(
    const float* __restrict__ A, const float* __restrict__ B,
    float* __restrict__ Co, float* __restrict__ Co2,
    int M, int N, int K, int lda, int ldb, int ldc)
{
    __shared__ float As[64][33];
    __shared__ __align__(16) float Bs[32][64];
    int tid = threadIdx.x;
    int m0 = blockIdx.x * 64, n0 = blockIdx.y * 64;
    int tx = tid & 15, ty = tid >> 4;
    float acc[4][4] = {};

    for (int k0 = 0; k0 < K; k0 += 32) {
        #pragma unroll
        for (int e = 0; e < 8; e++) {
            int idx = e * 256 + tid;
            if (ATRANS) {
                int m = idx & 63, k = idx >> 6;
                As[m][k] = A[(size_t)(k0 + k) * lda + (m0 + m)];
            } else {
                int k = idx & 31, m = idx >> 5;
                As[m][k] = A[(size_t)(m0 + m) * lda + (k0 + k)];
            }
            int n = idx & 63, k2 = idx >> 6;
            int nn = n0 + n;
            Bs[k2][n] = (nn < N) ? B[(size_t)(k0 + k2) * ldb + nn] : 0.f;
        }
        __syncthreads();
        #pragma unroll
        for (int k = 0; k < 32; k++) {
            float a0 = As[tx * 4 + 0][k];
            float a1 = As[tx * 4 + 1][k];
            float a2 = As[tx * 4 + 2][k];
            float a3 = As[tx * 4 + 3][k];
            float4 bv = *(const float4*)&Bs[k][ty * 4];
            acc[0][0] += a0 * bv.x; acc[0][1] += a0 * bv.y; acc[0][2] += a0 * bv.z; acc[0][3] += a0 * bv.w;
            acc[1][0] += a1 * bv.x; acc[1][1] += a1 * bv.y; acc[1][2] += a1 * bv.z; acc[1][3] += a1 * bv.w;
            acc[2][0] += a2 * bv.x; acc[2][1] += a2 * bv.y; acc[2][2] += a2 * bv.z; acc[2][3] += a2 * bv.w;
            acc[3][0] += a3 * bv.x; acc[3][1] += a3 * bv.y; acc[3][2] += a3 * bv.z; acc[3][3] += a3 * bv.w;
        }
        __syncthreads();
    }
    #pragma unroll
    for (int i = 0; i < 4; i++) {
        int m = m0 + tx * 4 + i;
        #pragma unroll
        for (int e = 0; e < 4; e++) {
            int nn = n0 + ty * 4 + e;
            if (nn < N) {
                if (SPLIT) {
                    if (nn < NCLS) Co[(size_t)m * NCLS + nn] = acc[i][e];
                    else           Co2[(size_t)m * NC + (nn - NCLS)] = acc[i][e];
                } else {
                    Co[(size_t)m * ldc + nn] = acc[i][e];
                }
            }
        }
    }
}

// ---- solve Z = G^{-1} Wc : column-owned GJ, 1 barrier/pivot ----------------
__global__ void __launch_bounds__(192) solve64()
{
    __shared__ float fc[2][64];
    int c = threadIdx.x;              // column owner: 0..163
    bool active = (c < 64 + NCLS);
    float col[64];

    if (active) {
        if (c < 64) {
            #pragma unroll
            for (int r = 0; r < 64; r++) col[r] = g_gram[r * 64 + c];
        } else {
            #pragma unroll
            for (int r = 0; r < 64; r++) col[r] = g_Wc[r * NCLS + (c - 64)];
        }
    }
    if (c == 0) {
        #pragma unroll
        for (int r = 0; r < 64; r++) fc[0][r] = col[r];
    }
    __syncthreads();

    #pragma unroll 1
    for (int p = 0; p < 64; p++) {
        const float* fcur = fc[p & 1];
        float pinv = 1.f / fcur[p];
        if (active) {
            float piv = col[p] * pinv;
            #pragma unroll
            for (int r = 0; r < 64; r++)
                col[r] = __fmaf_rn(-fcur[r], piv, col[r]);
            col[p] = piv;
            if (c == p + 1) {
                float* fnx = fc[(p + 1) & 1];
                #pragma unroll
                for (int r = 0; r < 64; r++) fnx[r] = col[r];
            }
        }
        __syncthreads();
    }
    if (c >= 64 && active) {
        #pragma unroll
        for (int r = 0; r < 64; r++) g_Z[r * NCLS + (c - 64)] = col[r];
    }
}

// -------- big GEMM v3: 1-term bf16 mma.sync, cp.async double buffer ---------
// SMEM (1024-aligned):
//  [0,65536)       RAW fp32 bank chunk x2        (epilogue: sT)
//  [65536,81920)   B bf16 tile x2 (8KB each)
//  [81920,98304)   A bf16 tile (16KB)
//  [98304,99072)   row_sq(512) + csq(256)
#define BG_SMEM (99072 + 1024)
__global__ void __launch_bounds__(256) big_gemm(const float* __restrict__ bank)
{
    extern __shared__ char sm[];
    uint32_t rawbase = smem_u32(sm);
    uint32_t base0 = (rawbase + 1023) & ~1023u;
    char* smp = sm + (base0 - rawbase);
    const int tid = threadIdx.x;
    const int lane = tid & 31, w = tid >> 5;
    const int wm = w & 3, wn = w >> 2;

    const uint32_t RAW = base0;
    const uint32_t BB  = base0 + 65536;
    const uint32_t AH  = base0 + 81920;
    float* row_sq = (float*)(smp + 98304);
    float* s_csq  = (float*)(smp + 98816);

    if (tid < NC) s_csq[tid] = g_csqv[tid];

    const int jbase = blockIdx.x * MTILE;
    const int r0 = tid >> 4, qa = tid & 15;
    float sq[8] = {};
    float acc[2][4][4] = {};
    const int arow = wm * 32 + (lane & 15);
    const int brow = wn * 32 + (lane & 15);
    const unsigned khb = (unsigned)(lane >> 4) * 16;

    auto issue = [&](int c, int b) {
        #pragma unroll
        for (int e = 0; e < 8; e++) {
            int s = e * 256 + tid;
            int r = s >> 4, cs = s & 15;
            int j = jbase + r; if (j >= NBANK) j = NBANK - 1;
            cp16(RAW + b * 32768 + s * 16, bank + (size_t)j * D + c * 64 + cs * 4);
        }
        #pragma unroll
        for (int e = 0; e < 2; e++) {
            int s = e * 256 + tid;
            cp16(BB + b * 8192 + s * 16, g_Bh4 + c * 512 + s);
        }
    };

    issue(0, 0); CP_COMMIT();

    for (int c = 0; c < NCHUNK; c++) {
        if (c) __syncthreads();                 // prev mma done; AH reusable
        if (c + 1 < NCHUNK) { issue(c + 1, (c + 1) & 1); CP_COMMIT(); CP_WAIT1(); }
        else CP_WAIT0();
        __syncthreads();                        // chunk c data visible

        // convert raw fp32 -> bf16 A tile (swizzled), accumulate sumsq
        const char* rb = smp + (c & 1) * 32768;
        #pragma unroll
        for (int p = 0; p < 8; p++) {
            int r = p * 16 + r0;
            float4 v = *(const float4*)(rb + r * 256 + qa * 16);
            sq[p] += v.x * v.x + v.y * v.y + v.z * v.z + v.w * v.w;
            __nv_bfloat162 h0 = __floats2bfloat162_rn(v.x, v.y);
            __nv_bfloat162 h1 = __floats2bfloat162_rn(v.z, v.w);
            uint2 hv;
            hv.x = *(unsigned*)&h0; hv.y = *(unsigned*)&h1;
            *(uint2*)(smp + 81920 + swz128((unsigned)(r * 128 + qa * 8))) = hv;
        }
        __syncthreads();                        // A tile ready

        const uint32_t BH = BB + (c & 1) * 8192;
        #pragma unroll
        for (int kc = 0; kc < 4; kc++) {
            uint32_t ah[2][4], bh4[2][4];
            #pragma unroll
            for (int mt = 0; mt < 2; mt++) {
                unsigned o = swz128((unsigned)((arow + mt * 16) * 128 + kc * 32 + khb));
                LDMX4(ah[mt], AH + o);
            }
            #pragma unroll
            for (int np = 0; np < 2; np++) {
                unsigned o = swz128((unsigned)((brow + np * 16) * 128 + kc * 32 + khb));
                LDMX4(bh4[np], BH + o);
            }
            #pragma unroll
            for (int mt = 0; mt < 2; mt++) {
                #pragma unroll
                for (int nt = 0; nt < 4; nt++) {
                    int np = nt >> 1, hf = nt & 1;
                    MMA16816(acc[mt][nt], ah[mt], bh4[np][hf], bh4[np][hf + 2]);
                }
            }
        }
    }

    // row sumsq: reduce over the 16 lanes sharing a row
    #pragma unroll
    for (int p = 0; p < 8; p++) {
        #pragma unroll
        for (int o = 8; o; o >>= 1)
            sq[p] += __shfl_xor_sync(0xffffffffu, sq[p], o, 16);
    }
    if (qa == 0) {
        #pragma unroll
        for (int p = 0; p < 8; p++) {
            int r = p * 16 + r0, j = jbase + r;
            row_sq[r] = sq[p];
            if (j < NBANK) g_bank_sq[j] = sq[p];
        }
    }
    __syncthreads();     // reuse RAW region as fp32 [n][SJ_LD] tile

    float* sT = (float*)smp;
    #pragma unroll
    for (int mt = 0; mt < 2; mt++) {
        #pragma unroll
        for (int nt = 0; nt < 4; nt++) {
            #pragma unroll
            for (int r = 0; r < 4; r++) {
                int m = wm * 32 + mt * 16 + (lane >> 2) + ((r >> 1) * 8);
                int n = wn * 32 + nt * 8 + (lane & 3) * 2 + (r & 1);
                sT[n * SJ_LD + m] = acc[mt][nt][r];
            }
        }
    }
    __syncthreads();

    // write d2 keys (coalesced), stash keys in-place for min/max
    {
        int j = tid & 127, nh = tid >> 7;
        float myb = row_sq[j];
        int jg = jbase + j;
        bool ok = (jg < NBANK);
        #pragma unroll 8
        for (int n = nh * 32; n < nh * 32 + 32; n++) {
            float s = sT[n * SJ_LD + j];
            float d2 = fmaxf(__fmaf_rn(-2.f, s, s_csq[n] + myb), 0.f);
            unsigned key = __float_as_uint(d2);
            if (ok) g_D2[(size_t)n * NBANK + jg] = key;
            ((unsigned*)sT)[n * SJ_LD + j] = key;
        }
    }
    __syncthreads();
    {
        int n = tid >> 2, seg = tid & 3;
        unsigned mn = 0xffffffffu, mx = 0u;
        const unsigned* u = (const unsigned*)sT + n * SJ_LD + seg * 32;
        #pragma unroll 8
        for (int i = 0; i < 32; i++) {
            unsigned k = u[i];
            mn = min(mn, k); mx = max(mx, k);
        }
        mn = min(mn, __shfl_xor_sync(0xffffffffu, mn, 1, 4));
        mn = min(mn, __shfl_xor_sync(0xffffffffu, mn, 2, 4));
        mx = max(mx, __shfl_xor_sync(0xffffffffu, mx, 1, 4));
        mx = max(mx, __shfl_xor_sync(0xffffffffu, mx, 2, 4));
        if (seg == 0) { atomicMin(&g_kmin[n], mn); atomicMax(&g_kmax[n], mx); }
    }
}

// ------------------- per-concept exact top-64 over d2 keys ------------------
#define SELCAP 2048
__global__ void __launch_bounds__(1024) select_topk()
{
    int n = blockIdx.x;
    int tid = threadIdx.x;
    int lane = tid & 31, w = tid >> 5;
    const uint4* keys = (const uint4*)(g_D2 + (size_t)n * NBANK);
    float csq = g_csqv[n];

    __shared__ unsigned hist[4096];
    __shared__ unsigned wbufa[32];
    __shared__ float    fred[32], fred2[32];
    __shared__ unsigned cand_key[SELCAP];
    __shared__ int      cand_j[SELCAP];
    __shared__ unsigned s_cnt, s_cb1;
    __shared__ int      s_b1;
    __shared__ float    s_d2b, s_bqb;

    unsigned kmin0 = g_kmin[n];
    unsigned range = g_kmax[n] - kmin0;
    unsigned sh = (range >= 4096u) ? (unsigned)(32 - __clz(range) - 12) : 0u;

    for (int i = tid; i < 4096; i += 1024) hist[i] = 0;
    if (tid == 0) s_cnt = 0;
    __syncthreads();

    for (int j4 = tid; j4 < NBANK / 4; j4 += 1024) {
        uint4 kv = keys[j4];
        unsigned ka[4] = {kv.x, kv.y, kv.z, kv.w};
        #pragma unroll
        for (int t = 0; t < 4; t++) {
            unsigned key = ka[t];
            unsigned b = (key < kmin0) ? 0u : min((key - kmin0) >> sh, 4095u);
            atomicAdd(&hist[b], 1u);
        }
    }
    __syncthreads();

    {
        unsigned h0 = hist[tid*4], h1 = hist[tid*4+1], h2 = hist[tid*4+2], h3 = hist[tid*4+3];
        unsigned tsum = h0 + h1 + h2 + h3;
        unsigned v = tsum;
        #pragma unroll
        for (int o = 1; o < 32; o <<= 1) {
            unsigned u = __shfl_up_sync(0xffffffffu, v, o);
            if (lane >= o) v += u;
        }
        if (lane == 31) wbufa[w] = v;
        __syncthreads();
        if (tid < 32) {
            unsigned x = wbufa[tid];
            #pragma unroll
            for (int o = 1; o < 32; o <<= 1) {
                unsigned u = __shfl_up_sync(0xffffffffu, x, o);
                if (tid >= o) x += u;
            }
            wbufa[tid] = x;
        }
        __syncthreads();
        unsigned excl = v - tsum + (w ? wbufa[w - 1] : 0u);
        if (excl < KSEL && excl + tsum >= KSEL) {
            unsigned c = excl;
            unsigned hh[4] = {h0, h1, h2, h3};
            int i = 0;
            while (i < 3 && c + hh[i] < KSEL) { c += hh[i]; i++; }
            s_b1 = tid * 4 + i; s_cb1 = c;
        }
    }
    __syncthreads();
    int b1 = s_b1;

    float d2s = 0.f, bqs = 0.f;
    for (int j4 = tid; j4 < NBANK / 4; j4 += 1024) {
        uint4 kv = keys[j4];
        unsigned ka[4] = {kv.x, kv.y, kv.z, kv.w};
        #pragma unroll
        for (int t = 0; t < 4; t++) {
            unsigned key = ka[t];
            int b = (key < kmin0) ? 0 : (int)min((key - kmin0) >> sh, 4095u);
            if (b < b1) {
                d2s += __uint_as_float(key);
                bqs += g_bank_sq[j4 * 4 + t];
            } else if (b == b1) {
                unsigned p = atomicAdd(&s_cnt, 1u);
                if (p < SELCAP) { cand_key[p] = key; cand_j[p] = j4 * 4 + t; }
            }
        }
    }
    #pragma unroll
    for (int o = 16; o; o >>= 1) {
        d2s += __shfl_xor_sync(0xffffffffu, d2s, o);
        bqs += __shfl_xor_sync(0xffffffffu, bqs, o);
    }
    if (lane == 0) { fred[w] = d2s; fred2[w] = bqs; }
    __syncthreads();
    if (tid < 32) {
        float x = fred[tid], y = fred2[tid];
        #pragma unroll
        for (int o = 16; o; o >>= 1) {
            x += __shfl_xor_sync(0xffffffffu, x, o);
            y += __shfl_xor_sync(0xffffffffu, y, o);
        }
        if (tid == 0) { s_d2b = x; s_bqb = y; }
    }
    __syncthreads();

    int r = KSEL - (int)s_cb1;
    int m = (int)min(s_cnt, (unsigned)SELCAP);
    if (tid < 32) {
        float d2x = 0.f, bqx = 0.f;
        for (int it = 0; it < r; it++) {
            unsigned best = 0xffffffffu;
            int bestj = 0x7fffffff, bi = -1;
            for (int i = tid; i < m; i += 32) {
                unsigned k = cand_key[i];
                int jj = cand_j[i];
                if (k < best || (k == best && jj < bestj)) { best = k; bestj = jj; bi = i; }
            }
            #pragma unroll
            for (int o = 16; o; o >>= 1) {
                unsigned ok = __shfl_xor_sync(0xffffffffu, best, o);
                int      oj = __shfl_xor_sync(0xffffffffu, bestj, o);
                int      ob = __shfl_xor_sync(0xffffffffu, bi, o);
                if (ok < best || (ok == best && oj < bestj)) { best = ok; bestj = oj; bi = ob; }
            }
            if (tid == 0 && bi >= 0) {
                d2x += __uint_as_float(best);
                bqx += g_bank_sq[bestj];
                cand_key[bi] = 0xffffffffu;
                cand_j[bi] = 0x7fffffff;
            }
            __syncwarp();
        }
        if (tid == 0)
            g_csum[n] = 0.5f * ((float)KSEL * csq + (s_bqb + bqx) - (s_d2b + d2x));
    }
}

// ------------------- scalars ------------------------------------------------
__global__ void __launch_bounds__(256) finalize(float* __restrict__ out)
{
    __shared__ float r1[8], r2[8], r3[8];
    int tid = threadIdx.x, lane = tid & 31, w = tid >> 5;
    float gs = 0.f, tr = 0.f;
    for (int i = tid; i < NC * NC; i += 256) {
        float v = g_gram[i];
        gs += v;
        if ((i >> 6) == (i & 63)) tr += v;
    }
    float cs = (tid < NC) ? g_csum[tid] : 0.f;
    #pragma unroll
    for (int o = 16; o; o >>= 1) {
        gs += __shfl_xor_sync(0xffffffffu, gs, o);
        tr += __shfl_xor_sync(0xffffffffu, tr, o);
        cs += __shfl_xor_sync(0xffffffffu, cs, o);
    }
    if (lane == 0) { r1[w] = gs; r2[w] = tr; r3[w] = cs; }
    __syncthreads();
    if (tid == 0) {
        float GS = 0, TR = 0, CS = 0;
        for (int i = 0; i < 8; i++) { GS += r1[i]; TR += r2[i]; CS += r3[i]; }
        out[O_L1]   = CS / (float)(NC * KSEL);
        out[O_L2]   = (GS - TR) / (float)(NC * NC);
        out[O_NORM] = TR / (float)(NC * NC);
    }
}

// ----------------------------------------------------------------------------
extern "C" void kernel_launch(void* const* d_in, const int* in_sizes, int n_in,
                              void* d_out, int out_size)
{
    (void)in_sizes; (void)n_in; (void)out_size;
    const float* C    = (const float*)d_in[0];  // (512, 64)
    const float* E    = (const float*)d_in[1];  // (2048, 512)
    const float* bank = (const float*)d_in[2];  // (200000, 512)
    const float* W    = (const float*)d_in[3];  // (512, 100)
    float* out = (float*)d_out;

    float *pgram, *pWc, *pZ, *pWC;
    cudaGetSymbolAddress((void**)&pgram, g_gram);
    cudaGetSymbolAddress((void**)&pWc,   g_Wc);
    cudaGetSymbolAddress((void**)&pZ,    g_Z);
    cudaGetSymbolAddress((void**)&pWC,   g_WC);

    cudaFuncSetAttribute(big_gemm, cudaFuncAttributeMaxDynamicSharedMemorySize, BG_SMEM);

    cudaStream_t s2;
    cudaStreamCreateWithFlags(&s2, cudaStreamNonBlocking);
    cudaEvent_t eF, eJ;
    cudaEventCreateWithFlags(&eF, cudaEventDisableTiming);
    cudaEventCreateWithFlags(&eJ, cudaEventDisableTiming);

    // main: prep (B tile bf16, [W|C], c_sq, minmax reset)
    prep<<<32, 256>>>(C, W);
    cudaEventRecord(eF, 0);
    cudaStreamWaitEvent(s2, eF, 0);

    // branch A (side stream): [Wc|gram] = C^T@[W|C] -> solve -> E@[W|C] -> y
    sgemm64<true, true><<<dim3(1, 3), 256, 0, s2>>>(C, pWC, pWc, pgram, NC, NWC, D, NC, NWC, 0);
    solve64<<<1, 192, 0, s2>>>();
    sgemm64<false, true><<<dim3(32, 3), 256, 0, s2>>>(E, pWC, out + O_ORIG, out + O_CPRED,
                                                      BSZ, NWC, D, D, NWC, 0);
    sgemm64<false, false><<<dim3(32, 2), 256, 0, s2>>>(out + O_CPRED, pZ, out + O_Y, nullptr,
                                                       BSZ, NCLS, NC, NC, NCLS, NCLS);
    cudaEventRecord(eJ, s2);

    // main: big_gemm -> select
    big_gemm<<<(NBANK + MTILE - 1) / MTILE, 256, BG_SMEM>>>(bank);
    select_topk<<<NC, 1024>>>();

    cudaStreamWaitEvent(0, eJ, 0);
    finalize<<<1, 256>>>(out);
}

// round 8
// speedup vs baseline: 2.8258x; 1.0075x over previous
#include <cuda_runtime.h>
#include <cuda_bf16.h>
#include <math.h>
#include <stdint.h>

#define D      512
#define NC     64
#define NBANK  200000
#define BSZ    2048
#define NCLS   100
#define KSEL   64
#define NCHUNK 8
#define MTILE  128
#define SJ_LD  132
#define NWC    164   // concat [W | C] columns
#define CCAP   2048

#define O_ORIG   0
#define O_Y      (BSZ*NCLS)
#define O_L1     (2*BSZ*NCLS)
#define O_L2     (O_L1+1)
#define O_NORM   (O_L1+2)
#define O_CPRED  (O_L1+3)

// ------------------------- device scratch ----------------------------------
__device__ unsigned g_D2[(size_t)NC*NBANK];   // d2 keys (float bits), row/concept
__device__ float    g_gram[NC*NC];
__device__ float    g_Wc[NC*NCLS];
__device__ float    g_Z[NC*NCLS];
__device__ float    g_WC[D*NWC];
__device__ float    g_csum[NC];
__device__ float    g_csqv[NC];
__device__ unsigned g_kmin[NC];
__device__ unsigned g_kmax[NC];
__device__ unsigned g_hist[NC*4096];
__device__ int      g_b1v[NC];
__device__ unsigned g_cb1v[NC];
__device__ int      g_widx[NC*KSEL];
__device__ unsigned g_wcnt[NC];
__device__ unsigned g_ccnt[NC];
__device__ unsigned g_candk[NC*CCAP];
__device__ int      g_candj[NC*CCAP];
// pre-swizzled bf16 C tiles: per chunk c, tile [64 n][64 k], 8KB each
__device__ uint4    g_Bh4[NCHUNK*512];

// ------------------------- helpers -----------------------------------------
__device__ __forceinline__ uint32_t smem_u32(const void* p) {
    uint32_t a;
    asm("{ .reg .u64 t; cvta.to.shared.u64 t, %1; cvt.u32.u64 %0, t; }"
        : "=r"(a) : "l"(p));
    return a;
}
__device__ __forceinline__ unsigned swz128(unsigned o) { return o ^ ((o >> 3) & 0x70u); }

__device__ __forceinline__ void cp16(uint32_t dst, const void* src) {
    asm volatile("cp.async.cg.shared.global [%0], [%1], 16;" :: "r"(dst), "l"(src));
}
#define CP_COMMIT() asm volatile("cp.async.commit_group;" ::: "memory")
#define CP_WAIT0()  asm volatile("cp.async.wait_group 0;" ::: "memory")
#define CP_WAIT1()  asm volatile("cp.async.wait_group 1;" ::: "memory")

#define LDMX4(r, a) \
    asm volatile("ldmatrix.sync.aligned.m8n8.x4.shared.b16 {%0,%1,%2,%3}, [%4];" \
        : "=r"((r)[0]), "=r"((r)[1]), "=r"((r)[2]), "=r"((r)[3]) : "r"(a))

#define MMA16816(d, a, b0, b1) \
    asm volatile("mma.sync.aligned.m16n8k16.row.col.f32.bf16.bf16.f32 " \
        "{%0,%1,%2,%3}, {%4,%5,%6,%7}, {%8,%9}, {%0,%1,%2,%3};" \
        : "+f"((d)[0]), "+f"((d)[1]), "+f"((d)[2]), "+f"((d)[3]) \
        : "r"((a)[0]), "r"((a)[1]), "r"((a)[2]), "r"((a)[3]), "r"(b0), "r"(b1))

__device__ __forceinline__ unsigned bin_of(unsigned key, unsigned kmin0, unsigned sh) {
    return (key < kmin0) ? 0u : min((key - kmin0) >> sh, 4095u);
}
__device__ __forceinline__ unsigned shift_of(unsigned range) {
    return (range >= 4096u) ? (unsigned)(32 - __clz(range) - 12) : 0u;
}

// -------- prep: swizzle C(bf16), build [W|C], c_sq, reset counters ----------
__global__ void __launch_bounds__(256) prep(const float* __restrict__ C,
                                            const float* __restrict__ W)
{
    int tid = threadIdx.x;
    int gtid = blockIdx.x * 256 + tid;
    int gstride = gridDim.x * 256;
    for (int idx = gtid; idx < D * NWC; idx += gstride) {
        int k = idx / NWC, n = idx % NWC;
        g_WC[idx] = (n < NCLS) ? W[k * NCLS + n] : C[k * NC + (n - NCLS)];
    }
    for (int i = gtid; i < NC * 4096; i += gstride) g_hist[i] = 0;
    if (blockIdx.x == 0) {
        char* bh = (char*)g_Bh4;
        for (int idx = tid; idx < D * NC; idx += 256) {
            int n = idx & 63, k = idx >> 6;
            float x = C[idx];
            __nv_bfloat16 h = __float2bfloat16_rn(x);
            int c = k >> 6, kk = k & 63;
            unsigned off = swz128((unsigned)(n * 128 + kk * 2));
            *(__nv_bfloat16*)(bh + c * 8192 + off) = h;
        }
        if (tid < NC) {
            float s = 0.f;
            #pragma unroll 8
            for (int k = 0; k < D; k++) {
                float x = C[k * NC + tid];
                s = __fmaf_rn(x, x, s);
            }
            g_csqv[tid] = s;
            g_kmin[tid] = 0xffffffffu;
            g_kmax[tid] = 0u;
            g_wcnt[tid] = 0u;
            g_ccnt[tid] = 0u;
        }
    }
}

// ------------------- small SGEMM (coalesced staging) ------------------------
template <bool ATRANS, bool SPLIT>
__global__ void __launch_bounds__(256) sgemm64(
    const float* __restrict__ A, const float* __restrict__ B,
    float* __restrict__ Co, float* __restrict__ Co2,
    int M, int N, int K, int lda, int ldb, int ldc)
{
    __shared__ float As[64][33];
    __shared__ __align__(16) float Bs[32][64];
    int tid = threadIdx.x;
    int m0 = blockIdx.x * 64, n0 = blockIdx.y * 64;
    int tx = tid & 15, ty = tid >> 4;
    float acc[4][4] = {};

    for (int k0 = 0; k0 < K; k0 += 32) {
        #pragma unroll
        for (int e = 0; e < 8; e++) {
            int idx = e * 256 + tid;
            if (ATRANS) {
                int m = idx & 63, k = idx >> 6;
                As[m][k] = A[(size_t)(k0 + k) * lda + (m0 + m)];
            } else {
                int k = idx & 31, m = idx >> 5;
                As[m][k] = A[(size_t)(m0 + m) * lda + (k0 + k)];
            }
            int n = idx & 63, k2 = idx >> 6;
            int nn = n0 + n;
            Bs[k2][n] = (nn < N) ? B[(size_t)(k0 + k2) * ldb + nn] : 0.f;
        }
        __syncthreads();
        #pragma unroll
        for (int k = 0; k < 32; k++) {
            float a0 = As[tx * 4 + 0][k];
            float a1 = As[tx * 4 + 1][k];
            float a2 = As[tx * 4 + 2][k];
            float a3 = As[tx * 4 + 3][k];
            float4 bv = *(const float4*)&Bs[k][ty * 4];
            acc[0][0] += a0 * bv.x; acc[0][1] += a0 * bv.y; acc[0][2] += a0 * bv.z; acc[0][3] += a0 * bv.w;
            acc[1][0] += a1 * bv.x; acc[1][1] += a1 * bv.y; acc[1][2] += a1 * bv.z; acc[1][3] += a1 * bv.w;
            acc[2][0] += a2 * bv.x; acc[2][1] += a2 * bv.y; acc[2][2] += a2 * bv.z; acc[2][3] += a2 * bv.w;
            acc[3][0] += a3 * bv.x; acc[3][1] += a3 * bv.y; acc[3][2] += a3 * bv.z; acc[3][3] += a3 * bv.w;
        }
        __syncthreads();
    }
    #pragma unroll
    for (int i = 0; i < 4; i++) {
        int m = m0 + tx * 4 + i;
        #pragma unroll
        for (int e = 0; e < 4; e++) {
            int nn = n0 + ty * 4 + e;
            if (nn < N) {
                if (SPLIT) {
                    if (nn < NCLS) Co[(size_t)m * NCLS + nn] = acc[i][e];
                    else           Co2[(size_t)m * NC + (nn - NCLS)] = acc[i][e];
                } else {
                    Co[(size_t)m * ldc + nn] = acc[i][e];
                }
            }
        }
    }
}

// ---- solve Z = G^{-1} Wc : column-owned GJ, 1 barrier/pivot ----------------
__global__ void __launch_bounds__(192) solve64()
{
    __shared__ float fc[2][64];
    int c = threadIdx.x;
    bool active = (c < 64 + NCLS);
    float col[64];

    if (active) {
        if (c < 64) {
            #pragma unroll
            for (int r = 0; r < 64; r++) col[r] = g_gram[r * 64 + c];
        } else {
            #pragma unroll
            for (int r = 0; r < 64; r++) col[r] = g_Wc[r * NCLS + (c - 64)];
        }
    }
    if (c == 0) {
        #pragma unroll
        for (int r = 0; r < 64; r++) fc[0][r] = col[r];
    }
    __syncthreads();

    #pragma unroll 1
    for (int p = 0; p < 64; p++) {
        const float* fcur = fc[p & 1];
        float pinv = 1.f / fcur[p];
        if (active) {
            float piv = col[p] * pinv;
            #pragma unroll
            for (int r = 0; r < 64; r++)
                col[r] = __fmaf_rn(-fcur[r], piv, col[r]);
            col[p] = piv;
            if (c == p + 1) {
                float* fnx = fc[(p + 1) & 1];
                #pragma unroll
                for (int r = 0; r < 64; r++) fnx[r] = col[r];
            }
        }
        __syncthreads();
    }
    if (c >= 64 && active) {
        #pragma unroll
        for (int r = 0; r < 64; r++) g_Z[r * NCLS + (c - 64)] = col[r];
    }
}

// -------- big GEMM: 1-term bf16 mma.sync, cp.async double buffer ------------
#define BG_SMEM (99072 + 1024)
__global__ void __launch_bounds__(256) big_gemm(const float* __restrict__ bank)
{
    extern __shared__ char sm[];
    uint32_t rawbase = smem_u32(sm);
    uint32_t base0 = (rawbase + 1023) & ~1023u;
    char* smp = sm + (base0 - rawbase);
    const int tid = threadIdx.x;
    const int lane = tid & 31, w = tid >> 5;
    const int wm = w & 3, wn = w >> 2;

    const uint32_t RAW = base0;
    const uint32_t BB  = base0 + 65536;
    const uint32_t AH  = base0 + 81920;
    float* row_sq = (float*)(smp + 98304);
    float* s_csq  = (float*)(smp + 98816);

    if (tid < NC) s_csq[tid] = g_csqv[tid];

    const int jbase = blockIdx.x * MTILE;
    const int r0 = tid >> 4, qa = tid & 15;
    float sq[8] = {};
    float acc[2][4][4] = {};
    const int arow = wm * 32 + (lane & 15);
    const int brow = wn * 32 + (lane & 15);
    const unsigned khb = (unsigned)(lane >> 4) * 16;

    auto issue = [&](int c, int b) {
        #pragma unroll
        for (int e = 0; e < 8; e++) {
            int s = e * 256 + tid;
            int r = s >> 4, cs = s & 15;
            int j = jbase + r; if (j >= NBANK) j = NBANK - 1;
            cp16(RAW + b * 32768 + s * 16, bank + (size_t)j * D + c * 64 + cs * 4);
        }
        #pragma unroll
        for (int e = 0; e < 2; e++) {
            int s = e * 256 + tid;
            cp16(BB + b * 8192 + s * 16, g_Bh4 + c * 512 + s);
        }
    };

    issue(0, 0); CP_COMMIT();

    for (int c = 0; c < NCHUNK; c++) {
        if (c) __syncthreads();
        if (c + 1 < NCHUNK) { issue(c + 1, (c + 1) & 1); CP_COMMIT(); CP_WAIT1(); }
        else CP_WAIT0();
        __syncthreads();

        const char* rb = smp + (c & 1) * 32768;
        #pragma unroll
        for (int p = 0; p < 8; p++) {
            int r = p * 16 + r0;
            float4 v = *(const float4*)(rb + r * 256 + qa * 16);
            sq[p] += v.x * v.x + v.y * v.y + v.z * v.z + v.w * v.w;
            __nv_bfloat162 h0 = __floats2bfloat162_rn(v.x, v.y);
            __nv_bfloat162 h1 = __floats2bfloat162_rn(v.z, v.w);
            uint2 hv;
            hv.x = *(unsigned*)&h0; hv.y = *(unsigned*)&h1;
            *(uint2*)(smp + 81920 + swz128((unsigned)(r * 128 + qa * 8))) = hv;
        }
        __syncthreads();

        const uint32_t BH = BB + (c & 1) * 8192;
        #pragma unroll
        for (int kc = 0; kc < 4; kc++) {
            uint32_t ah[2][4], bh4[2][4];
            #pragma unroll
            for (int mt = 0; mt < 2; mt++) {
                unsigned o = swz128((unsigned)((arow + mt * 16) * 128 + kc * 32 + khb));
                LDMX4(ah[mt], AH + o);
            }
            #pragma unroll
            for (int np = 0; np < 2; np++) {
                unsigned o = swz128((unsigned)((brow + np * 16) * 128 + kc * 32 + khb));
                LDMX4(bh4[np], BH + o);
            }
            #pragma unroll
            for (int mt = 0; mt < 2; mt++) {
                #pragma unroll
                for (int nt = 0; nt < 4; nt++) {
                    int np = nt >> 1, hf = nt & 1;
                    MMA16816(acc[mt][nt], ah[mt], bh4[np][hf], bh4[np][hf + 2]);
                }
            }
        }
    }

    // row sumsq (local only)
    #pragma unroll
    for (int p = 0; p < 8; p++) {
        #pragma unroll
        for (int o = 8; o; o >>= 1)
            sq[p] += __shfl_xor_sync(0xffffffffu, sq[p], o, 16);
    }
    if (qa == 0) {
        #pragma unroll
        for (int p = 0; p < 8; p++) row_sq[p * 16 + r0] = sq[p];
    }
    __syncthreads();

    float* sT = (float*)smp;
    #pragma unroll
    for (int mt = 0; mt < 2; mt++) {
        #pragma unroll
        for (int nt = 0; nt < 4; nt++) {
            #pragma unroll
            for (int r = 0; r < 4; r++) {
                int m = wm * 32 + mt * 16 + (lane >> 2) + ((r >> 1) * 8);
                int n = wn * 32 + nt * 8 + (lane & 3) * 2 + (r & 1);
                sT[n * SJ_LD + m] = acc[mt][nt][r];
            }
        }
    }
    __syncthreads();

    {
        int j = tid & 127, nh = tid >> 7;
        float myb = row_sq[j];
        int jg = jbase + j;
        bool ok = (jg < NBANK);
        #pragma unroll 8
        for (int n = nh * 32; n < nh * 32 + 32; n++) {
            float s = sT[n * SJ_LD + j];
            float d2 = fmaxf(__fmaf_rn(-2.f, s, s_csq[n] + myb), 0.f);
            unsigned key = __float_as_uint(d2);
            if (ok) g_D2[(size_t)n * NBANK + jg] = key;
            ((unsigned*)sT)[n * SJ_LD + j] = key;
        }
    }
    __syncthreads();
    {
        int n = tid >> 2, seg = tid & 3;
        unsigned mn = 0xffffffffu, mx = 0u;
        const unsigned* u = (const unsigned*)sT + n * SJ_LD + seg * 32;
        #pragma unroll 8
        for (int i = 0; i < 32; i++) {
            unsigned k = u[i];
            mn = min(mn, k); mx = max(mx, k);
        }
        mn = min(mn, __shfl_xor_sync(0xffffffffu, mn, 1, 4));
        mn = min(mn, __shfl_xor_sync(0xffffffffu, mn, 2, 4));
        mx = max(mx, __shfl_xor_sync(0xffffffffu, mx, 1, 4));
        mx = max(mx, __shfl_xor_sync(0xffffffffu, mx, 2, 4));
        if (seg == 0) { atomicMin(&g_kmin[n], mn); atomicMax(&g_kmax[n], mx); }
    }
}

// ---------- select stage 1: histogram (2 CTAs per concept) ------------------
__global__ void __launch_bounds__(1024) sel_hist()
{
    int n = blockIdx.x >> 1, half = blockIdx.x & 1;
    int tid = threadIdx.x;
    __shared__ unsigned hist[4096];
    for (int i = tid; i < 4096; i += 1024) hist[i] = 0;
    __syncthreads();

    unsigned kmin0 = g_kmin[n];
    unsigned sh = shift_of(g_kmax[n] - kmin0);
    const uint4* keys = (const uint4*)(g_D2 + (size_t)n * NBANK);
    int j40 = half * (NBANK / 8), j41 = j40 + NBANK / 8;
    for (int j4 = j40 + tid; j4 < j41; j4 += 1024) {
        uint4 kv = keys[j4];
        atomicAdd(&hist[bin_of(kv.x, kmin0, sh)], 1u);
        atomicAdd(&hist[bin_of(kv.y, kmin0, sh)], 1u);
        atomicAdd(&hist[bin_of(kv.z, kmin0, sh)], 1u);
        atomicAdd(&hist[bin_of(kv.w, kmin0, sh)], 1u);
    }
    __syncthreads();
    for (int i = tid; i < 4096; i += 1024)
        if (hist[i]) atomicAdd(&g_hist[n * 4096 + i], hist[i]);
}

// ---------- select stage 2: find boundary bin per concept -------------------
__global__ void __launch_bounds__(1024) sel_pick()
{
    int n = blockIdx.x;
    int tid = threadIdx.x, lane = tid & 31, w = tid >> 5;
    __shared__ unsigned wbufa[32];
    const unsigned* hist = g_hist + n * 4096;

    unsigned h0 = hist[tid*4], h1 = hist[tid*4+1], h2 = hist[tid*4+2], h3 = hist[tid*4+3];
    unsigned tsum = h0 + h1 + h2 + h3;
    unsigned v = tsum;
    #pragma unroll
    for (int o = 1; o < 32; o <<= 1) {
        unsigned u = __shfl_up_sync(0xffffffffu, v, o);
        if (lane >= o) v += u;
    }
    if (lane == 31) wbufa[w] = v;
    __syncthreads();
    if (tid < 32) {
        unsigned x = wbufa[tid];
        #pragma unroll
        for (int o = 1; o < 32; o <<= 1) {
            unsigned u = __shfl_up_sync(0xffffffffu, x, o);
            if (tid >= o) x += u;
        }
        wbufa[tid] = x;
    }
    __syncthreads();
    unsigned excl = v - tsum + (w ? wbufa[w - 1] : 0u);
    if (excl < KSEL && excl + tsum >= KSEL) {
        unsigned c = excl;
        unsigned hh[4] = {h0, h1, h2, h3};
        int i = 0;
        while (i < 3 && c + hh[i] < KSEL) { c += hh[i]; i++; }
        g_b1v[n] = tid * 4 + i;
        g_cb1v[n] = c;
    }
}

// ---------- select stage 3: collect winners + boundary candidates -----------
__global__ void __launch_bounds__(1024) sel_collect()
{
    int n = blockIdx.x >> 1, half = blockIdx.x & 1;
    int tid = threadIdx.x;
    unsigned kmin0 = g_kmin[n];
    unsigned sh = shift_of(g_kmax[n] - kmin0);
    int b1 = g_b1v[n];
    const uint4* keys = (const uint4*)(g_D2 + (size_t)n * NBANK);
    int j40 = half * (NBANK / 8), j41 = j40 + NBANK / 8;
    for (int j4 = j40 + tid; j4 < j41; j4 += 1024) {
        uint4 kv = keys[j4];
        unsigned ka[4] = {kv.x, kv.y, kv.z, kv.w};
        #pragma unroll
        for (int t = 0; t < 4; t++) {
            int b = (int)bin_of(ka[t], kmin0, sh);
            if (b < b1) {
                unsigned p = atomicAdd(&g_wcnt[n], 1u);
                if (p < KSEL) g_widx[n * KSEL + p] = j4 * 4 + t;
            } else if (b == b1) {
                unsigned p = atomicAdd(&g_ccnt[n], 1u);
                if (p < CCAP) { g_candk[n * CCAP + p] = ka[t]; g_candj[n * CCAP + p] = j4 * 4 + t; }
            }
        }
    }
}

// ---------- select stage 4: boundary picks + exact fp32 rescore -------------
__global__ void __launch_bounds__(256) rescore(const float* __restrict__ C,
                                               const float* __restrict__ bank)
{
    int n = blockIdx.x;
    int tid = threadIdx.x;
    __shared__ float cvec[D];
    __shared__ int   widx[KSEL];
    __shared__ float dots[KSEL];
    __shared__ unsigned ck[CCAP];
    __shared__ int      cj[CCAP];

    int nb = (int)g_wcnt[n];                      // definite winners (< KSEL)
    int m  = (int)min(g_ccnt[n], (unsigned)CCAP);
    int r  = KSEL - nb;

    // stage candidates into smem
    for (int i = tid; i < m; i += 256) {
        ck[i] = g_candk[n * CCAP + i];
        cj[i] = g_candj[n * CCAP + i];
    }
    for (int i = tid; i < nb && i < KSEL; i += 256) widx[i] = g_widx[n * KSEL + i];
    // C column n
    cvec[tid]       = C[tid * NC + n];
    cvec[tid + 256] = C[(tid + 256) * NC + n];
    __syncthreads();

    // warp 0 picks r smallest (key, j) among candidates
    if (tid < 32) {
        for (int it = 0; it < r; it++) {
            unsigned best = 0xffffffffu;
            int bestj = 0x7fffffff, bi = -1;
            for (int i = tid; i < m; i += 32) {
                unsigned k = ck[i];
                int jj = cj[i];
                if (k < best || (k == best && jj < bestj)) { best = k; bestj = jj; bi = i; }
            }
            #pragma unroll
            for (int o = 16; o; o >>= 1) {
                unsigned ok = __shfl_xor_sync(0xffffffffu, best, o);
                int      oj = __shfl_xor_sync(0xffffffffu, bestj, o);
                int      ob = __shfl_xor_sync(0xffffffffu, bi, o);
                if (ok < best || (ok == best && oj < bestj)) { best = ok; bestj = oj; bi = ob; }
            }
            if (tid == 0) {
                widx[nb + it] = bestj;
                if (bi >= 0) { ck[bi] = 0xffffffffu; cj[bi] = 0x7fffffff; }
            }
            __syncwarp();
        }
    }
    __syncthreads();

    // deterministic order: insertion-sort 64 indices (thread 0)
    if (tid == 0) {
        for (int i = 1; i < KSEL; i++) {
            int key = widx[i], k2 = i - 1;
            while (k2 >= 0 && widx[k2] > key) { widx[k2 + 1] = widx[k2]; k2--; }
            widx[k2 + 1] = key;
        }
    }
    __syncthreads();

    // exact fp32 dots: quad per winner
    {
        int wi = tid >> 2, l = tid & 3;
        const float* brow = bank + (size_t)widx[wi] * D;
        float s = 0.f;
        #pragma unroll 16
        for (int k = l * 4; k < D; k += 16) {
            float4 bv = *(const float4*)(brow + k);
            s = __fmaf_rn(bv.x, cvec[k], s);
            s = __fmaf_rn(bv.y, cvec[k + 1], s);
            s = __fmaf_rn(bv.z, cvec[k + 2], s);
            s = __fmaf_rn(bv.w, cvec[k + 3], s);
        }
        s += __shfl_xor_sync(0xffffffffu, s, 1, 4);
        s += __shfl_xor_sync(0xffffffffu, s, 2, 4);
        if (l == 0) dots[wi] = s;
    }
    __syncthreads();
    if (tid == 0) {
        float s = 0.f;
        for (int i = 0; i < KSEL; i++) s += dots[i];
        g_csum[n] = s;
    }
}

// ------------------- scalars ------------------------------------------------
__global__ void __launch_bounds__(256) finalize(float* __restrict__ out)
{
    __shared__ float r1[8], r2[8], r3[8];
    int tid = threadIdx.x, lane = tid & 31, w = tid >> 5;
    float gs = 0.f, tr = 0.f;
    for (int i = tid; i < NC * NC; i += 256) {
        float v = g_gram[i];
        gs += v;
        if ((i >> 6) == (i & 63)) tr += v;
    }
    float cs = (tid < NC) ? g_csum[tid] : 0.f;
    #pragma unroll
    for (int o = 16; o; o >>= 1) {
        gs += __shfl_xor_sync(0xffffffffu, gs, o);
        tr += __shfl_xor_sync(0xffffffffu, tr, o);
        cs += __shfl_xor_sync(0xffffffffu, cs, o);
    }
    if (lane == 0) { r1[w] = gs; r2[w] = tr; r3[w] = cs; }
    __syncthreads();
    if (tid == 0) {
        float GS = 0, TR = 0, CS = 0;
        for (int i = 0; i < 8; i++) { GS += r1[i]; TR += r2[i]; CS += r3[i]; }
        out[O_L1]   = CS / (float)(NC * KSEL);
        out[O_L2]   = (GS - TR) / (float)(NC * NC);
        out[O_NORM] = TR / (float)(NC * NC);
    }
}

// ----------------------------------------------------------------------------
extern "C" void kernel_launch(void* const* d_in, const int* in_sizes, int n_in,
                              void* d_out, int out_size)
{
    (void)in_sizes; (void)n_in; (void)out_size;
    const float* C    = (const float*)d_in[0];  // (512, 64)
    const float* E    = (const float*)d_in[1];  // (2048, 512)
    const float* bank = (const float*)d_in[2];  // (200000, 512)
    const float* W    = (const float*)d_in[3];  // (512, 100)
    float* out = (float*)d_out;

    float *pgram, *pWc, *pZ, *pWC;
    cudaGetSymbolAddress((void**)&pgram, g_gram);
    cudaGetSymbolAddress((void**)&pWc,   g_Wc);
    cudaGetSymbolAddress((void**)&pZ,    g_Z);
    cudaGetSymbolAddress((void**)&pWC,   g_WC);

    cudaFuncSetAttribute(big_gemm, cudaFuncAttributeMaxDynamicSharedMemorySize, BG_SMEM);

    cudaStream_t s2;
    cudaStreamCreateWithFlags(&s2, cudaStreamNonBlocking);
    cudaEvent_t eF, eJ;
    cudaEventCreateWithFlags(&eF, cudaEventDisableTiming);
    cudaEventCreateWithFlags(&eJ, cudaEventDisableTiming);

    // main: prep (B tile bf16, [W|C], c_sq, counter/hist reset)
    prep<<<64, 256>>>(C, W);
    cudaEventRecord(eF, 0);
    cudaStreamWaitEvent(s2, eF, 0);

    // branch A (side stream): [Wc|gram] = C^T@[W|C] -> solve -> E@[W|C] -> y
    sgemm64<true, true><<<dim3(1, 3), 256, 0, s2>>>(C, pWC, pWc, pgram, NC, NWC, D, NC, NWC, 0);
    solve64<<<1, 192, 0, s2>>>();
    sgemm64<false, true><<<dim3(32, 3), 256, 0, s2>>>(E, pWC, out + O_ORIG, out + O_CPRED,
                                                      BSZ, NWC, D, D, NWC, 0);
    sgemm64<false, false><<<dim3(32, 2), 256, 0, s2>>>(out + O_CPRED, pZ, out + O_Y, nullptr,
                                                       BSZ, NCLS, NC, NC, NCLS, NCLS);
    cudaEventRecord(eJ, s2);

    // main: big_gemm -> select (4 stages, full-chip) -> rescore
    big_gemm<<<(NBANK + MTILE - 1) / MTILE, 256, BG_SMEM>>>(bank);
    sel_hist<<<NC * 2, 1024>>>();
    sel_pick<<<NC, 1024>>>();
    sel_collect<<<NC * 2, 1024>>>();
    rescore<<<NC, 256>>>(C, bank);

    cudaStreamWaitEvent(0, eJ, 0);
    finalize<<<1, 256>>>(out);
}

// round 9
// speedup vs baseline: 2.8331x; 1.0026x over previous
#include <cuda_runtime.h>
#include <cuda_bf16.h>
#include <math.h>
#include <stdint.h>

#define D      512
#define NC     64
#define NBANK  200000
#define BSZ    2048
#define NCLS   100
#define KSEL   64
#define NCHUNK 8
#define MTILE  128
#define SJ_LD  132
#define NWC    164   // concat [W | C] columns
#define CCAP   3072
#define D2EPS  1.5f  // margin on approx d2 (~28 sigma of bf16 noise)

#define O_ORIG   0
#define O_Y      (BSZ*NCLS)
#define O_L1     (2*BSZ*NCLS)
#define O_L2     (O_L1+1)
#define O_NORM   (O_L1+2)
#define O_CPRED  (O_L1+3)

// ------------------------- device scratch ----------------------------------
__device__ unsigned g_D2[(size_t)NC*NBANK];   // approx d2 keys (float bits)
__device__ float    g_gram[NC*NC];
__device__ float    g_Wc[NC*NCLS];
__device__ float    g_Z[NC*NCLS];
__device__ float    g_WC[D*NWC];
__device__ float    g_csum[NC];
__device__ float    g_csqv[NC];
__device__ unsigned g_kmin[NC];
__device__ unsigned g_kmax[NC];
__device__ unsigned g_hist[NC*4096];
__device__ int      g_bhiv[NC];
__device__ unsigned g_ccnt[NC];
__device__ int      g_candj[NC*CCAP];
// pre-swizzled bf16 C tiles: per chunk c, tile [64 n][64 k], 8KB each
__device__ uint4    g_Bh4[NCHUNK*512];

// ------------------------- helpers -----------------------------------------
__device__ __forceinline__ uint32_t smem_u32(const void* p) {
    uint32_t a;
    asm("{ .reg .u64 t; cvta.to.shared.u64 t, %1; cvt.u32.u64 %0, t; }"
        : "=r"(a) : "l"(p));
    return a;
}
__device__ __forceinline__ unsigned swz128(unsigned o) { return o ^ ((o >> 3) & 0x70u); }

__device__ __forceinline__ void cp16(uint32_t dst, const void* src) {
    asm volatile("cp.async.cg.shared.global [%0], [%1], 16;" :: "r"(dst), "l"(src));
}
#define CP_COMMIT() asm volatile("cp.async.commit_group;" ::: "memory")
#define CP_WAIT0()  asm volatile("cp.async.wait_group 0;" ::: "memory")
#define CP_WAIT1()  asm volatile("cp.async.wait_group 1;" ::: "memory")

#define LDMX4(r, a) \
    asm volatile("ldmatrix.sync.aligned.m8n8.x4.shared.b16 {%0,%1,%2,%3}, [%4];" \
        : "=r"((r)[0]), "=r"((r)[1]), "=r"((r)[2]), "=r"((r)[3]) : "r"(a))

#define MMA16816(d, a, b0, b1) \
    asm volatile("mma.sync.aligned.m16n8k16.row.col.f32.bf16.bf16.f32 " \
        "{%0,%1,%2,%3}, {%4,%5,%6,%7}, {%8,%9}, {%0,%1,%2,%3};" \
        : "+f"((d)[0]), "+f"((d)[1]), "+f"((d)[2]), "+f"((d)[3]) \
        : "r"((a)[0]), "r"((a)[1]), "r"((a)[2]), "r"((a)[3]), "r"(b0), "r"(b1))

__device__ __forceinline__ unsigned bin_of(unsigned key, unsigned kmin0, unsigned sh) {
    return (key < kmin0) ? 0u : min((key - kmin0) >> sh, 4095u);
}
__device__ __forceinline__ unsigned shift_of(unsigned range) {
    return (range >= 4096u) ? (unsigned)(32 - __clz(range) - 12) : 0u;
}

// -------- prep: swizzle C(bf16), build [W|C], c_sq, reset counters ----------
__global__ void __launch_bounds__(256) prep(const float* __restrict__ C,
                                            const float* __restrict__ W)
{
    int tid = threadIdx.x;
    int gtid = blockIdx.x * 256 + tid;
    int gstride = gridDim.x * 256;
    for (int idx = gtid; idx < D * NWC; idx += gstride) {
        int k = idx / NWC, n = idx % NWC;
        g_WC[idx] = (n < NCLS) ? W[k * NCLS + n] : C[k * NC + (n - NCLS)];
    }
    for (int i = gtid; i < NC * 4096; i += gstride) g_hist[i] = 0;
    if (blockIdx.x == 0) {
        char* bh = (char*)g_Bh4;
        for (int idx = tid; idx < D * NC; idx += 256) {
            int n = idx & 63, k = idx >> 6;
            float x = C[idx];
            __nv_bfloat16 h = __float2bfloat16_rn(x);
            int c = k >> 6, kk = k & 63;
            unsigned off = swz128((unsigned)(n * 128 + kk * 2));
            *(__nv_bfloat16*)(bh + c * 8192 + off) = h;
        }
        if (tid < NC) {
            float s = 0.f;
            #pragma unroll 8
            for (int k = 0; k < D; k++) {
                float x = C[k * NC + tid];
                s = __fmaf_rn(x, x, s);
            }
            g_csqv[tid] = s;
            g_kmin[tid] = 0xffffffffu;
            g_kmax[tid] = 0u;
            g_ccnt[tid] = 0u;
        }
    }
}

// ------------------- small SGEMM (coalesced staging) ------------------------
template <bool ATRANS, bool SPLIT>
__global__ void __launch_bounds__(256) sgemm64(
    const float* __restrict__ A, const float* __restrict__ B,
    float* __restrict__ Co, float* __restrict__ Co2,
    int M, int N, int K, int lda, int ldb, int ldc)
{
    __shared__ float As[64][33];
    __shared__ __align__(16) float Bs[32][64];
    int tid = threadIdx.x;
    int m0 = blockIdx.x * 64, n0 = blockIdx.y * 64;
    int tx = tid & 15, ty = tid >> 4;
    float acc[4][4] = {};

    for (int k0 = 0; k0 < K; k0 += 32) {
        #pragma unroll
        for (int e = 0; e < 8; e++) {
            int idx = e * 256 + tid;
            if (ATRANS) {
                int m = idx & 63, k = idx >> 6;
                As[m][k] = A[(size_t)(k0 + k) * lda + (m0 + m)];
            } else {
                int k = idx & 31, m = idx >> 5;
                As[m][k] = A[(size_t)(m0 + m) * lda + (k0 + k)];
            }
            int n = idx & 63, k2 = idx >> 6;
            int nn = n0 + n;
            Bs[k2][n] = (nn < N) ? B[(size_t)(k0 + k2) * ldb + nn] : 0.f;
        }
        __syncthreads();
        #pragma unroll
        for (int k = 0; k < 32; k++) {
            float a0 = As[tx * 4 + 0][k];
            float a1 = As[tx * 4 + 1][k];
            float a2 = As[tx * 4 + 2][k];
            float a3 = As[tx * 4 + 3][k];
            float4 bv = *(const float4*)&Bs[k][ty * 4];
            acc[0][0] += a0 * bv.x; acc[0][1] += a0 * bv.y; acc[0][2] += a0 * bv.z; acc[0][3] += a0 * bv.w;
            acc[1][0] += a1 * bv.x; acc[1][1] += a1 * bv.y; acc[1][2] += a1 * bv.z; acc[1][3] += a1 * bv.w;
            acc[2][0] += a2 * bv.x; acc[2][1] += a2 * bv.y; acc[2][2] += a2 * bv.z; acc[2][3] += a2 * bv.w;
            acc[3][0] += a3 * bv.x; acc[3][1] += a3 * bv.y; acc[3][2] += a3 * bv.z; acc[3][3] += a3 * bv.w;
        }
        __syncthreads();
    }
    #pragma unroll
    for (int i = 0; i < 4; i++) {
        int m = m0 + tx * 4 + i;
        #pragma unroll
        for (int e = 0; e < 4; e++) {
            int nn = n0 + ty * 4 + e;
            if (nn < N) {
                if (SPLIT) {
                    if (nn < NCLS) Co[(size_t)m * NCLS + nn] = acc[i][e];
                    else           Co2[(size_t)m * NC + (nn - NCLS)] = acc[i][e];
                } else {
                    Co[(size_t)m * ldc + nn] = acc[i][e];
                }
            }
        }
    }
}

// ---- solve Z = G^{-1} Wc : column-owned GJ, 1 barrier/pivot ----------------
__global__ void __launch_bounds__(192) solve64()
{
    __shared__ float fc[2][64];
    int c = threadIdx.x;
    bool active = (c < 64 + NCLS);
    float col[64];

    if (active) {
        if (c < 64) {
            #pragma unroll
            for (int r = 0; r < 64; r++) col[r] = g_gram[r * 64 + c];
        } else {
            #pragma unroll
            for (int r = 0; r < 64; r++) col[r] = g_Wc[r * NCLS + (c - 64)];
        }
    }
    if (c == 0) {
        #pragma unroll
        for (int r = 0; r < 64; r++) fc[0][r] = col[r];
    }
    __syncthreads();

    #pragma unroll 1
    for (int p = 0; p < 64; p++) {
        const float* fcur = fc[p & 1];
        float pinv = 1.f / fcur[p];
        if (active) {
            float piv = col[p] * pinv;
            #pragma unroll
            for (int r = 0; r < 64; r++)
                col[r] = __fmaf_rn(-fcur[r], piv, col[r]);
            col[p] = piv;
            if (c == p + 1) {
                float* fnx = fc[(p + 1) & 1];
                #pragma unroll
                for (int r = 0; r < 64; r++) fnx[r] = col[r];
            }
        }
        __syncthreads();
    }
    if (c >= 64 && active) {
        #pragma unroll
        for (int r = 0; r < 64; r++) g_Z[r * NCLS + (c - 64)] = col[r];
    }
}

// -------- big GEMM: 1-term bf16 mma.sync, cp.async double buffer ------------
#define BG_SMEM (99072 + 1024)
__global__ void __launch_bounds__(256) big_gemm(const float* __restrict__ bank)
{
    extern __shared__ char sm[];
    uint32_t rawbase = smem_u32(sm);
    uint32_t base0 = (rawbase + 1023) & ~1023u;
    char* smp = sm + (base0 - rawbase);
    const int tid = threadIdx.x;
    const int lane = tid & 31, w = tid >> 5;
    const int wm = w & 3, wn = w >> 2;

    const uint32_t RAW = base0;
    const uint32_t BB  = base0 + 65536;
    const uint32_t AH  = base0 + 81920;
    float* row_sq = (float*)(smp + 98304);
    float* s_csq  = (float*)(smp + 98816);

    if (tid < NC) s_csq[tid] = g_csqv[tid];

    const int jbase = blockIdx.x * MTILE;
    const int r0 = tid >> 4, qa = tid & 15;
    float sq[8] = {};
    float acc[2][4][4] = {};
    const int arow = wm * 32 + (lane & 15);
    const int brow = wn * 32 + (lane & 15);
    const unsigned khb = (unsigned)(lane >> 4) * 16;

    auto issue = [&](int c, int b) {
        #pragma unroll
        for (int e = 0; e < 8; e++) {
            int s = e * 256 + tid;
            int r = s >> 4, cs = s & 15;
            int j = jbase + r; if (j >= NBANK) j = NBANK - 1;
            cp16(RAW + b * 32768 + s * 16, bank + (size_t)j * D + c * 64 + cs * 4);
        }
        #pragma unroll
        for (int e = 0; e < 2; e++) {
            int s = e * 256 + tid;
            cp16(BB + b * 8192 + s * 16, g_Bh4 + c * 512 + s);
        }
    };

    issue(0, 0); CP_COMMIT();

    for (int c = 0; c < NCHUNK; c++) {
        if (c) __syncthreads();
        if (c + 1 < NCHUNK) { issue(c + 1, (c + 1) & 1); CP_COMMIT(); CP_WAIT1(); }
        else CP_WAIT0();
        __syncthreads();

        const char* rb = smp + (c & 1) * 32768;
        #pragma unroll
        for (int p = 0; p < 8; p++) {
            int r = p * 16 + r0;
            float4 v = *(const float4*)(rb + r * 256 + qa * 16);
            sq[p] += v.x * v.x + v.y * v.y + v.z * v.z + v.w * v.w;
            __nv_bfloat162 h0 = __floats2bfloat162_rn(v.x, v.y);
            __nv_bfloat162 h1 = __floats2bfloat162_rn(v.z, v.w);
            uint2 hv;
            hv.x = *(unsigned*)&h0; hv.y = *(unsigned*)&h1;
            *(uint2*)(smp + 81920 + swz128((unsigned)(r * 128 + qa * 8))) = hv;
        }
        __syncthreads();

        const uint32_t BH = BB + (c & 1) * 8192;
        #pragma unroll
        for (int kc = 0; kc < 4; kc++) {
            uint32_t ah[2][4], bh4[2][4];
            #pragma unroll
            for (int mt = 0; mt < 2; mt++) {
                unsigned o = swz128((unsigned)((arow + mt * 16) * 128 + kc * 32 + khb));
                LDMX4(ah[mt], AH + o);
            }
            #pragma unroll
            for (int np = 0; np < 2; np++) {
                unsigned o = swz128((unsigned)((brow + np * 16) * 128 + kc * 32 + khb));
                LDMX4(bh4[np], BH + o);
            }
            #pragma unroll
            for (int mt = 0; mt < 2; mt++) {
                #pragma unroll
                for (int nt = 0; nt < 4; nt++) {
                    int np = nt >> 1, hf = nt & 1;
                    MMA16816(acc[mt][nt], ah[mt], bh4[np][hf], bh4[np][hf + 2]);
                }
            }
        }
    }

    #pragma unroll
    for (int p = 0; p < 8; p++) {
        #pragma unroll
        for (int o = 8; o; o >>= 1)
            sq[p] += __shfl_xor_sync(0xffffffffu, sq[p], o, 16);
    }
    if (qa == 0) {
        #pragma unroll
        for (int p = 0; p < 8; p++) row_sq[p * 16 + r0] = sq[p];
    }
    __syncthreads();

    float* sT = (float*)smp;
    #pragma unroll
    for (int mt = 0; mt < 2; mt++) {
        #pragma unroll
        for (int nt = 0; nt < 4; nt++) {
            #pragma unroll
            for (int r = 0; r < 4; r++) {
                int m = wm * 32 + mt * 16 + (lane >> 2) + ((r >> 1) * 8);
                int n = wn * 32 + nt * 8 + (lane & 3) * 2 + (r & 1);
                sT[n * SJ_LD + m] = acc[mt][nt][r];
            }
        }
    }
    __syncthreads();

    {
        int j = tid & 127, nh = tid >> 7;
        float myb = row_sq[j];
        int jg = jbase + j;
        bool ok = (jg < NBANK);
        #pragma unroll 8
        for (int n = nh * 32; n < nh * 32 + 32; n++) {
            float s = sT[n * SJ_LD + j];
            float d2 = fmaxf(__fmaf_rn(-2.f, s, s_csq[n] + myb), 0.f);
            unsigned key = __float_as_uint(d2);
            if (ok) g_D2[(size_t)n * NBANK + jg] = key;
            ((unsigned*)sT)[n * SJ_LD + j] = key;
        }
    }
    __syncthreads();
    {
        int n = tid >> 2, seg = tid & 3;
        unsigned mn = 0xffffffffu, mx = 0u;
        const unsigned* u = (const unsigned*)sT + n * SJ_LD + seg * 32;
        #pragma unroll 8
        for (int i = 0; i < 32; i++) {
            unsigned k = u[i];
            mn = min(mn, k); mx = max(mx, k);
        }
        mn = min(mn, __shfl_xor_sync(0xffffffffu, mn, 1, 4));
        mn = min(mn, __shfl_xor_sync(0xffffffffu, mn, 2, 4));
        mx = max(mx, __shfl_xor_sync(0xffffffffu, mx, 1, 4));
        mx = max(mx, __shfl_xor_sync(0xffffffffu, mx, 2, 4));
        if (seg == 0) { atomicMin(&g_kmin[n], mn); atomicMax(&g_kmax[n], mx); }
    }
}

// ---------- select stage 1: histogram (2 CTAs per concept) ------------------
__global__ void __launch_bounds__(1024) sel_hist()
{
    int n = blockIdx.x >> 1, half = blockIdx.x & 1;
    int tid = threadIdx.x;
    __shared__ unsigned hist[4096];
    for (int i = tid; i < 4096; i += 1024) hist[i] = 0;
    __syncthreads();

    unsigned kmin0 = g_kmin[n];
    unsigned sh = shift_of(g_kmax[n] - kmin0);
    const uint4* keys = (const uint4*)(g_D2 + (size_t)n * NBANK);
    int j40 = half * (NBANK / 8), j41 = j40 + NBANK / 8;
    for (int j4 = j40 + tid; j4 < j41; j4 += 1024) {
        uint4 kv = keys[j4];
        atomicAdd(&hist[bin_of(kv.x, kmin0, sh)], 1u);
        atomicAdd(&hist[bin_of(kv.y, kmin0, sh)], 1u);
        atomicAdd(&hist[bin_of(kv.z, kmin0, sh)], 1u);
        atomicAdd(&hist[bin_of(kv.w, kmin0, sh)], 1u);
    }
    __syncthreads();
    for (int i = tid; i < 4096; i += 1024)
        if (hist[i]) atomicAdd(&g_hist[n * 4096 + i], hist[i]);
}

// ---------- select stage 2: boundary bin + margin bin per concept -----------
__global__ void __launch_bounds__(1024) sel_pick()
{
    int n = blockIdx.x;
    int tid = threadIdx.x, lane = tid & 31, w = tid >> 5;
    __shared__ unsigned wbufa[32];
    const unsigned* hist = g_hist + n * 4096;
    unsigned kmin0 = g_kmin[n];
    unsigned sh = shift_of(g_kmax[n] - kmin0);

    unsigned h0 = hist[tid*4], h1 = hist[tid*4+1], h2 = hist[tid*4+2], h3 = hist[tid*4+3];
    unsigned tsum = h0 + h1 + h2 + h3;
    unsigned v = tsum;
    #pragma unroll
    for (int o = 1; o < 32; o <<= 1) {
        unsigned u = __shfl_up_sync(0xffffffffu, v, o);
        if (lane >= o) v += u;
    }
    if (lane == 31) wbufa[w] = v;
    __syncthreads();
    if (tid < 32) {
        unsigned x = wbufa[tid];
        #pragma unroll
        for (int o = 1; o < 32; o <<= 1) {
            unsigned u = __shfl_up_sync(0xffffffffu, x, o);
            if (tid >= o) x += u;
        }
        wbufa[tid] = x;
    }
    __syncthreads();
    unsigned excl = v - tsum + (w ? wbufa[w - 1] : 0u);
    if (excl < KSEL && excl + tsum >= KSEL) {
        unsigned c = excl;
        unsigned hh[4] = {h0, h1, h2, h3};
        int i = 0;
        while (i < 3 && c + hh[i] < KSEL) { c += hh[i]; i++; }
        int b1 = tid * 4 + i;
        // margin: upper key edge of bin b1, plus D2EPS in float domain
        unsigned tb = kmin0 + ((unsigned)(b1 + 1) << sh);
        float tf = __uint_as_float(tb) + D2EPS;
        g_bhiv[n] = (int)bin_of(__float_as_uint(tf), kmin0, sh);
    }
}

// ---------- select stage 3: collect all candidates within margin ------------
__global__ void __launch_bounds__(1024) sel_collect()
{
    int n = blockIdx.x >> 1, half = blockIdx.x & 1;
    int tid = threadIdx.x;
    unsigned kmin0 = g_kmin[n];
    unsigned sh = shift_of(g_kmax[n] - kmin0);
    int bhi = g_bhiv[n];
    const uint4* keys = (const uint4*)(g_D2 + (size_t)n * NBANK);
    int j40 = half * (NBANK / 8), j41 = j40 + NBANK / 8;
    for (int j4 = j40 + tid; j4 < j41; j4 += 1024) {
        uint4 kv = keys[j4];
        unsigned ka[4] = {kv.x, kv.y, kv.z, kv.w};
        #pragma unroll
        for (int t = 0; t < 4; t++) {
            if ((int)bin_of(ka[t], kmin0, sh) <= bhi) {
                unsigned p = atomicAdd(&g_ccnt[n], 1u);
                if (p < CCAP) g_candj[n * CCAP + p] = j4 * 4 + t;
            }
        }
    }
}

// ---------- select stage 4: exact fp32 re-rank + sum of top-64 dots ---------
__global__ void __launch_bounds__(256) rescore(const float* __restrict__ C,
                                               const float* __restrict__ bank)
{
    int n = blockIdx.x;
    int tid = threadIdx.x, lane = tid & 31, w = tid >> 5;
    __shared__ float    cvec[D];
    __shared__ int      cj[CCAP];
    __shared__ unsigned sd2[CCAP];
    __shared__ float    sdot[CCAP];

    int m = (int)min(g_ccnt[n], (unsigned)CCAP);
    for (int i = tid; i < m; i += 256) cj[i] = g_candj[n * CCAP + i];
    cvec[tid]       = C[tid * NC + n];
    cvec[tid + 256] = C[(tid + 256) * NC + n];
    float csq = g_csqv[n];
    __syncthreads();

    // exact fp32 dot + bank_sq per candidate (one warp each)
    for (int i = w; i < m; i += 8) {
        const float* brow = bank + (size_t)cj[i] * D;
        float dot = 0.f, bsq = 0.f;
        #pragma unroll
        for (int k0 = 0; k0 < D; k0 += 128) {
            int k = k0 + lane * 4;
            float4 bv = *(const float4*)(brow + k);
            dot = __fmaf_rn(bv.x, cvec[k], dot);
            dot = __fmaf_rn(bv.y, cvec[k + 1], dot);
            dot = __fmaf_rn(bv.z, cvec[k + 2], dot);
            dot = __fmaf_rn(bv.w, cvec[k + 3], dot);
            bsq = __fmaf_rn(bv.x, bv.x, bsq);
            bsq = __fmaf_rn(bv.y, bv.y, bsq);
            bsq = __fmaf_rn(bv.z, bv.z, bsq);
            bsq = __fmaf_rn(bv.w, bv.w, bsq);
        }
        #pragma unroll
        for (int o = 16; o; o >>= 1) {
            dot += __shfl_xor_sync(0xffffffffu, dot, o);
            bsq += __shfl_xor_sync(0xffffffffu, bsq, o);
        }
        if (lane == 0) {
            sdot[i] = dot;
            float d2 = fmaxf(__fmaf_rn(-2.f, dot, csq + bsq), 0.f);
            sd2[i] = __float_as_uint(d2);
        }
    }
    __syncthreads();

    // warp 0: exact top-64 by (d2 bits, j) — matches reference's stable top_k
    if (tid < 32) {
        float s = 0.f;
        int kk = (m < KSEL) ? m : KSEL;
        for (int it = 0; it < kk; it++) {
            unsigned best = 0xffffffffu;
            int bestj = 0x7fffffff, bi = -1;
            for (int i = tid; i < m; i += 32) {
                unsigned k = sd2[i];
                int jj = cj[i];
                if (k < best || (k == best && jj < bestj)) { best = k; bestj = jj; bi = i; }
            }
            #pragma unroll
            for (int o = 16; o; o >>= 1) {
                unsigned ok = __shfl_xor_sync(0xffffffffu, best, o);
                int      oj = __shfl_xor_sync(0xffffffffu, bestj, o);
                int      ob = __shfl_xor_sync(0xffffffffu, bi, o);
                if (ok < best || (ok == best && oj < bestj)) { best = ok; bestj = oj; bi = ob; }
            }
            if (tid == 0 && bi >= 0) {
                s += sdot[bi];
                sd2[bi] = 0xffffffffu;
                cj[bi] = 0x7fffffff;
            }
            __syncwarp();
        }
        if (tid == 0) g_csum[n] = s;
    }
}

// ------------------- scalars ------------------------------------------------
__global__ void __launch_bounds__(256) finalize(float* __restrict__ out)
{
    __shared__ float r1[8], r2[8], r3[8];
    int tid = threadIdx.x, lane = tid & 31, w = tid >> 5;
    float gs = 0.f, tr = 0.f;
    for (int i = tid; i < NC * NC; i += 256) {
        float v = g_gram[i];
        gs += v;
        if ((i >> 6) == (i & 63)) tr += v;
    }
    float cs = (tid < NC) ? g_csum[tid] : 0.f;
    #pragma unroll
    for (int o = 16; o; o >>= 1) {
        gs += __shfl_xor_sync(0xffffffffu, gs, o);
        tr += __shfl_xor_sync(0xffffffffu, tr, o);
        cs += __shfl_xor_sync(0xffffffffu, cs, o);
    }
    if (lane == 0) { r1[w] = gs; r2[w] = tr; r3[w] = cs; }
    __syncthreads();
    if (tid == 0) {
        float GS = 0, TR = 0, CS = 0;
        for (int i = 0; i < 8; i++) { GS += r1[i]; TR += r2[i]; CS += r3[i]; }
        out[O_L1]   = CS / (float)(NC * KSEL);
        out[O_L2]   = (GS - TR) / (float)(NC * NC);
        out[O_NORM] = TR / (float)(NC * NC);
    }
}

// ----------------------------------------------------------------------------
extern "C" void kernel_launch(void* const* d_in, const int* in_sizes, int n_in,
                              void* d_out, int out_size)
{
    (void)in_sizes; (void)n_in; (void)out_size;
    const float* C    = (const float*)d_in[0];  // (512, 64)
    const float* E    = (const float*)d_in[1];  // (2048, 512)
    const float* bank = (const float*)d_in[2];  // (200000, 512)
    const float* W    = (const float*)d_in[3];  // (512, 100)
    float* out = (float*)d_out;

    float *pgram, *pWc, *pZ, *pWC;
    cudaGetSymbolAddress((void**)&pgram, g_gram);
    cudaGetSymbolAddress((void**)&pWc,   g_Wc);
    cudaGetSymbolAddress((void**)&pZ,    g_Z);
    cudaGetSymbolAddress((void**)&pWC,   g_WC);

    cudaFuncSetAttribute(big_gemm, cudaFuncAttributeMaxDynamicSharedMemorySize, BG_SMEM);

    cudaStream_t s2;
    cudaStreamCreateWithFlags(&s2, cudaStreamNonBlocking);
    cudaEvent_t eF, eJ;
    cudaEventCreateWithFlags(&eF, cudaEventDisableTiming);
    cudaEventCreateWithFlags(&eJ, cudaEventDisableTiming);

    // main: prep (B tile bf16, [W|C], c_sq, counter/hist reset)
    prep<<<64, 256>>>(C, W);
    cudaEventRecord(eF, 0);
    cudaStreamWaitEvent(s2, eF, 0);

    // branch A (side stream): [Wc|gram] = C^T@[W|C] -> solve -> E@[W|C] -> y
    sgemm64<true, true><<<dim3(1, 3), 256, 0, s2>>>(C, pWC, pWc, pgram, NC, NWC, D, NC, NWC, 0);
    solve64<<<1, 192, 0, s2>>>();
    sgemm64<false, true><<<dim3(32, 3), 256, 0, s2>>>(E, pWC, out + O_ORIG, out + O_CPRED,
                                                      BSZ, NWC, D, D, NWC, 0);
    sgemm64<false, false><<<dim3(32, 2), 256, 0, s2>>>(out + O_CPRED, pZ, out + O_Y, nullptr,
                                                       BSZ, NCLS, NC, NC, NCLS, NCLS);
    cudaEventRecord(eJ, s2);

    // main: big_gemm -> approx select (margin) -> exact rescore
    big_gemm<<<(NBANK + MTILE - 1) / MTILE, 256, BG_SMEM>>>(bank);
    sel_hist<<<NC * 2, 1024>>>();
    sel_pick<<<NC, 1024>>>();
    sel_collect<<<NC * 2, 1024>>>();
    rescore<<<NC, 256>>>(C, bank);

    cudaStreamWaitEvent(0, eJ, 0);
    finalize<<<1, 256>>>(out);
}